// round 1
// baseline (speedup 1.0000x reference)
#include <cuda_runtime.h>
#include <math.h>

// ---------------- problem constants ----------------
#define BATCH 2
#define SEQ   2048
#define DIM   1024
#define HEADS 16
#define DHEAD 64
#define FFI   4096          // ff_inner
#define ROWS  (BATCH*SEQ)   // 4096 flattened rows

// ---------------- scratch (static device memory; no allocs allowed) -------
__device__ float g_xn  [(size_t)ROWS*DIM];        // layernorm(x)
__device__ float g_cn  [(size_t)ROWS*DIM];        // layernorm(context)
__device__ float g_q   [(size_t)ROWS*DIM];        // q (pre-scaled), row=(b*SEQ+i), col=h*64+d
__device__ float g_kv  [(size_t)ROWS*2*DHEAD];    // [k(64) | v(64)] per context row
__device__ float g_attn[(size_t)ROWS*DIM];        // attention output, (b,i,h,d) flattened
__device__ float g_h   [(size_t)ROWS*2*FFI];      // xn @ Wff1
__device__ float g_ff  [(size_t)ROWS*FFI];        // silu(gate)*a

// ---------------- LayerNorm: one CTA per 1024-wide row ----------------
__global__ void __launch_bounds__(256) ln_kernel(const float* __restrict__ in,
                                                 const float* __restrict__ g,
                                                 float* __restrict__ out) {
    const int row = blockIdx.x;
    const int t = threadIdx.x;
    const float* p = in + (size_t)row * DIM;
    float4 v = *(const float4*)&p[t * 4];
    float s  = v.x + v.y + v.z + v.w;
    float sq = v.x*v.x + v.y*v.y + v.z*v.z + v.w*v.w;
#pragma unroll
    for (int off = 16; off; off >>= 1) {
        s  += __shfl_xor_sync(0xffffffffu, s,  off);
        sq += __shfl_xor_sync(0xffffffffu, sq, off);
    }
    __shared__ float rs[8], rq[8];
    if ((t & 31) == 0) { rs[t >> 5] = s; rq[t >> 5] = sq; }
    __syncthreads();
    float ts = 0.f, tq = 0.f;
#pragma unroll
    for (int i = 0; i < 8; i++) { ts += rs[i]; tq += rq[i]; }
    const float mu  = ts * (1.f / DIM);
    const float var = tq * (1.f / DIM) - mu * mu;
    const float rstd = rsqrtf(var + 1e-5f);
    float4 gv = *(const float4*)&g[t * 4];
    float4 o;
    o.x = (v.x - mu) * rstd * gv.x;
    o.y = (v.y - mu) * rstd * gv.y;
    o.z = (v.z - mu) * rstd * gv.z;
    o.w = (v.w - mu) * rstd * gv.w;
    *(float4*)&out[(size_t)row * DIM + t * 4] = o;
}

// ---------------- generic tiled SGEMM: C(MxN) = A(MxK) @ B(KxN) ----------
// EPI: 0 = store, 1 = store*scale, 2 = accumulate into C
template<int BM, int BN, int BK, int TM, int TN, int EPI>
__global__ void __launch_bounds__((BM/TM)*(BN/TN)) sgemm_kernel(
        int M, int N, int K,
        const float* __restrict__ A, const float* __restrict__ B,
        float* __restrict__ C, float scale) {
    constexpr int THREADS = (BM / TM) * (BN / TN);
    __shared__ float As[BK][BM];   // transposed A tile
    __shared__ float Bs[BK][BN];

    const int tid = threadIdx.x;
    const int tx = tid % (BN / TN);
    const int ty = tid / (BN / TN);
    const int bm = blockIdx.y * BM;
    const int bn = blockIdx.x * BN;

    float acc[TM][TN] = {};

    constexpr int AK4 = BK / 4;
    const int aRow = tid / AK4;
    const int aCol = (tid % AK4) * 4;
    constexpr int AROWS = THREADS / AK4;
    constexpr int APASS = BM / AROWS;
    constexpr int BN4 = BN / 4;
    const int bRow = tid / BN4;
    const int bCol = (tid % BN4) * 4;
    constexpr int BROWS = THREADS / BN4;
    constexpr int BPASS = BK / BROWS;

    for (int k0 = 0; k0 < K; k0 += BK) {
#pragma unroll
        for (int p = 0; p < APASS; p++) {
            const int r = aRow + p * AROWS;
            float4 v = *(const float4*)&A[(size_t)(bm + r) * K + k0 + aCol];
            As[aCol + 0][r] = v.x; As[aCol + 1][r] = v.y;
            As[aCol + 2][r] = v.z; As[aCol + 3][r] = v.w;
        }
#pragma unroll
        for (int p = 0; p < BPASS; p++) {
            const int r = bRow + p * BROWS;
            *(float4*)&Bs[r][bCol] = *(const float4*)&B[(size_t)(k0 + r) * N + bn + bCol];
        }
        __syncthreads();
#pragma unroll
        for (int kk = 0; kk < BK; kk++) {
            float a[TM], b[TN];
#pragma unroll
            for (int i = 0; i < TM; i += 4)
                *(float4*)&a[i] = *(const float4*)&As[kk][ty * TM + i];
#pragma unroll
            for (int j = 0; j < TN; j += 4)
                *(float4*)&b[j] = *(const float4*)&Bs[kk][tx * TN + j];
#pragma unroll
            for (int i = 0; i < TM; i++)
#pragma unroll
                for (int j = 0; j < TN; j++)
                    acc[i][j] += a[i] * b[j];
        }
        __syncthreads();
    }

#pragma unroll
    for (int i = 0; i < TM; i++) {
        float* cp = &C[(size_t)(bm + ty * TM + i) * N + bn + tx * TN];
#pragma unroll
        for (int j = 0; j < TN; j += 4) {
            float4 r;
            if (EPI == 2) {
                float4 c = *(const float4*)&cp[j];
                r.x = c.x + acc[i][j + 0];
                r.y = c.y + acc[i][j + 1];
                r.z = c.z + acc[i][j + 2];
                r.w = c.w + acc[i][j + 3];
            } else if (EPI == 1) {
                r.x = acc[i][j + 0] * scale; r.y = acc[i][j + 1] * scale;
                r.z = acc[i][j + 2] * scale; r.w = acc[i][j + 3] * scale;
            } else {
                r.x = acc[i][j + 0]; r.y = acc[i][j + 1];
                r.z = acc[i][j + 2]; r.w = acc[i][j + 3];
            }
            *(float4*)&cp[j] = r;
        }
    }
}

// ---------------- flash attention -----------------------------------------
// grid (32 qtiles, 16 heads, 2 batch), 256 threads (16x16), Br=Bc=64, d=64.
// sQ, sK transposed [d][row] padded to 68; sV row-major [j][64]; P reuses sK.
#define AT_W 68
#define AT_SMEM_FLOATS (2*64*AT_W + 64*64 + 64)
#define AT_SMEM_BYTES  (AT_SMEM_FLOATS*4)

__global__ void __launch_bounds__(256) attn_kernel(const float* __restrict__ q,
                                                   const float* __restrict__ kv,
                                                   const int* __restrict__ mask,
                                                   float* __restrict__ out) {
    extern __shared__ float smem[];
    float* sQ = smem;                 // [64][AT_W] : [d][r]
    float* sK = smem + 64 * AT_W;     // [d][c], reused as P: [jj][r]
    float* sV = smem + 2 * 64 * AT_W; // [j][64]
    int*  sM = (int*)(smem + 2 * 64 * AT_W + 64 * 64);

    const int tid = threadIdx.x;
    const int tx = tid & 15, ty = tid >> 4;
    const int r0 = ty * 4, c0 = tx * 4;
    const int qt = blockIdx.x, h = blockIdx.y, b = blockIdx.z;
    const size_t qbase = ((size_t)(b * SEQ + qt * 64)) * DIM + h * DHEAD;

    // load Q tile transposed
#pragma unroll
    for (int p = 0; p < 4; p++) {
        const int lin = p * 256 + tid;
        const int r = lin >> 4;
        const int d = (lin & 15) * 4;
        float4 v = *(const float4*)&q[qbase + (size_t)r * DIM + d];
        sQ[(d + 0) * AT_W + r] = v.x;
        sQ[(d + 1) * AT_W + r] = v.y;
        sQ[(d + 2) * AT_W + r] = v.z;
        sQ[(d + 3) * AT_W + r] = v.w;
    }

    float m[4], l[4], o[4][4];
#pragma unroll
    for (int i = 0; i < 4; i++) {
        m[i] = -1e30f; l[i] = 0.f;
#pragma unroll
        for (int j = 0; j < 4; j++) o[i][j] = 0.f;
    }

    for (int jt = 0; jt < SEQ / 64; jt++) {
        __syncthreads();  // protects sK/sV reuse from previous iteration
        const size_t kbase = ((size_t)(b * SEQ + jt * 64)) * (2 * DHEAD);
#pragma unroll
        for (int p = 0; p < 4; p++) {
            const int lin = p * 256 + tid;
            const int j = lin >> 4;
            const int d = (lin & 15) * 4;
            float4 kvec = *(const float4*)&kv[kbase + (size_t)j * (2 * DHEAD) + d];
            sK[(d + 0) * AT_W + j] = kvec.x;
            sK[(d + 1) * AT_W + j] = kvec.y;
            sK[(d + 2) * AT_W + j] = kvec.z;
            sK[(d + 3) * AT_W + j] = kvec.w;
            float4 vvec = *(const float4*)&kv[kbase + (size_t)j * (2 * DHEAD) + DHEAD + d];
            *(float4*)&sV[j * 64 + d] = vvec;
        }
        if (tid < 64) sM[tid] = mask[b * SEQ + jt * 64 + tid];
        __syncthreads();

        // S = Q K^T (64x64, 4x4 per thread)
        float s[4][4] = {};
#pragma unroll
        for (int kk = 0; kk < 64; kk++) {
            float a[4], bb[4];
            *(float4*)a  = *(const float4*)&sQ[kk * AT_W + r0];
            *(float4*)bb = *(const float4*)&sK[kk * AT_W + c0];
#pragma unroll
            for (int i = 0; i < 4; i++)
#pragma unroll
                for (int j = 0; j < 4; j++)
                    s[i][j] += a[i] * bb[j];
        }
        int mk[4];
#pragma unroll
        for (int j = 0; j < 4; j++) mk[j] = sM[c0 + j];
#pragma unroll
        for (int i = 0; i < 4; i++)
#pragma unroll
            for (int j = 0; j < 4; j++)
                if (mk[j] == 0) s[i][j] = -1e30f;

        // online softmax update
        float pfrag[4][4];
#pragma unroll
        for (int i = 0; i < 4; i++) {
            float mx = fmaxf(fmaxf(s[i][0], s[i][1]), fmaxf(s[i][2], s[i][3]));
#pragma unroll
            for (int off = 1; off < 16; off <<= 1)
                mx = fmaxf(mx, __shfl_xor_sync(0xffffffffu, mx, off));
            const float mn = fmaxf(m[i], mx);
            const float corr = __expf(m[i] - mn);
            float rs = 0.f;
#pragma unroll
            for (int j = 0; j < 4; j++) {
                pfrag[i][j] = __expf(s[i][j] - mn);
                rs += pfrag[i][j];
            }
#pragma unroll
            for (int off = 1; off < 16; off <<= 1)
                rs += __shfl_xor_sync(0xffffffffu, rs, off);
            l[i] = l[i] * corr + rs;
            m[i] = mn;
#pragma unroll
            for (int j = 0; j < 4; j++) o[i][j] *= corr;
        }
        __syncthreads();  // everyone done reading sK as K
        // store P transposed into sK region: P[r][jj] at sK[jj*AT_W + r]
#pragma unroll
        for (int j = 0; j < 4; j++)
#pragma unroll
            for (int i = 0; i < 4; i++)
                sK[(c0 + j) * AT_W + r0 + i] = pfrag[i][j];
        __syncthreads();
        // O += P @ V
#pragma unroll
        for (int jj = 0; jj < 64; jj++) {
            float pf[4], vf[4];
            *(float4*)pf = *(const float4*)&sK[jj * AT_W + r0];
            *(float4*)vf = *(const float4*)&sV[jj * 64 + c0];
#pragma unroll
            for (int i = 0; i < 4; i++)
#pragma unroll
                for (int j = 0; j < 4; j++)
                    o[i][j] += pf[i] * vf[j];
        }
    }

#pragma unroll
    for (int i = 0; i < 4; i++) {
        const float inv = 1.f / l[i];
        float4 v = make_float4(o[i][0] * inv, o[i][1] * inv, o[i][2] * inv, o[i][3] * inv);
        *(float4*)&out[qbase + (size_t)(r0 + i) * DIM + c0] = v;
    }
}

// ---------------- SwiGLU elementwise: ff = silu(gate)*a -------------------
__global__ void __launch_bounds__(256) silu_mul_kernel(const float* __restrict__ h,
                                                       float* __restrict__ ff) {
    const size_t idx = ((size_t)blockIdx.x * blockDim.x + threadIdx.x) * 4;
    const size_t row = idx >> 12;          // / FFI (4096)
    const size_t c = idx & (FFI - 1);
    const float* hp = h + row * (2 * FFI);
    float4 a = *(const float4*)&hp[c];
    float4 g = *(const float4*)&hp[FFI + c];
    float4 o;
    o.x = a.x * (g.x / (1.f + __expf(-g.x)));
    o.y = a.y * (g.y / (1.f + __expf(-g.y)));
    o.z = a.z * (g.z / (1.f + __expf(-g.z)));
    o.w = a.w * (g.w / (1.f + __expf(-g.w)));
    *(float4*)&ff[idx] = o;
}

// ---------------- launch --------------------------------------------------
extern "C" void kernel_launch(void* const* d_in, const int* in_sizes, int n_in,
                              void* d_out, int out_size) {
    (void)in_sizes; (void)n_in; (void)out_size;
    const float* x        = (const float*)d_in[0];
    const float* context  = (const float*)d_in[1];
    const int*   mask     = (const int*)  d_in[2];
    const float* gamma    = (const float*)d_in[3];
    const float* ctxgamma = (const float*)d_in[4];
    const float* Wq       = (const float*)d_in[5];
    const float* Wkv      = (const float*)d_in[6];
    const float* Wout     = (const float*)d_in[7];
    const float* Wff1     = (const float*)d_in[8];
    const float* Wff2     = (const float*)d_in[9];
    float* out = (float*)d_out;

    float *xn, *cn, *qb, *kvb, *attnb, *hb, *ffb;
    cudaGetSymbolAddress((void**)&xn,    g_xn);
    cudaGetSymbolAddress((void**)&cn,    g_cn);
    cudaGetSymbolAddress((void**)&qb,    g_q);
    cudaGetSymbolAddress((void**)&kvb,   g_kv);
    cudaGetSymbolAddress((void**)&attnb, g_attn);
    cudaGetSymbolAddress((void**)&hb,    g_h);
    cudaGetSymbolAddress((void**)&ffb,   g_ff);

    cudaFuncSetAttribute(attn_kernel, cudaFuncAttributeMaxDynamicSharedMemorySize, AT_SMEM_BYTES);

    // layernorms
    ln_kernel<<<ROWS, 256>>>(x, gamma, xn);
    ln_kernel<<<ROWS, 256>>>(context, ctxgamma, cn);

    // q = (xn @ Wq) * scale          [4096 x 1024 x 1024]
    sgemm_kernel<128,128,16,8,8,1><<<dim3(DIM/128, ROWS/128), 256>>>(
        ROWS, DIM, DIM, xn, Wq, qb, 0.125f);

    // kv = cn @ Wkv                  [4096 x 128 x 1024]
    sgemm_kernel<64,64,16,4,4,0><<<dim3((2*DHEAD)/64, ROWS/64), 256>>>(
        ROWS, 2*DHEAD, DIM, cn, Wkv, kvb, 1.f);

    // attention
    attn_kernel<<<dim3(SEQ/64, HEADS, BATCH), 256, AT_SMEM_BYTES>>>(qb, kvb, mask, attnb);

    // out = attn @ Wout              [4096 x 1024 x 1024]
    sgemm_kernel<128,128,16,8,8,0><<<dim3(DIM/128, ROWS/128), 256>>>(
        ROWS, DIM, DIM, attnb, Wout, out, 1.f);

    // h = xn @ Wff1                  [4096 x 8192 x 1024]
    sgemm_kernel<128,128,16,8,8,0><<<dim3((2*FFI)/128, ROWS/128), 256>>>(
        ROWS, 2*FFI, DIM, xn, Wff1, hb, 1.f);

    // ff = silu(gate) * a
    silu_mul_kernel<<<(ROWS*(size_t)FFI)/4/256, 256>>>(hb, ffb);

    // out += ff @ Wff2               [4096 x 1024 x 4096]
    sgemm_kernel<128,128,16,8,8,2><<<dim3(DIM/128, ROWS/128), 256>>>(
        ROWS, DIM, FFI, ffb, Wff2, out, 1.f);
}

// round 2
// speedup vs baseline: 2.0906x; 2.0906x over previous
#include <cuda_runtime.h>
#include <math.h>
#include <stdint.h>

// ---------------- problem constants ----------------
#define BATCH 2
#define SEQ   2048
#define DIM   1024
#define HEADS 16
#define DHEAD 64
#define FFI   4096
#define ROWS  (BATCH*SEQ)

// ---------------- scratch ----------------
__device__ float g_xn  [(size_t)ROWS*DIM];
__device__ float g_cn  [(size_t)ROWS*DIM];
__device__ float g_q   [(size_t)ROWS*DIM];
__device__ float g_kv  [(size_t)ROWS*2*DHEAD];
__device__ float g_attn[(size_t)ROWS*DIM];
__device__ float g_h   [(size_t)ROWS*2*FFI];
__device__ float g_ff  [(size_t)ROWS*FFI];
__device__ float g_wr  [14811136];   // tf32-rounded weights

#define WQ_OFF   0
#define WKV_OFF  1048576
#define WOUT_OFF 1179648
#define WFF1_OFF 2228224
#define WFF2_OFF 10616832

__device__ __forceinline__ float round_tf32(float x) {
    uint32_t u;
    asm("cvt.rna.tf32.f32 %0, %1;" : "=r"(u) : "f"(x));
    return __uint_as_float(u);
}

__device__ __forceinline__ void cp16(void* smem_ptr, const void* gptr) {
    unsigned sa;
    asm("{.reg .u64 t; cvta.to.shared.u64 t, %1; cvt.u32.u64 %0, t;}" : "=r"(sa) : "l"(smem_ptr));
    asm volatile("cp.async.cg.shared.global [%0], [%1], 16;" :: "r"(sa), "l"(gptr));
}

// ---------------- weight rounding ----------------
__global__ void __launch_bounds__(256) round_kernel(const float* __restrict__ in,
                                                    float* __restrict__ out, int n4) {
    int i = blockIdx.x * blockDim.x + threadIdx.x;
    if (i < n4) {
        float4 v = ((const float4*)in)[i];
        v.x = round_tf32(v.x); v.y = round_tf32(v.y);
        v.z = round_tf32(v.z); v.w = round_tf32(v.w);
        ((float4*)out)[i] = v;
    }
}

// ---------------- LayerNorm (outputs tf32-rounded) ----------------
__global__ void __launch_bounds__(256) ln_kernel(const float* __restrict__ in,
                                                 const float* __restrict__ g,
                                                 float* __restrict__ out) {
    const int row = blockIdx.x;
    const int t = threadIdx.x;
    const float* p = in + (size_t)row * DIM;
    float4 v = *(const float4*)&p[t * 4];
    float s  = v.x + v.y + v.z + v.w;
    float sq = v.x*v.x + v.y*v.y + v.z*v.z + v.w*v.w;
#pragma unroll
    for (int off = 16; off; off >>= 1) {
        s  += __shfl_xor_sync(0xffffffffu, s,  off);
        sq += __shfl_xor_sync(0xffffffffu, sq, off);
    }
    __shared__ float rs[8], rq[8];
    if ((t & 31) == 0) { rs[t >> 5] = s; rq[t >> 5] = sq; }
    __syncthreads();
    float ts = 0.f, tq = 0.f;
#pragma unroll
    for (int i = 0; i < 8; i++) { ts += rs[i]; tq += rq[i]; }
    const float mu  = ts * (1.f / DIM);
    const float var = tq * (1.f / DIM) - mu * mu;
    const float rstd = rsqrtf(var + 1e-5f);
    float4 gv = *(const float4*)&g[t * 4];
    float4 o;
    o.x = round_tf32((v.x - mu) * rstd * gv.x);
    o.y = round_tf32((v.y - mu) * rstd * gv.y);
    o.z = round_tf32((v.z - mu) * rstd * gv.z);
    o.w = round_tf32((v.w - mu) * rstd * gv.w);
    *(float4*)&out[(size_t)row * DIM + t * 4] = o;
}

// ---------------- TF32 tensor-core GEMM ----------------
// C(MxN) = A(MxK) @ B(KxN); A,B pre-rounded to tf32-representable fp32.
// 128x128x32 tiles, 8 warps (2x4), warp tile 64x32, mma.m16n8k8.tf32.
// EPI: 0 = store, 1 = store*scale, 2 = accumulate into C
#define AS_STRIDE 36
#define BS_STRIDE 136
#define STAGE_FLOATS (128*AS_STRIDE + 32*BS_STRIDE)
#define GEMM_SMEM_BYTES (2*STAGE_FLOATS*4)

template<int EPI>
__global__ void __launch_bounds__(256) tf32_gemm_kernel(
        int M, int N, int K,
        const float* __restrict__ A, const float* __restrict__ B,
        float* __restrict__ C, float scale) {
    extern __shared__ float sm[];
    const int tid = threadIdx.x, lane = tid & 31, wid = tid >> 5;
    const int wm = (wid & 1) * 64, wn = (wid >> 1) * 32;
    const int bm = blockIdx.y * 128, bn = blockIdx.x * 128;
    const int r = lane >> 2, cc = lane & 3;

    const int am = tid >> 3, ak = (tid & 7) * 4;   // A copy: rows am+p*32, cols ak..ak+3
    const int bk = wid, bnn = lane * 4;            // B copy: rows bk+p*8, cols bnn..bnn+3

    float acc[4][4][4] = {};
    const int T = K / 32;

    // prologue: tile 0 -> stage 0
    {
        float* As = sm;
        float* Bs = sm + 128 * AS_STRIDE;
#pragma unroll
        for (int p = 0; p < 4; p++)
            cp16(&As[(am + p * 32) * AS_STRIDE + ak], &A[(size_t)(bm + am + p * 32) * K + ak]);
#pragma unroll
        for (int p = 0; p < 4; p++)
            cp16(&Bs[(bk + p * 8) * BS_STRIDE + bnn], &B[(size_t)(bk + p * 8) * N + bn + bnn]);
        asm volatile("cp.async.commit_group;");
    }

    for (int t = 0; t < T; t++) {
        if (t + 1 < T) {
            const int s = (t + 1) & 1;
            const int k0 = (t + 1) * 32;
            float* As = sm + s * STAGE_FLOATS;
            float* Bs = As + 128 * AS_STRIDE;
#pragma unroll
            for (int p = 0; p < 4; p++)
                cp16(&As[(am + p * 32) * AS_STRIDE + ak],
                     &A[(size_t)(bm + am + p * 32) * K + k0 + ak]);
#pragma unroll
            for (int p = 0; p < 4; p++)
                cp16(&Bs[(bk + p * 8) * BS_STRIDE + bnn],
                     &B[(size_t)(k0 + bk + p * 8) * N + bn + bnn]);
            asm volatile("cp.async.commit_group;");
            asm volatile("cp.async.wait_group 1;");
        } else {
            asm volatile("cp.async.wait_group 0;");
        }
        __syncthreads();

        const int s = t & 1;
        const float* As = sm + s * STAGE_FLOATS;
        const float* Bs = As + 128 * AS_STRIDE;
#pragma unroll
        for (int kk = 0; kk < 4; kk++) {
            const int k = kk * 8;
            unsigned a[4][4], b[4][2];
#pragma unroll
            for (int mi = 0; mi < 4; mi++) {
                const float* ap = As + (wm + mi * 16) * AS_STRIDE + k;
                a[mi][0] = __float_as_uint(ap[r * AS_STRIDE + cc]);
                a[mi][1] = __float_as_uint(ap[(r + 8) * AS_STRIDE + cc]);
                a[mi][2] = __float_as_uint(ap[r * AS_STRIDE + cc + 4]);
                a[mi][3] = __float_as_uint(ap[(r + 8) * AS_STRIDE + cc + 4]);
            }
#pragma unroll
            for (int ni = 0; ni < 4; ni++) {
                const float* bp = Bs + k * BS_STRIDE + wn + ni * 8;
                b[ni][0] = __float_as_uint(bp[cc * BS_STRIDE + r]);
                b[ni][1] = __float_as_uint(bp[(cc + 4) * BS_STRIDE + r]);
            }
#pragma unroll
            for (int mi = 0; mi < 4; mi++)
#pragma unroll
                for (int ni = 0; ni < 4; ni++)
                    asm volatile(
                        "mma.sync.aligned.m16n8k8.row.col.f32.tf32.tf32.f32 "
                        "{%0,%1,%2,%3},{%4,%5,%6,%7},{%8,%9},{%0,%1,%2,%3};"
                        : "+f"(acc[mi][ni][0]), "+f"(acc[mi][ni][1]),
                          "+f"(acc[mi][ni][2]), "+f"(acc[mi][ni][3])
                        : "r"(a[mi][0]), "r"(a[mi][1]), "r"(a[mi][2]), "r"(a[mi][3]),
                          "r"(b[ni][0]), "r"(b[ni][1]));
        }
        __syncthreads();
    }

    // epilogue
#pragma unroll
    for (int mi = 0; mi < 4; mi++) {
#pragma unroll
        for (int ni = 0; ni < 4; ni++) {
            const int row0 = bm + wm + mi * 16 + r;
            const int col  = bn + wn + ni * 8 + cc * 2;
            float2* p0 = (float2*)&C[(size_t)row0 * N + col];
            float2* p1 = (float2*)&C[(size_t)(row0 + 8) * N + col];
            float2 v0 = make_float2(acc[mi][ni][0], acc[mi][ni][1]);
            float2 v1 = make_float2(acc[mi][ni][2], acc[mi][ni][3]);
            if (EPI == 1) { v0.x *= scale; v0.y *= scale; v1.x *= scale; v1.y *= scale; }
            if (EPI == 2) {
                float2 c0 = *p0, c1 = *p1;
                v0.x += c0.x; v0.y += c0.y; v1.x += c1.x; v1.y += c1.y;
            }
            *p0 = v0; *p1 = v1;
        }
    }
}

// ---------------- flash attention (fp32; outputs tf32-rounded) -----------
#define AT_W 68
#define AT_SMEM_FLOATS (2*64*AT_W + 64*64 + 64)
#define AT_SMEM_BYTES  (AT_SMEM_FLOATS*4)

__global__ void __launch_bounds__(256) attn_kernel(const float* __restrict__ q,
                                                   const float* __restrict__ kv,
                                                   const int* __restrict__ mask,
                                                   float* __restrict__ out) {
    extern __shared__ float smem[];
    float* sQ = smem;
    float* sK = smem + 64 * AT_W;
    float* sV = smem + 2 * 64 * AT_W;
    int*  sM = (int*)(smem + 2 * 64 * AT_W + 64 * 64);

    const int tid = threadIdx.x;
    const int tx = tid & 15, ty = tid >> 4;
    const int r0 = ty * 4, c0 = tx * 4;
    const int qt = blockIdx.x, h = blockIdx.y, b = blockIdx.z;
    const size_t qbase = ((size_t)(b * SEQ + qt * 64)) * DIM + h * DHEAD;

#pragma unroll
    for (int p = 0; p < 4; p++) {
        const int lin = p * 256 + tid;
        const int r = lin >> 4;
        const int d = (lin & 15) * 4;
        float4 v = *(const float4*)&q[qbase + (size_t)r * DIM + d];
        sQ[(d + 0) * AT_W + r] = v.x;
        sQ[(d + 1) * AT_W + r] = v.y;
        sQ[(d + 2) * AT_W + r] = v.z;
        sQ[(d + 3) * AT_W + r] = v.w;
    }

    float m[4], l[4], o[4][4];
#pragma unroll
    for (int i = 0; i < 4; i++) {
        m[i] = -1e30f; l[i] = 0.f;
#pragma unroll
        for (int j = 0; j < 4; j++) o[i][j] = 0.f;
    }

    for (int jt = 0; jt < SEQ / 64; jt++) {
        __syncthreads();
        const size_t kbase = ((size_t)(b * SEQ + jt * 64)) * (2 * DHEAD);
#pragma unroll
        for (int p = 0; p < 4; p++) {
            const int lin = p * 256 + tid;
            const int j = lin >> 4;
            const int d = (lin & 15) * 4;
            float4 kvec = *(const float4*)&kv[kbase + (size_t)j * (2 * DHEAD) + d];
            sK[(d + 0) * AT_W + j] = kvec.x;
            sK[(d + 1) * AT_W + j] = kvec.y;
            sK[(d + 2) * AT_W + j] = kvec.z;
            sK[(d + 3) * AT_W + j] = kvec.w;
            float4 vvec = *(const float4*)&kv[kbase + (size_t)j * (2 * DHEAD) + DHEAD + d];
            *(float4*)&sV[j * 64 + d] = vvec;
        }
        if (tid < 64) sM[tid] = mask[b * SEQ + jt * 64 + tid];
        __syncthreads();

        float s[4][4] = {};
#pragma unroll
        for (int kk = 0; kk < 64; kk++) {
            float a[4], bb[4];
            *(float4*)a  = *(const float4*)&sQ[kk * AT_W + r0];
            *(float4*)bb = *(const float4*)&sK[kk * AT_W + c0];
#pragma unroll
            for (int i = 0; i < 4; i++)
#pragma unroll
                for (int j = 0; j < 4; j++)
                    s[i][j] += a[i] * bb[j];
        }
        int mk[4];
#pragma unroll
        for (int j = 0; j < 4; j++) mk[j] = sM[c0 + j];
#pragma unroll
        for (int i = 0; i < 4; i++)
#pragma unroll
            for (int j = 0; j < 4; j++)
                if (mk[j] == 0) s[i][j] = -1e30f;

        float pfrag[4][4];
#pragma unroll
        for (int i = 0; i < 4; i++) {
            float mx = fmaxf(fmaxf(s[i][0], s[i][1]), fmaxf(s[i][2], s[i][3]));
#pragma unroll
            for (int off = 1; off < 16; off <<= 1)
                mx = fmaxf(mx, __shfl_xor_sync(0xffffffffu, mx, off));
            const float mn = fmaxf(m[i], mx);
            const float corr = __expf(m[i] - mn);
            float rs = 0.f;
#pragma unroll
            for (int j = 0; j < 4; j++) {
                pfrag[i][j] = __expf(s[i][j] - mn);
                rs += pfrag[i][j];
            }
#pragma unroll
            for (int off = 1; off < 16; off <<= 1)
                rs += __shfl_xor_sync(0xffffffffu, rs, off);
            l[i] = l[i] * corr + rs;
            m[i] = mn;
#pragma unroll
            for (int j = 0; j < 4; j++) o[i][j] *= corr;
        }
        __syncthreads();
#pragma unroll
        for (int j = 0; j < 4; j++)
#pragma unroll
            for (int i = 0; i < 4; i++)
                sK[(c0 + j) * AT_W + r0 + i] = pfrag[i][j];
        __syncthreads();
#pragma unroll
        for (int jj = 0; jj < 64; jj++) {
            float pf[4], vf[4];
            *(float4*)pf = *(const float4*)&sK[jj * AT_W + r0];
            *(float4*)vf = *(const float4*)&sV[jj * 64 + c0];
#pragma unroll
            for (int i = 0; i < 4; i++)
#pragma unroll
                for (int j = 0; j < 4; j++)
                    o[i][j] += pf[i] * vf[j];
        }
    }

#pragma unroll
    for (int i = 0; i < 4; i++) {
        const float inv = 1.f / l[i];
        float4 v = make_float4(round_tf32(o[i][0] * inv), round_tf32(o[i][1] * inv),
                               round_tf32(o[i][2] * inv), round_tf32(o[i][3] * inv));
        *(float4*)&out[qbase + (size_t)(r0 + i) * DIM + c0] = v;
    }
}

// ---------------- SwiGLU (outputs tf32-rounded) ----------------
__global__ void __launch_bounds__(256) silu_mul_kernel(const float* __restrict__ h,
                                                       float* __restrict__ ff) {
    const size_t idx = ((size_t)blockIdx.x * blockDim.x + threadIdx.x) * 4;
    const size_t row = idx >> 12;
    const size_t c = idx & (FFI - 1);
    const float* hp = h + row * (2 * FFI);
    float4 a = *(const float4*)&hp[c];
    float4 g = *(const float4*)&hp[FFI + c];
    float4 o;
    o.x = round_tf32(a.x * (g.x / (1.f + __expf(-g.x))));
    o.y = round_tf32(a.y * (g.y / (1.f + __expf(-g.y))));
    o.z = round_tf32(a.z * (g.z / (1.f + __expf(-g.z))));
    o.w = round_tf32(a.w * (g.w / (1.f + __expf(-g.w))));
    *(float4*)&ff[idx] = o;
}

// ---------------- launch --------------------------------------------------
extern "C" void kernel_launch(void* const* d_in, const int* in_sizes, int n_in,
                              void* d_out, int out_size) {
    (void)in_sizes; (void)n_in; (void)out_size;
    const float* x        = (const float*)d_in[0];
    const float* context  = (const float*)d_in[1];
    const int*   mask     = (const int*)  d_in[2];
    const float* gamma    = (const float*)d_in[3];
    const float* ctxgamma = (const float*)d_in[4];
    const float* Wq       = (const float*)d_in[5];
    const float* Wkv      = (const float*)d_in[6];
    const float* Wout     = (const float*)d_in[7];
    const float* Wff1     = (const float*)d_in[8];
    const float* Wff2     = (const float*)d_in[9];
    float* out = (float*)d_out;

    float *xn, *cn, *qb, *kvb, *attnb, *hb, *ffb, *wr;
    cudaGetSymbolAddress((void**)&xn,    g_xn);
    cudaGetSymbolAddress((void**)&cn,    g_cn);
    cudaGetSymbolAddress((void**)&qb,    g_q);
    cudaGetSymbolAddress((void**)&kvb,   g_kv);
    cudaGetSymbolAddress((void**)&attnb, g_attn);
    cudaGetSymbolAddress((void**)&hb,    g_h);
    cudaGetSymbolAddress((void**)&ffb,   g_ff);
    cudaGetSymbolAddress((void**)&wr,    g_wr);

    cudaFuncSetAttribute(attn_kernel, cudaFuncAttributeMaxDynamicSharedMemorySize, AT_SMEM_BYTES);
    cudaFuncSetAttribute(tf32_gemm_kernel<0>, cudaFuncAttributeMaxDynamicSharedMemorySize, GEMM_SMEM_BYTES);
    cudaFuncSetAttribute(tf32_gemm_kernel<1>, cudaFuncAttributeMaxDynamicSharedMemorySize, GEMM_SMEM_BYTES);
    cudaFuncSetAttribute(tf32_gemm_kernel<2>, cudaFuncAttributeMaxDynamicSharedMemorySize, GEMM_SMEM_BYTES);

    // round weights to tf32
    round_kernel<<<(1048576/4+255)/256, 256>>>(Wq,   wr + WQ_OFF,   1048576/4);
    round_kernel<<<(131072/4+255)/256,  256>>>(Wkv,  wr + WKV_OFF,  131072/4);
    round_kernel<<<(1048576/4+255)/256, 256>>>(Wout, wr + WOUT_OFF, 1048576/4);
    round_kernel<<<(8388608/4+255)/256, 256>>>(Wff1, wr + WFF1_OFF, 8388608/4);
    round_kernel<<<(4194304/4+255)/256, 256>>>(Wff2, wr + WFF2_OFF, 4194304/4);

    // layernorms (tf32-rounded outputs)
    ln_kernel<<<ROWS, 256>>>(x, gamma, xn);
    ln_kernel<<<ROWS, 256>>>(context, ctxgamma, cn);

    // q = (xn @ Wq) * scale
    tf32_gemm_kernel<1><<<dim3(DIM/128, ROWS/128), 256, GEMM_SMEM_BYTES>>>(
        ROWS, DIM, DIM, xn, wr + WQ_OFF, qb, 0.125f);

    // kv = cn @ Wkv
    tf32_gemm_kernel<0><<<dim3(1, ROWS/128), 256, GEMM_SMEM_BYTES>>>(
        ROWS, 2*DHEAD, DIM, cn, wr + WKV_OFF, kvb, 1.f);

    // attention
    attn_kernel<<<dim3(SEQ/64, HEADS, BATCH), 256, AT_SMEM_BYTES>>>(qb, kvb, mask, attnb);

    // out = attn @ Wout
    tf32_gemm_kernel<0><<<dim3(DIM/128, ROWS/128), 256, GEMM_SMEM_BYTES>>>(
        ROWS, DIM, DIM, attnb, wr + WOUT_OFF, out, 1.f);

    // h = xn @ Wff1
    tf32_gemm_kernel<0><<<dim3((2*FFI)/128, ROWS/128), 256, GEMM_SMEM_BYTES>>>(
        ROWS, 2*FFI, DIM, xn, wr + WFF1_OFF, hb, 1.f);

    // ff = silu(gate) * a
    silu_mul_kernel<<<(int)((ROWS*(size_t)FFI)/4/256), 256>>>(hb, ffb);

    // out += ff @ Wff2
    tf32_gemm_kernel<2><<<dim3(DIM/128, ROWS/128), 256, GEMM_SMEM_BYTES>>>(
        ROWS, DIM, FFI, ffb, wr + WFF2_OFF, out, 1.f);
}

// round 3
// speedup vs baseline: 3.2744x; 1.5663x over previous
#include <cuda_runtime.h>
#include <math.h>
#include <stdint.h>

// ---------------- problem constants ----------------
#define BATCH 2
#define SEQ   2048
#define DIM   1024
#define HEADS 16
#define DHEAD 64
#define FFI   4096
#define ROWS  (BATCH*SEQ)

// ---------------- scratch ----------------
__device__ float g_xn  [(size_t)ROWS*DIM];
__device__ float g_cn  [(size_t)ROWS*DIM];
__device__ float g_q   [(size_t)ROWS*DIM];
__device__ float g_kv  [(size_t)ROWS*2*DHEAD];
__device__ float g_attn[(size_t)ROWS*DIM];
__device__ float g_h   [(size_t)ROWS*2*FFI];
__device__ float g_ff  [(size_t)ROWS*FFI];
__device__ float g_wr  [14811136];   // tf32-rounded weights

#define WQ_OFF   0
#define WKV_OFF  1048576
#define WOUT_OFF 1179648
#define WFF1_OFF 2228224
#define WFF2_OFF 10616832

__device__ __forceinline__ float round_tf32(float x) {
    uint32_t u;
    asm("cvt.rna.tf32.f32 %0, %1;" : "=r"(u) : "f"(x));
    return __uint_as_float(u);
}

__device__ __forceinline__ void cp16(void* smem_ptr, const void* gptr) {
    unsigned sa;
    asm("{.reg .u64 t; cvta.to.shared.u64 t, %1; cvt.u32.u64 %0, t;}" : "=r"(sa) : "l"(smem_ptr));
    asm volatile("cp.async.cg.shared.global [%0], [%1], 16;" :: "r"(sa), "l"(gptr));
}

// ---------------- weight rounding ----------------
__global__ void __launch_bounds__(256) round_kernel(const float* __restrict__ in,
                                                    float* __restrict__ out, int n4) {
    int i = blockIdx.x * blockDim.x + threadIdx.x;
    if (i < n4) {
        float4 v = ((const float4*)in)[i];
        v.x = round_tf32(v.x); v.y = round_tf32(v.y);
        v.z = round_tf32(v.z); v.w = round_tf32(v.w);
        ((float4*)out)[i] = v;
    }
}

// ---------------- LayerNorm (outputs tf32-rounded) ----------------
__global__ void __launch_bounds__(256) ln_kernel(const float* __restrict__ in,
                                                 const float* __restrict__ g,
                                                 float* __restrict__ out) {
    const int row = blockIdx.x;
    const int t = threadIdx.x;
    const float* p = in + (size_t)row * DIM;
    float4 v = *(const float4*)&p[t * 4];
    float s  = v.x + v.y + v.z + v.w;
    float sq = v.x*v.x + v.y*v.y + v.z*v.z + v.w*v.w;
#pragma unroll
    for (int off = 16; off; off >>= 1) {
        s  += __shfl_xor_sync(0xffffffffu, s,  off);
        sq += __shfl_xor_sync(0xffffffffu, sq, off);
    }
    __shared__ float rs[8], rq[8];
    if ((t & 31) == 0) { rs[t >> 5] = s; rq[t >> 5] = sq; }
    __syncthreads();
    float ts = 0.f, tq = 0.f;
#pragma unroll
    for (int i = 0; i < 8; i++) { ts += rs[i]; tq += rq[i]; }
    const float mu  = ts * (1.f / DIM);
    const float var = tq * (1.f / DIM) - mu * mu;
    const float rstd = rsqrtf(var + 1e-5f);
    float4 gv = *(const float4*)&g[t * 4];
    float4 o;
    o.x = round_tf32((v.x - mu) * rstd * gv.x);
    o.y = round_tf32((v.y - mu) * rstd * gv.y);
    o.z = round_tf32((v.z - mu) * rstd * gv.z);
    o.w = round_tf32((v.w - mu) * rstd * gv.w);
    *(float4*)&out[(size_t)row * DIM + t * 4] = o;
}

// ---------------- TF32 tensor-core GEMM ----------------
// EPI: 0 = store, 1 = store*scale rounded, 2 = accumulate into C, 3 = store rounded
#define AS_STRIDE 36
#define BS_STRIDE 136
#define STAGE_FLOATS (128*AS_STRIDE + 32*BS_STRIDE)
#define GEMM_SMEM_BYTES (2*STAGE_FLOATS*4)

template<int EPI>
__global__ void __launch_bounds__(256) tf32_gemm_kernel(
        int M, int N, int K,
        const float* __restrict__ A, const float* __restrict__ B,
        float* __restrict__ C, float scale) {
    extern __shared__ float sm[];
    const int tid = threadIdx.x, lane = tid & 31, wid = tid >> 5;
    const int wm = (wid & 1) * 64, wn = (wid >> 1) * 32;
    const int bm = blockIdx.y * 128, bn = blockIdx.x * 128;
    const int r = lane >> 2, cc = lane & 3;

    const int am = tid >> 3, ak = (tid & 7) * 4;
    const int bk = wid, bnn = lane * 4;

    float acc[4][4][4] = {};
    const int T = K / 32;

    {
        float* As = sm;
        float* Bs = sm + 128 * AS_STRIDE;
#pragma unroll
        for (int p = 0; p < 4; p++)
            cp16(&As[(am + p * 32) * AS_STRIDE + ak], &A[(size_t)(bm + am + p * 32) * K + ak]);
#pragma unroll
        for (int p = 0; p < 4; p++)
            cp16(&Bs[(bk + p * 8) * BS_STRIDE + bnn], &B[(size_t)(bk + p * 8) * N + bn + bnn]);
        asm volatile("cp.async.commit_group;");
    }

    for (int t = 0; t < T; t++) {
        if (t + 1 < T) {
            const int s = (t + 1) & 1;
            const int k0 = (t + 1) * 32;
            float* As = sm + s * STAGE_FLOATS;
            float* Bs = As + 128 * AS_STRIDE;
#pragma unroll
            for (int p = 0; p < 4; p++)
                cp16(&As[(am + p * 32) * AS_STRIDE + ak],
                     &A[(size_t)(bm + am + p * 32) * K + k0 + ak]);
#pragma unroll
            for (int p = 0; p < 4; p++)
                cp16(&Bs[(bk + p * 8) * BS_STRIDE + bnn],
                     &B[(size_t)(k0 + bk + p * 8) * N + bn + bnn]);
            asm volatile("cp.async.commit_group;");
            asm volatile("cp.async.wait_group 1;");
        } else {
            asm volatile("cp.async.wait_group 0;");
        }
        __syncthreads();

        const int s = t & 1;
        const float* As = sm + s * STAGE_FLOATS;
        const float* Bs = As + 128 * AS_STRIDE;
#pragma unroll
        for (int kk = 0; kk < 4; kk++) {
            const int k = kk * 8;
            unsigned a[4][4], b[4][2];
#pragma unroll
            for (int mi = 0; mi < 4; mi++) {
                const float* ap = As + (wm + mi * 16) * AS_STRIDE + k;
                a[mi][0] = __float_as_uint(ap[r * AS_STRIDE + cc]);
                a[mi][1] = __float_as_uint(ap[(r + 8) * AS_STRIDE + cc]);
                a[mi][2] = __float_as_uint(ap[r * AS_STRIDE + cc + 4]);
                a[mi][3] = __float_as_uint(ap[(r + 8) * AS_STRIDE + cc + 4]);
            }
#pragma unroll
            for (int ni = 0; ni < 4; ni++) {
                const float* bp = Bs + k * BS_STRIDE + wn + ni * 8;
                b[ni][0] = __float_as_uint(bp[cc * BS_STRIDE + r]);
                b[ni][1] = __float_as_uint(bp[(cc + 4) * BS_STRIDE + r]);
            }
#pragma unroll
            for (int mi = 0; mi < 4; mi++)
#pragma unroll
                for (int ni = 0; ni < 4; ni++)
                    asm volatile(
                        "mma.sync.aligned.m16n8k8.row.col.f32.tf32.tf32.f32 "
                        "{%0,%1,%2,%3},{%4,%5,%6,%7},{%8,%9},{%0,%1,%2,%3};"
                        : "+f"(acc[mi][ni][0]), "+f"(acc[mi][ni][1]),
                          "+f"(acc[mi][ni][2]), "+f"(acc[mi][ni][3])
                        : "r"(a[mi][0]), "r"(a[mi][1]), "r"(a[mi][2]), "r"(a[mi][3]),
                          "r"(b[ni][0]), "r"(b[ni][1]));
        }
        __syncthreads();
    }

#pragma unroll
    for (int mi = 0; mi < 4; mi++) {
#pragma unroll
        for (int ni = 0; ni < 4; ni++) {
            const int row0 = bm + wm + mi * 16 + r;
            const int col  = bn + wn + ni * 8 + cc * 2;
            float2* p0 = (float2*)&C[(size_t)row0 * N + col];
            float2* p1 = (float2*)&C[(size_t)(row0 + 8) * N + col];
            float2 v0 = make_float2(acc[mi][ni][0], acc[mi][ni][1]);
            float2 v1 = make_float2(acc[mi][ni][2], acc[mi][ni][3]);
            if (EPI == 1) {
                v0.x = round_tf32(v0.x * scale); v0.y = round_tf32(v0.y * scale);
                v1.x = round_tf32(v1.x * scale); v1.y = round_tf32(v1.y * scale);
            }
            if (EPI == 3) {
                v0.x = round_tf32(v0.x); v0.y = round_tf32(v0.y);
                v1.x = round_tf32(v1.x); v1.y = round_tf32(v1.y);
            }
            if (EPI == 2) {
                float2 c0 = *p0, c1 = *p1;
                v0.x += c0.x; v0.y += c0.y; v1.x += c1.x; v1.y += c1.y;
            }
            *p0 = v0; *p1 = v1;
        }
    }
}

// ---------------- flash attention on tf32 tensor cores --------------------
// CTA: 64 q-rows, 4 warps x 16 rows, 128 threads. Bc = 64.
// smem strides chosen for conflict-free fragment LDS.
#define AT_QS 68
#define AT_VS 72
#define OFF_K 4352            // 64*68
#define OFF_V 8704            // OFF_K + 64*68
#define OFF_P 13312           // OFF_V + 64*72
#define OFF_M 17664           // OFF_P + 64*68
#define AT2_SMEM_BYTES ((OFF_M + 64)*4)

__global__ void __launch_bounds__(128) attn_mma_kernel(const float* __restrict__ q,
                                                       const float* __restrict__ kv,
                                                       const int* __restrict__ mask,
                                                       float* __restrict__ out) {
    extern __shared__ float sm[];
    float* sQ = sm;
    float* sK = sm + OFF_K;
    float* sV = sm + OFF_V;
    float* sP = sm + OFF_P;
    int*  sM = (int*)(sm + OFF_M);

    const int tid = threadIdx.x, lane = tid & 31, wid = tid >> 5;
    const int gr = lane >> 2, gq = lane & 3;
    const int wm = wid * 16;
    const int qt = blockIdx.x, h = blockIdx.y, b = blockIdx.z;
    const size_t qbase = ((size_t)(b * SEQ + qt * 64)) * DIM + h * DHEAD;

    // load Q tile (already tf32-rounded by producer)
#pragma unroll
    for (int p = 0; p < 8; p++) {
        const int lin = p * 128 + tid;
        const int r = lin >> 4, c = (lin & 15) * 4;
        *(float4*)&sQ[r * AT_QS + c] = *(const float4*)&q[qbase + (size_t)r * DIM + c];
    }

    float m0 = -1e30f, m1 = -1e30f, l0 = 0.f, l1 = 0.f;
    float o[8][4];
#pragma unroll
    for (int d = 0; d < 8; d++)
#pragma unroll
        for (int j = 0; j < 4; j++) o[d][j] = 0.f;

    for (int jt = 0; jt < SEQ / 64; jt++) {
        __syncthreads();
        const size_t kbase = (size_t)(b * SEQ + jt * 64) * (2 * DHEAD);
#pragma unroll
        for (int p = 0; p < 16; p++) {
            const int lin = p * 128 + tid;
            const int j = lin >> 5, cc = (lin & 31) * 4;
            float4 v = *(const float4*)&kv[kbase + (size_t)j * 128 + cc];
            if (cc < 64) *(float4*)&sK[j * AT_QS + cc] = v;
            else         *(float4*)&sV[j * AT_VS + cc - 64] = v;
        }
        if (tid < 64) sM[tid] = mask[b * SEQ + jt * 64 + tid];
        __syncthreads();

        // ---- S = Q K^T : 8 n-tiles of m16n8, k = 64 in 8 steps ----
        float sc[8][4];
#pragma unroll
        for (int n = 0; n < 8; n++)
#pragma unroll
            for (int j = 0; j < 4; j++) sc[n][j] = 0.f;

#pragma unroll
        for (int k8 = 0; k8 < 8; k8++) {
            const int kc = k8 * 8 + gq;
            unsigned a0 = __float_as_uint(sQ[(wm + gr) * AT_QS + kc]);
            unsigned a1 = __float_as_uint(sQ[(wm + gr + 8) * AT_QS + kc]);
            unsigned a2 = __float_as_uint(sQ[(wm + gr) * AT_QS + kc + 4]);
            unsigned a3 = __float_as_uint(sQ[(wm + gr + 8) * AT_QS + kc + 4]);
#pragma unroll
            for (int n = 0; n < 8; n++) {
                unsigned b0 = __float_as_uint(sK[(n * 8 + gr) * AT_QS + kc]);
                unsigned b1 = __float_as_uint(sK[(n * 8 + gr) * AT_QS + kc + 4]);
                asm volatile(
                    "mma.sync.aligned.m16n8k8.row.col.f32.tf32.tf32.f32 "
                    "{%0,%1,%2,%3},{%4,%5,%6,%7},{%8,%9},{%0,%1,%2,%3};"
                    : "+f"(sc[n][0]), "+f"(sc[n][1]), "+f"(sc[n][2]), "+f"(sc[n][3])
                    : "r"(a0), "r"(a1), "r"(a2), "r"(a3), "r"(b0), "r"(b1));
            }
        }

        // ---- mask + online softmax (rows wm+gr and wm+gr+8) ----
#pragma unroll
        for (int n = 0; n < 8; n++) {
            const int c0 = n * 8 + 2 * gq;
            if (sM[c0] == 0)     { sc[n][0] = -1e30f; sc[n][2] = -1e30f; }
            if (sM[c0 + 1] == 0) { sc[n][1] = -1e30f; sc[n][3] = -1e30f; }
        }
        float mx0 = -1e30f, mx1 = -1e30f;
#pragma unroll
        for (int n = 0; n < 8; n++) {
            mx0 = fmaxf(mx0, fmaxf(sc[n][0], sc[n][1]));
            mx1 = fmaxf(mx1, fmaxf(sc[n][2], sc[n][3]));
        }
        mx0 = fmaxf(mx0, __shfl_xor_sync(0xffffffffu, mx0, 1));
        mx0 = fmaxf(mx0, __shfl_xor_sync(0xffffffffu, mx0, 2));
        mx1 = fmaxf(mx1, __shfl_xor_sync(0xffffffffu, mx1, 1));
        mx1 = fmaxf(mx1, __shfl_xor_sync(0xffffffffu, mx1, 2));
        const float mn0 = fmaxf(m0, mx0), mn1 = fmaxf(m1, mx1);
        const float corr0 = __expf(m0 - mn0), corr1 = __expf(m1 - mn1);
        float rs0 = 0.f, rs1 = 0.f;
#pragma unroll
        for (int n = 0; n < 8; n++) {
            float p0 = __expf(sc[n][0] - mn0);
            float p1 = __expf(sc[n][1] - mn0);
            float p2 = __expf(sc[n][2] - mn1);
            float p3 = __expf(sc[n][3] - mn1);
            rs0 += p0 + p1; rs1 += p2 + p3;
            *(float2*)&sP[(wm + gr) * AT_QS + n * 8 + 2 * gq] =
                make_float2(round_tf32(p0), round_tf32(p1));
            *(float2*)&sP[(wm + gr + 8) * AT_QS + n * 8 + 2 * gq] =
                make_float2(round_tf32(p2), round_tf32(p3));
        }
        rs0 += __shfl_xor_sync(0xffffffffu, rs0, 1);
        rs0 += __shfl_xor_sync(0xffffffffu, rs0, 2);
        rs1 += __shfl_xor_sync(0xffffffffu, rs1, 1);
        rs1 += __shfl_xor_sync(0xffffffffu, rs1, 2);
        l0 = l0 * corr0 + rs0; m0 = mn0;
        l1 = l1 * corr1 + rs1; m1 = mn1;
#pragma unroll
        for (int d = 0; d < 8; d++) {
            o[d][0] *= corr0; o[d][1] *= corr0;
            o[d][2] *= corr1; o[d][3] *= corr1;
        }
        __syncwarp();

        // ---- O += P V : contraction over c (8 steps), 8 d-tiles ----
#pragma unroll
        for (int k8 = 0; k8 < 8; k8++) {
            const int kc = k8 * 8 + gq;
            unsigned a0 = __float_as_uint(sP[(wm + gr) * AT_QS + kc]);
            unsigned a1 = __float_as_uint(sP[(wm + gr + 8) * AT_QS + kc]);
            unsigned a2 = __float_as_uint(sP[(wm + gr) * AT_QS + kc + 4]);
            unsigned a3 = __float_as_uint(sP[(wm + gr + 8) * AT_QS + kc + 4]);
#pragma unroll
            for (int dt = 0; dt < 8; dt++) {
                unsigned b0 = __float_as_uint(sV[kc * AT_VS + dt * 8 + gr]);
                unsigned b1 = __float_as_uint(sV[(kc + 4) * AT_VS + dt * 8 + gr]);
                asm volatile(
                    "mma.sync.aligned.m16n8k8.row.col.f32.tf32.tf32.f32 "
                    "{%0,%1,%2,%3},{%4,%5,%6,%7},{%8,%9},{%0,%1,%2,%3};"
                    : "+f"(o[dt][0]), "+f"(o[dt][1]), "+f"(o[dt][2]), "+f"(o[dt][3])
                    : "r"(a0), "r"(a1), "r"(a2), "r"(a3), "r"(b0), "r"(b1));
            }
        }
    }

    const float inv0 = 1.f / l0, inv1 = 1.f / l1;
#pragma unroll
    for (int dt = 0; dt < 8; dt++) {
        const int col = dt * 8 + 2 * gq;
        *(float2*)&out[qbase + (size_t)(wm + gr) * DIM + col] =
            make_float2(round_tf32(o[dt][0] * inv0), round_tf32(o[dt][1] * inv0));
        *(float2*)&out[qbase + (size_t)(wm + gr + 8) * DIM + col] =
            make_float2(round_tf32(o[dt][2] * inv1), round_tf32(o[dt][3] * inv1));
    }
}

// ---------------- SwiGLU (outputs tf32-rounded) ----------------
__global__ void __launch_bounds__(256) silu_mul_kernel(const float* __restrict__ h,
                                                       float* __restrict__ ff) {
    const size_t idx = ((size_t)blockIdx.x * blockDim.x + threadIdx.x) * 4;
    const size_t row = idx >> 12;
    const size_t c = idx & (FFI - 1);
    const float* hp = h + row * (2 * FFI);
    float4 a = *(const float4*)&hp[c];
    float4 g = *(const float4*)&hp[FFI + c];
    float4 o;
    o.x = round_tf32(a.x * (g.x / (1.f + __expf(-g.x))));
    o.y = round_tf32(a.y * (g.y / (1.f + __expf(-g.y))));
    o.z = round_tf32(a.z * (g.z / (1.f + __expf(-g.z))));
    o.w = round_tf32(a.w * (g.w / (1.f + __expf(-g.w))));
    *(float4*)&ff[idx] = o;
}

// ---------------- launch --------------------------------------------------
extern "C" void kernel_launch(void* const* d_in, const int* in_sizes, int n_in,
                              void* d_out, int out_size) {
    (void)in_sizes; (void)n_in; (void)out_size;
    const float* x        = (const float*)d_in[0];
    const float* context  = (const float*)d_in[1];
    const int*   mask     = (const int*)  d_in[2];
    const float* gamma    = (const float*)d_in[3];
    const float* ctxgamma = (const float*)d_in[4];
    const float* Wq       = (const float*)d_in[5];
    const float* Wkv      = (const float*)d_in[6];
    const float* Wout     = (const float*)d_in[7];
    const float* Wff1     = (const float*)d_in[8];
    const float* Wff2     = (const float*)d_in[9];
    float* out = (float*)d_out;

    float *xn, *cn, *qb, *kvb, *attnb, *hb, *ffb, *wr;
    cudaGetSymbolAddress((void**)&xn,    g_xn);
    cudaGetSymbolAddress((void**)&cn,    g_cn);
    cudaGetSymbolAddress((void**)&qb,    g_q);
    cudaGetSymbolAddress((void**)&kvb,   g_kv);
    cudaGetSymbolAddress((void**)&attnb, g_attn);
    cudaGetSymbolAddress((void**)&hb,    g_h);
    cudaGetSymbolAddress((void**)&ffb,   g_ff);
    cudaGetSymbolAddress((void**)&wr,    g_wr);

    cudaFuncSetAttribute(attn_mma_kernel, cudaFuncAttributeMaxDynamicSharedMemorySize, AT2_SMEM_BYTES);
    cudaFuncSetAttribute(tf32_gemm_kernel<0>, cudaFuncAttributeMaxDynamicSharedMemorySize, GEMM_SMEM_BYTES);
    cudaFuncSetAttribute(tf32_gemm_kernel<1>, cudaFuncAttributeMaxDynamicSharedMemorySize, GEMM_SMEM_BYTES);
    cudaFuncSetAttribute(tf32_gemm_kernel<2>, cudaFuncAttributeMaxDynamicSharedMemorySize, GEMM_SMEM_BYTES);
    cudaFuncSetAttribute(tf32_gemm_kernel<3>, cudaFuncAttributeMaxDynamicSharedMemorySize, GEMM_SMEM_BYTES);

    // round weights to tf32
    round_kernel<<<(1048576/4+255)/256, 256>>>(Wq,   wr + WQ_OFF,   1048576/4);
    round_kernel<<<(131072/4+255)/256,  256>>>(Wkv,  wr + WKV_OFF,  131072/4);
    round_kernel<<<(1048576/4+255)/256, 256>>>(Wout, wr + WOUT_OFF, 1048576/4);
    round_kernel<<<(8388608/4+255)/256, 256>>>(Wff1, wr + WFF1_OFF, 8388608/4);
    round_kernel<<<(4194304/4+255)/256, 256>>>(Wff2, wr + WFF2_OFF, 4194304/4);

    // layernorms (tf32-rounded outputs)
    ln_kernel<<<ROWS, 256>>>(x, gamma, xn);
    ln_kernel<<<ROWS, 256>>>(context, ctxgamma, cn);

    // q = round((xn @ Wq) * scale)
    tf32_gemm_kernel<1><<<dim3(DIM/128, ROWS/128), 256, GEMM_SMEM_BYTES>>>(
        ROWS, DIM, DIM, xn, wr + WQ_OFF, qb, 0.125f);

    // kv = round(cn @ Wkv)
    tf32_gemm_kernel<3><<<dim3(1, ROWS/128), 256, GEMM_SMEM_BYTES>>>(
        ROWS, 2*DHEAD, DIM, cn, wr + WKV_OFF, kvb, 1.f);

    // attention (tensor-core flash)
    attn_mma_kernel<<<dim3(SEQ/64, HEADS, BATCH), 128, AT2_SMEM_BYTES>>>(qb, kvb, mask, attnb);

    // out = attn @ Wout
    tf32_gemm_kernel<0><<<dim3(DIM/128, ROWS/128), 256, GEMM_SMEM_BYTES>>>(
        ROWS, DIM, DIM, attnb, wr + WOUT_OFF, out, 1.f);

    // h = xn @ Wff1
    tf32_gemm_kernel<0><<<dim3((2*FFI)/128, ROWS/128), 256, GEMM_SMEM_BYTES>>>(
        ROWS, 2*FFI, DIM, xn, wr + WFF1_OFF, hb, 1.f);

    // ff = round(silu(gate) * a)
    silu_mul_kernel<<<(int)((ROWS*(size_t)FFI)/4/256), 256>>>(hb, ffb);

    // out += ff @ Wff2
    tf32_gemm_kernel<2><<<dim3(DIM/128, ROWS/128), 256, GEMM_SMEM_BYTES>>>(
        ROWS, DIM, FFI, ffb, wr + WFF2_OFF, out, 1.f);
}

// round 4
// speedup vs baseline: 3.3795x; 1.0321x over previous
#include <cuda_runtime.h>
#include <math.h>
#include <stdint.h>

// ---------------- problem constants ----------------
#define BATCH 2
#define SEQ   2048
#define DIM   1024
#define HEADS 16
#define DHEAD 64
#define FFI   4096
#define ROWS  (BATCH*SEQ)

// ---------------- scratch ----------------
__device__ float g_xn  [(size_t)ROWS*DIM];
__device__ float g_cn  [(size_t)ROWS*DIM];
__device__ float g_q   [(size_t)ROWS*DIM];
__device__ float g_kv  [(size_t)ROWS*2*DHEAD];
__device__ float g_attn[(size_t)ROWS*DIM];
__device__ float g_ff  [(size_t)ROWS*FFI];
__device__ float g_wr  [14811136];   // tf32-rounded weights

#define WQ_OFF   0
#define WKV_OFF  1048576
#define WOUT_OFF 1179648
#define WFF1_OFF 2228224
#define WFF2_OFF 10616832

__device__ __forceinline__ float round_tf32(float x) {
    uint32_t u;
    asm("cvt.rna.tf32.f32 %0, %1;" : "=r"(u) : "f"(x));
    return __uint_as_float(u);
}

__device__ __forceinline__ void cp16(void* smem_ptr, const void* gptr) {
    unsigned sa;
    asm("{.reg .u64 t; cvta.to.shared.u64 t, %1; cvt.u32.u64 %0, t;}" : "=r"(sa) : "l"(smem_ptr));
    asm volatile("cp.async.cg.shared.global [%0], [%1], 16;" :: "r"(sa), "l"(gptr));
}

// ---------------- weight rounding ----------------
__global__ void __launch_bounds__(256) round_kernel(const float* __restrict__ in,
                                                    float* __restrict__ out, int n4) {
    int i = blockIdx.x * blockDim.x + threadIdx.x;
    if (i < n4) {
        float4 v = ((const float4*)in)[i];
        v.x = round_tf32(v.x); v.y = round_tf32(v.y);
        v.z = round_tf32(v.z); v.w = round_tf32(v.w);
        ((float4*)out)[i] = v;
    }
}

// Wff1: round + interleave columns so (a, gate) become adjacent pairs.
// in: [1024][8192] (a = cols 0..4095, gate = 4096..8191)
// out[k][2j] = a[k][j], out[k][2j+1] = gate[k][j]
__global__ void __launch_bounds__(256) round_permute_kernel(const float* __restrict__ in,
                                                            float* __restrict__ out) {
    const int idx = blockIdx.x * 256 + threadIdx.x;   // over 1024*4096
    const int k = idx >> 12;
    const int j = idx & 4095;
    const float a = round_tf32(in[(size_t)k * 8192 + j]);
    const float g = round_tf32(in[(size_t)k * 8192 + 4096 + j]);
    float2 v = make_float2(a, g);
    *(float2*)&out[(size_t)k * 8192 + 2 * j] = v;
}

// ---------------- LayerNorm (outputs tf32-rounded) ----------------
__global__ void __launch_bounds__(256) ln_kernel(const float* __restrict__ in,
                                                 const float* __restrict__ g,
                                                 float* __restrict__ out) {
    const int row = blockIdx.x;
    const int t = threadIdx.x;
    const float* p = in + (size_t)row * DIM;
    float4 v = *(const float4*)&p[t * 4];
    float s  = v.x + v.y + v.z + v.w;
    float sq = v.x*v.x + v.y*v.y + v.z*v.z + v.w*v.w;
#pragma unroll
    for (int off = 16; off; off >>= 1) {
        s  += __shfl_xor_sync(0xffffffffu, s,  off);
        sq += __shfl_xor_sync(0xffffffffu, sq, off);
    }
    __shared__ float rs[8], rq[8];
    if ((t & 31) == 0) { rs[t >> 5] = s; rq[t >> 5] = sq; }
    __syncthreads();
    float ts = 0.f, tq = 0.f;
#pragma unroll
    for (int i = 0; i < 8; i++) { ts += rs[i]; tq += rq[i]; }
    const float mu  = ts * (1.f / DIM);
    const float var = tq * (1.f / DIM) - mu * mu;
    const float rstd = rsqrtf(var + 1e-5f);
    float4 gv = *(const float4*)&g[t * 4];
    float4 o;
    o.x = round_tf32((v.x - mu) * rstd * gv.x);
    o.y = round_tf32((v.y - mu) * rstd * gv.y);
    o.z = round_tf32((v.z - mu) * rstd * gv.z);
    o.w = round_tf32((v.w - mu) * rstd * gv.w);
    *(float4*)&out[(size_t)row * DIM + t * 4] = o;
}

// ---------------- TF32 tensor-core GEMM ----------------
// EPI: 0 store, 1 store*scale rounded, 2 accumulate, 3 store rounded,
//      4 SwiGLU fused: N interleaved (a,gate); writes N/2-wide rounded output
#define AS_STRIDE 36
#define BS_STRIDE 136
#define STAGE_FLOATS (128*AS_STRIDE + 32*BS_STRIDE)
#define GEMM_SMEM_BYTES (2*STAGE_FLOATS*4)

template<int EPI>
__global__ void __launch_bounds__(256) tf32_gemm_kernel(
        int M, int N, int K,
        const float* __restrict__ A, const float* __restrict__ B,
        float* __restrict__ C, float scale) {
    extern __shared__ float sm[];
    const int tid = threadIdx.x, lane = tid & 31, wid = tid >> 5;
    const int wm = (wid & 1) * 64, wn = (wid >> 1) * 32;
    const int bm = blockIdx.y * 128, bn = blockIdx.x * 128;
    const int r = lane >> 2, cc = lane & 3;

    const int am = tid >> 3, ak = (tid & 7) * 4;
    const int bk = wid, bnn = lane * 4;

    float acc[4][4][4] = {};
    const int T = K / 32;

    {
        float* As = sm;
        float* Bs = sm + 128 * AS_STRIDE;
#pragma unroll
        for (int p = 0; p < 4; p++)
            cp16(&As[(am + p * 32) * AS_STRIDE + ak], &A[(size_t)(bm + am + p * 32) * K + ak]);
#pragma unroll
        for (int p = 0; p < 4; p++)
            cp16(&Bs[(bk + p * 8) * BS_STRIDE + bnn], &B[(size_t)(bk + p * 8) * N + bn + bnn]);
        asm volatile("cp.async.commit_group;");
    }

    for (int t = 0; t < T; t++) {
        if (t + 1 < T) {
            const int s = (t + 1) & 1;
            const int k0 = (t + 1) * 32;
            float* As = sm + s * STAGE_FLOATS;
            float* Bs = As + 128 * AS_STRIDE;
#pragma unroll
            for (int p = 0; p < 4; p++)
                cp16(&As[(am + p * 32) * AS_STRIDE + ak],
                     &A[(size_t)(bm + am + p * 32) * K + k0 + ak]);
#pragma unroll
            for (int p = 0; p < 4; p++)
                cp16(&Bs[(bk + p * 8) * BS_STRIDE + bnn],
                     &B[(size_t)(k0 + bk + p * 8) * N + bn + bnn]);
            asm volatile("cp.async.commit_group;");
            asm volatile("cp.async.wait_group 1;");
        } else {
            asm volatile("cp.async.wait_group 0;");
        }
        __syncthreads();

        const int s = t & 1;
        const float* As = sm + s * STAGE_FLOATS;
        const float* Bs = As + 128 * AS_STRIDE;
#pragma unroll
        for (int kk = 0; kk < 4; kk++) {
            const int k = kk * 8;
            unsigned a[4][4], b[4][2];
#pragma unroll
            for (int mi = 0; mi < 4; mi++) {
                const float* ap = As + (wm + mi * 16) * AS_STRIDE + k;
                a[mi][0] = __float_as_uint(ap[r * AS_STRIDE + cc]);
                a[mi][1] = __float_as_uint(ap[(r + 8) * AS_STRIDE + cc]);
                a[mi][2] = __float_as_uint(ap[r * AS_STRIDE + cc + 4]);
                a[mi][3] = __float_as_uint(ap[(r + 8) * AS_STRIDE + cc + 4]);
            }
#pragma unroll
            for (int ni = 0; ni < 4; ni++) {
                const float* bp = Bs + k * BS_STRIDE + wn + ni * 8;
                b[ni][0] = __float_as_uint(bp[cc * BS_STRIDE + r]);
                b[ni][1] = __float_as_uint(bp[(cc + 4) * BS_STRIDE + r]);
            }
#pragma unroll
            for (int mi = 0; mi < 4; mi++)
#pragma unroll
                for (int ni = 0; ni < 4; ni++)
                    asm volatile(
                        "mma.sync.aligned.m16n8k8.row.col.f32.tf32.tf32.f32 "
                        "{%0,%1,%2,%3},{%4,%5,%6,%7},{%8,%9},{%0,%1,%2,%3};"
                        : "+f"(acc[mi][ni][0]), "+f"(acc[mi][ni][1]),
                          "+f"(acc[mi][ni][2]), "+f"(acc[mi][ni][3])
                        : "r"(a[mi][0]), "r"(a[mi][1]), "r"(a[mi][2]), "r"(a[mi][3]),
                          "r"(b[ni][0]), "r"(b[ni][1]));
        }
        __syncthreads();
    }

#pragma unroll
    for (int mi = 0; mi < 4; mi++) {
#pragma unroll
        for (int ni = 0; ni < 4; ni++) {
            const int row0 = bm + wm + mi * 16 + r;
            const int col  = bn + wn + ni * 8 + cc * 2;
            if (EPI == 4) {
                // acc[0]=a(row0), acc[1]=gate(row0); acc[2]=a(row0+8), acc[3]=gate(row0+8)
                const float g0 = acc[mi][ni][1], g1 = acc[mi][ni][3];
                const float f0 = round_tf32(acc[mi][ni][0] * (g0 / (1.f + __expf(-g0))));
                const float f1 = round_tf32(acc[mi][ni][2] * (g1 / (1.f + __expf(-g1))));
                const int colh = col >> 1;
                const int Nh = N >> 1;
                C[(size_t)row0 * Nh + colh] = f0;
                C[(size_t)(row0 + 8) * Nh + colh] = f1;
            } else {
                float2* p0 = (float2*)&C[(size_t)row0 * N + col];
                float2* p1 = (float2*)&C[(size_t)(row0 + 8) * N + col];
                float2 v0 = make_float2(acc[mi][ni][0], acc[mi][ni][1]);
                float2 v1 = make_float2(acc[mi][ni][2], acc[mi][ni][3]);
                if (EPI == 1) {
                    v0.x = round_tf32(v0.x * scale); v0.y = round_tf32(v0.y * scale);
                    v1.x = round_tf32(v1.x * scale); v1.y = round_tf32(v1.y * scale);
                }
                if (EPI == 3) {
                    v0.x = round_tf32(v0.x); v0.y = round_tf32(v0.y);
                    v1.x = round_tf32(v1.x); v1.y = round_tf32(v1.y);
                }
                if (EPI == 2) {
                    float2 c0 = *p0, c1 = *p1;
                    v0.x += c0.x; v0.y += c0.y; v1.x += c1.x; v1.y += c1.y;
                }
                *p0 = v0; *p1 = v1;
            }
        }
    }
}

// ---------------- flash attention, tf32 mma + cp.async double buffer ------
// smem layout (floats): sQ[64*68] | sP[64*68] | stage0 | stage1
// stage = K[64*68] + V[64*72] + mask[64 words]
#define AT_QS 68
#define AT_VS 72
#define AT_OFF_P   4352
#define AT_OFF_ST  8704
#define AT_STAGE   9024
#define AT2_SMEM_BYTES ((AT_OFF_ST + 2*AT_STAGE)*4)

__global__ void __launch_bounds__(128) attn_mma_kernel(const float* __restrict__ q,
                                                       const float* __restrict__ kv,
                                                       const int* __restrict__ mask,
                                                       float* __restrict__ out) {
    extern __shared__ float sm[];
    float* sQ = sm;
    float* sP = sm + AT_OFF_P;

    const int tid = threadIdx.x, lane = tid & 31, wid = tid >> 5;
    const int gr = lane >> 2, gq = lane & 3;
    const int wm = wid * 16;
    const int qt = blockIdx.x, h = blockIdx.y, b = blockIdx.z;
    const size_t qbase = ((size_t)(b * SEQ + qt * 64)) * DIM + h * DHEAD;

    // load Q tile (tf32-rounded by producer)
#pragma unroll
    for (int p = 0; p < 8; p++) {
        const int lin = p * 128 + tid;
        const int r = lin >> 4, c = (lin & 15) * 4;
        *(float4*)&sQ[r * AT_QS + c] = *(const float4*)&q[qbase + (size_t)r * DIM + c];
    }

    // stage-issue helper (16 cp16/thread for kv, 16 threads for mask)
    auto issue = [&](int jt, int s) {
        float* sK = sm + AT_OFF_ST + s * AT_STAGE;
        float* sV = sK + 64 * AT_QS;
        int*  sMs = (int*)(sV + 64 * AT_VS);
        const size_t kbase = (size_t)(b * SEQ + jt * 64) * 128;
#pragma unroll
        for (int p = 0; p < 16; p++) {
            const int lin = p * 128 + tid;
            const int j = lin >> 5, cidx = (lin & 31) * 4;
            const float* src = &kv[kbase + (size_t)j * 128 + cidx];
            if (cidx < 64) cp16(&sK[j * AT_QS + cidx], src);
            else           cp16(&sV[j * AT_VS + cidx - 64], src);
        }
        if (tid < 16) cp16(&sMs[tid * 4], &mask[b * SEQ + jt * 64 + tid * 4]);
        asm volatile("cp.async.commit_group;");
    };

    issue(0, 0);

    float m0 = -1e30f, m1 = -1e30f, l0 = 0.f, l1 = 0.f;
    float o[8][4];
#pragma unroll
    for (int d = 0; d < 8; d++)
#pragma unroll
        for (int j = 0; j < 4; j++) o[d][j] = 0.f;

    for (int jt = 0; jt < SEQ / 64; jt++) {
        if (jt + 1 < SEQ / 64) {
            issue(jt + 1, (jt + 1) & 1);
            asm volatile("cp.async.wait_group 1;");
        } else {
            asm volatile("cp.async.wait_group 0;");
        }
        __syncthreads();

        const int s = jt & 1;
        const float* sK = sm + AT_OFF_ST + s * AT_STAGE;
        const float* sV = sK + 64 * AT_QS;
        const int*  sM = (const int*)(sV + 64 * AT_VS);

        // ---- S = Q K^T ----
        float sc[8][4];
#pragma unroll
        for (int n = 0; n < 8; n++)
#pragma unroll
            for (int j = 0; j < 4; j++) sc[n][j] = 0.f;

#pragma unroll
        for (int k8 = 0; k8 < 8; k8++) {
            const int kc = k8 * 8 + gq;
            unsigned a0 = __float_as_uint(sQ[(wm + gr) * AT_QS + kc]);
            unsigned a1 = __float_as_uint(sQ[(wm + gr + 8) * AT_QS + kc]);
            unsigned a2 = __float_as_uint(sQ[(wm + gr) * AT_QS + kc + 4]);
            unsigned a3 = __float_as_uint(sQ[(wm + gr + 8) * AT_QS + kc + 4]);
#pragma unroll
            for (int n = 0; n < 8; n++) {
                unsigned b0 = __float_as_uint(sK[(n * 8 + gr) * AT_QS + kc]);
                unsigned b1 = __float_as_uint(sK[(n * 8 + gr) * AT_QS + kc + 4]);
                asm volatile(
                    "mma.sync.aligned.m16n8k8.row.col.f32.tf32.tf32.f32 "
                    "{%0,%1,%2,%3},{%4,%5,%6,%7},{%8,%9},{%0,%1,%2,%3};"
                    : "+f"(sc[n][0]), "+f"(sc[n][1]), "+f"(sc[n][2]), "+f"(sc[n][3])
                    : "r"(a0), "r"(a1), "r"(a2), "r"(a3), "r"(b0), "r"(b1));
            }
        }

        // ---- mask + online softmax ----
#pragma unroll
        for (int n = 0; n < 8; n++) {
            const int c0 = n * 8 + 2 * gq;
            if (sM[c0] == 0)     { sc[n][0] = -1e30f; sc[n][2] = -1e30f; }
            if (sM[c0 + 1] == 0) { sc[n][1] = -1e30f; sc[n][3] = -1e30f; }
        }
        float mx0 = -1e30f, mx1 = -1e30f;
#pragma unroll
        for (int n = 0; n < 8; n++) {
            mx0 = fmaxf(mx0, fmaxf(sc[n][0], sc[n][1]));
            mx1 = fmaxf(mx1, fmaxf(sc[n][2], sc[n][3]));
        }
        mx0 = fmaxf(mx0, __shfl_xor_sync(0xffffffffu, mx0, 1));
        mx0 = fmaxf(mx0, __shfl_xor_sync(0xffffffffu, mx0, 2));
        mx1 = fmaxf(mx1, __shfl_xor_sync(0xffffffffu, mx1, 1));
        mx1 = fmaxf(mx1, __shfl_xor_sync(0xffffffffu, mx1, 2));
        const float mn0 = fmaxf(m0, mx0), mn1 = fmaxf(m1, mx1);
        const float corr0 = __expf(m0 - mn0), corr1 = __expf(m1 - mn1);
        float rs0 = 0.f, rs1 = 0.f;
#pragma unroll
        for (int n = 0; n < 8; n++) {
            float p0 = __expf(sc[n][0] - mn0);
            float p1 = __expf(sc[n][1] - mn0);
            float p2 = __expf(sc[n][2] - mn1);
            float p3 = __expf(sc[n][3] - mn1);
            rs0 += p0 + p1; rs1 += p2 + p3;
            *(float2*)&sP[(wm + gr) * AT_QS + n * 8 + 2 * gq] =
                make_float2(round_tf32(p0), round_tf32(p1));
            *(float2*)&sP[(wm + gr + 8) * AT_QS + n * 8 + 2 * gq] =
                make_float2(round_tf32(p2), round_tf32(p3));
        }
        rs0 += __shfl_xor_sync(0xffffffffu, rs0, 1);
        rs0 += __shfl_xor_sync(0xffffffffu, rs0, 2);
        rs1 += __shfl_xor_sync(0xffffffffu, rs1, 1);
        rs1 += __shfl_xor_sync(0xffffffffu, rs1, 2);
        l0 = l0 * corr0 + rs0; m0 = mn0;
        l1 = l1 * corr1 + rs1; m1 = mn1;
#pragma unroll
        for (int d = 0; d < 8; d++) {
            o[d][0] *= corr0; o[d][1] *= corr0;
            o[d][2] *= corr1; o[d][3] *= corr1;
        }
        __syncwarp();

        // ---- O += P V ----
#pragma unroll
        for (int k8 = 0; k8 < 8; k8++) {
            const int kc = k8 * 8 + gq;
            unsigned a0 = __float_as_uint(sP[(wm + gr) * AT_QS + kc]);
            unsigned a1 = __float_as_uint(sP[(wm + gr + 8) * AT_QS + kc]);
            unsigned a2 = __float_as_uint(sP[(wm + gr) * AT_QS + kc + 4]);
            unsigned a3 = __float_as_uint(sP[(wm + gr + 8) * AT_QS + kc + 4]);
#pragma unroll
            for (int dt = 0; dt < 8; dt++) {
                unsigned b0 = __float_as_uint(sV[kc * AT_VS + dt * 8 + gr]);
                unsigned b1 = __float_as_uint(sV[(kc + 4) * AT_VS + dt * 8 + gr]);
                asm volatile(
                    "mma.sync.aligned.m16n8k8.row.col.f32.tf32.tf32.f32 "
                    "{%0,%1,%2,%3},{%4,%5,%6,%7},{%8,%9},{%0,%1,%2,%3};"
                    : "+f"(o[dt][0]), "+f"(o[dt][1]), "+f"(o[dt][2]), "+f"(o[dt][3])
                    : "r"(a0), "r"(a1), "r"(a2), "r"(a3), "r"(b0), "r"(b1));
            }
        }
        __syncthreads();   // stage reuse barrier (before next issue overwrites)
    }

    const float inv0 = 1.f / l0, inv1 = 1.f / l1;
#pragma unroll
    for (int dt = 0; dt < 8; dt++) {
        const int col = dt * 8 + 2 * gq;
        *(float2*)&out[qbase + (size_t)(wm + gr) * DIM + col] =
            make_float2(round_tf32(o[dt][0] * inv0), round_tf32(o[dt][1] * inv0));
        *(float2*)&out[qbase + (size_t)(wm + gr + 8) * DIM + col] =
            make_float2(round_tf32(o[dt][2] * inv1), round_tf32(o[dt][3] * inv1));
    }
}

// ---------------- launch --------------------------------------------------
extern "C" void kernel_launch(void* const* d_in, const int* in_sizes, int n_in,
                              void* d_out, int out_size) {
    (void)in_sizes; (void)n_in; (void)out_size;
    const float* x        = (const float*)d_in[0];
    const float* context  = (const float*)d_in[1];
    const int*   mask     = (const int*)  d_in[2];
    const float* gamma    = (const float*)d_in[3];
    const float* ctxgamma = (const float*)d_in[4];
    const float* Wq       = (const float*)d_in[5];
    const float* Wkv      = (const float*)d_in[6];
    const float* Wout     = (const float*)d_in[7];
    const float* Wff1     = (const float*)d_in[8];
    const float* Wff2     = (const float*)d_in[9];
    float* out = (float*)d_out;

    float *xn, *cn, *qb, *kvb, *attnb, *ffb, *wr;
    cudaGetSymbolAddress((void**)&xn,    g_xn);
    cudaGetSymbolAddress((void**)&cn,    g_cn);
    cudaGetSymbolAddress((void**)&qb,    g_q);
    cudaGetSymbolAddress((void**)&kvb,   g_kv);
    cudaGetSymbolAddress((void**)&attnb, g_attn);
    cudaGetSymbolAddress((void**)&ffb,   g_ff);
    cudaGetSymbolAddress((void**)&wr,    g_wr);

    cudaFuncSetAttribute(attn_mma_kernel, cudaFuncAttributeMaxDynamicSharedMemorySize, AT2_SMEM_BYTES);
    cudaFuncSetAttribute(tf32_gemm_kernel<0>, cudaFuncAttributeMaxDynamicSharedMemorySize, GEMM_SMEM_BYTES);
    cudaFuncSetAttribute(tf32_gemm_kernel<1>, cudaFuncAttributeMaxDynamicSharedMemorySize, GEMM_SMEM_BYTES);
    cudaFuncSetAttribute(tf32_gemm_kernel<2>, cudaFuncAttributeMaxDynamicSharedMemorySize, GEMM_SMEM_BYTES);
    cudaFuncSetAttribute(tf32_gemm_kernel<3>, cudaFuncAttributeMaxDynamicSharedMemorySize, GEMM_SMEM_BYTES);
    cudaFuncSetAttribute(tf32_gemm_kernel<4>, cudaFuncAttributeMaxDynamicSharedMemorySize, GEMM_SMEM_BYTES);

    // round weights to tf32 (Wff1 also interleaved for SwiGLU fusion)
    round_kernel<<<(1048576/4+255)/256, 256>>>(Wq,   wr + WQ_OFF,   1048576/4);
    round_kernel<<<(131072/4+255)/256,  256>>>(Wkv,  wr + WKV_OFF,  131072/4);
    round_kernel<<<(1048576/4+255)/256, 256>>>(Wout, wr + WOUT_OFF, 1048576/4);
    round_permute_kernel<<<(1024*4096)/256, 256>>>(Wff1, wr + WFF1_OFF);
    round_kernel<<<(4194304/4+255)/256, 256>>>(Wff2, wr + WFF2_OFF, 4194304/4);

    // layernorms (tf32-rounded outputs)
    ln_kernel<<<ROWS, 256>>>(x, gamma, xn);
    ln_kernel<<<ROWS, 256>>>(context, ctxgamma, cn);

    // q = round((xn @ Wq) * scale)
    tf32_gemm_kernel<1><<<dim3(DIM/128, ROWS/128), 256, GEMM_SMEM_BYTES>>>(
        ROWS, DIM, DIM, xn, wr + WQ_OFF, qb, 0.125f);

    // kv = round(cn @ Wkv)
    tf32_gemm_kernel<3><<<dim3(1, ROWS/128), 256, GEMM_SMEM_BYTES>>>(
        ROWS, 2*DHEAD, DIM, cn, wr + WKV_OFF, kvb, 1.f);

    // attention (tensor-core flash, double-buffered KV)
    attn_mma_kernel<<<dim3(SEQ/64, HEADS, BATCH), 128, AT2_SMEM_BYTES>>>(qb, kvb, mask, attnb);

    // out = attn @ Wout
    tf32_gemm_kernel<0><<<dim3(DIM/128, ROWS/128), 256, GEMM_SMEM_BYTES>>>(
        ROWS, DIM, DIM, attnb, wr + WOUT_OFF, out, 1.f);

    // ff = round(silu(gate) * a) fused into h = xn @ Wff1_interleaved
    tf32_gemm_kernel<4><<<dim3((2*FFI)/128, ROWS/128), 256, GEMM_SMEM_BYTES>>>(
        ROWS, 2*FFI, DIM, xn, wr + WFF1_OFF, ffb, 1.f);

    // out += ff @ Wff2
    tf32_gemm_kernel<2><<<dim3(DIM/128, ROWS/128), 256, GEMM_SMEM_BYTES>>>(
        ROWS, DIM, FFI, ffb, wr + WFF2_OFF, out, 1.f);
}

// round 6
// speedup vs baseline: 5.1452x; 1.5225x over previous
#include <cuda_runtime.h>
#include <cuda_fp16.h>
#include <math.h>
#include <stdint.h>

// ---------------- problem constants ----------------
#define BATCH 2
#define SEQ   2048
#define DIM   1024
#define HEADS 16
#define DHEAD 64
#define FFI   4096
#define ROWS  (BATCH*SEQ)

// ---------------- scratch (all fp16 activations) ----------------
__device__ __half g_xn  [(size_t)ROWS*DIM];
__device__ __half g_cn  [(size_t)ROWS*DIM];
__device__ __half g_q   [(size_t)ROWS*DIM];
__device__ __half g_kv  [(size_t)ROWS*2*DHEAD];
__device__ __half g_attn[(size_t)ROWS*DIM];
__device__ __half g_ff  [(size_t)ROWS*FFI];
__device__ __half g_w   [14811136];   // fp16 transposed weights

#define WQ_OFF   0
#define WKV_OFF  1048576
#define WOUT_OFF 1179648
#define WFF1_OFF 2228224
#define WFF2_OFF 10616832

__device__ __forceinline__ unsigned smem_u32(const void* p) {
    unsigned sa;
    asm("{.reg .u64 t; cvta.to.shared.u64 t, %1; cvt.u32.u64 %0, t;}" : "=r"(sa) : "l"(p));
    return sa;
}
__device__ __forceinline__ void cp16(void* smem_ptr, const void* gptr) {
    asm volatile("cp.async.cg.shared.global [%0], [%1], 16;"
                 :: "r"(smem_u32(smem_ptr)), "l"(gptr));
}

#define MMA_F16(C0,C1,C2,C3,A0,A1,A2,A3,B0,B1) \
    asm volatile("mma.sync.aligned.m16n8k16.row.col.f32.f16.f16.f32 " \
        "{%0,%1,%2,%3},{%4,%5,%6,%7},{%8,%9},{%0,%1,%2,%3};" \
        : "+f"(C0), "+f"(C1), "+f"(C2), "+f"(C3) \
        : "r"(A0), "r"(A1), "r"(A2), "r"(A3), "r"(B0), "r"(B1))

// ---------------- preprocessing: transpose f32 -> half [N][K] -------------
__global__ void __launch_bounds__(256) transpose_half_kernel(const float* __restrict__ in,
                                                             __half* __restrict__ out,
                                                             int K, int N) {
    __shared__ float t[32][33];
    const int tx = threadIdx.x, ty = threadIdx.y;   // 32 x 8
    const int n0 = blockIdx.x * 32, k0 = blockIdx.y * 32;
#pragma unroll
    for (int i = 0; i < 32; i += 8)
        t[ty + i][tx] = in[(size_t)(k0 + ty + i) * N + n0 + tx];
    __syncthreads();
#pragma unroll
    for (int i = 0; i < 32; i += 8)
        out[(size_t)(n0 + ty + i) * K + k0 + tx] = __float2half(t[tx][ty + i]);
}

// Wff1: transpose + interleave (a,gate) rows: out row 2j = col j, 2j+1 = col 4096+j
__global__ void __launch_bounds__(256) transpose_swiglu_kernel(const float* __restrict__ in,
                                                               __half* __restrict__ out) {
    __shared__ float ta[32][33], tg[32][33];
    const int tx = threadIdx.x, ty = threadIdx.y;
    const int j0 = blockIdx.x * 32, k0 = blockIdx.y * 32;
#pragma unroll
    for (int i = 0; i < 32; i += 8) {
        ta[ty + i][tx] = in[(size_t)(k0 + ty + i) * 8192 + j0 + tx];
        tg[ty + i][tx] = in[(size_t)(k0 + ty + i) * 8192 + 4096 + j0 + tx];
    }
    __syncthreads();
#pragma unroll
    for (int i = 0; i < 32; i += 8) {
        const int jj = j0 + ty + i;
        out[(size_t)(2 * jj)     * 1024 + k0 + tx] = __float2half(ta[tx][ty + i]);
        out[(size_t)(2 * jj + 1) * 1024 + k0 + tx] = __float2half(tg[tx][ty + i]);
    }
}

// ---------------- LayerNorm (f32 in -> half out) ----------------
__global__ void __launch_bounds__(256) ln_kernel(const float* __restrict__ in,
                                                 const float* __restrict__ g,
                                                 __half* __restrict__ out) {
    const int row = blockIdx.x;
    const int t = threadIdx.x;
    const float* p = in + (size_t)row * DIM;
    float4 v = *(const float4*)&p[t * 4];
    float s  = v.x + v.y + v.z + v.w;
    float sq = v.x*v.x + v.y*v.y + v.z*v.z + v.w*v.w;
#pragma unroll
    for (int off = 16; off; off >>= 1) {
        s  += __shfl_xor_sync(0xffffffffu, s,  off);
        sq += __shfl_xor_sync(0xffffffffu, sq, off);
    }
    __shared__ float rs[8], rq[8];
    if ((t & 31) == 0) { rs[t >> 5] = s; rq[t >> 5] = sq; }
    __syncthreads();
    float ts = 0.f, tq = 0.f;
#pragma unroll
    for (int i = 0; i < 8; i++) { ts += rs[i]; tq += rq[i]; }
    const float mu  = ts * (1.f / DIM);
    const float var = tq * (1.f / DIM) - mu * mu;
    const float rstd = rsqrtf(var + 1e-5f);
    float4 gv = *(const float4*)&g[t * 4];
    __half2* op = (__half2*)&out[(size_t)row * DIM + t * 4];
    op[0] = __floats2half2_rn((v.x - mu) * rstd * gv.x, (v.y - mu) * rstd * gv.y);
    op[1] = __floats2half2_rn((v.z - mu) * rstd * gv.z, (v.w - mu) * rstd * gv.w);
}

// ============ fp16 tensor-core GEMM ============
// C(MxN) = A(MxK) @ Bt(NxK)^T ; A,Bt half row-major. 128x128x32 tiles,
// 8 warps (2x4), warp tile 64x32, mma m16n8k16, cp.async double buffer.
// EPI: 0 store f32, 1 store half*scale, 2 accumulate f32, 3 store half,
//      4 SwiGLU (interleaved pairs -> N/2 half)
#define HS 40                        // smem stride in halves
#define HSTAGE (128*HS*2)            // halves per stage (A+B)
#define HGEMM_SMEM_BYTES (2*HSTAGE*2)

template<int EPI>
__global__ void __launch_bounds__(256) hgemm_kernel(
        int M, int N, int K,
        const __half* __restrict__ A, const __half* __restrict__ Bt,
        void* __restrict__ Cv, float scale) {
    extern __shared__ __half smh[];
    const int tid = threadIdx.x, lane = tid & 31, wid = tid >> 5;
    const int wm = (wid & 1) * 64, wn = (wid >> 1) * 32;
    const int bm = blockIdx.y * 128, bn = blockIdx.x * 128;
    const int gr = lane >> 2, gq = lane & 3;

    float acc[4][4][4] = {};
    const int T = K / 32;

    auto issue = [&](int t) {
        const int s = t & 1;
        const int k0 = t * 32;
        __half* As = smh + s * HSTAGE;
        __half* Bs = As + 128 * HS;
#pragma unroll
        for (int p = 0; p < 2; p++) {
            const int lin = p * 256 + tid;          // 0..511
            const int row = lin >> 2, q8 = (lin & 3) * 8;
            cp16(&As[row * HS + q8], &A [(size_t)(bm + row) * K + k0 + q8]);
            cp16(&Bs[row * HS + q8], &Bt[(size_t)(bn + row) * K + k0 + q8]);
        }
        asm volatile("cp.async.commit_group;");
    };

    issue(0);
    for (int t = 0; t < T; t++) {
        if (t + 1 < T) {
            issue(t + 1);
            asm volatile("cp.async.wait_group 1;");
        } else {
            asm volatile("cp.async.wait_group 0;");
        }
        __syncthreads();

        const int s = t & 1;
        const __half* As = smh + s * HSTAGE;
        const __half* Bs = As + 128 * HS;
#pragma unroll
        for (int ks = 0; ks < 2; ks++) {
            const int k = ks * 16 + 2 * gq;
            unsigned a[4][4], b[4][2];
#pragma unroll
            for (int mi = 0; mi < 4; mi++) {
                const __half* ap = As + (wm + mi * 16 + gr) * HS + k;
                a[mi][0] = *(const unsigned*)ap;
                a[mi][1] = *(const unsigned*)(ap + 8 * HS);
                a[mi][2] = *(const unsigned*)(ap + 8);
                a[mi][3] = *(const unsigned*)(ap + 8 * HS + 8);
            }
#pragma unroll
            for (int ni = 0; ni < 4; ni++) {
                const __half* bp = Bs + (wn + ni * 8 + gr) * HS + k;
                b[ni][0] = *(const unsigned*)bp;
                b[ni][1] = *(const unsigned*)(bp + 8);
            }
#pragma unroll
            for (int mi = 0; mi < 4; mi++)
#pragma unroll
                for (int ni = 0; ni < 4; ni++)
                    MMA_F16(acc[mi][ni][0], acc[mi][ni][1], acc[mi][ni][2], acc[mi][ni][3],
                            a[mi][0], a[mi][1], a[mi][2], a[mi][3], b[ni][0], b[ni][1]);
        }
        __syncthreads();
    }

#pragma unroll
    for (int mi = 0; mi < 4; mi++) {
#pragma unroll
        for (int ni = 0; ni < 4; ni++) {
            const int row0 = bm + wm + mi * 16 + gr;
            const int col  = bn + wn + ni * 8 + 2 * gq;
            if (EPI == 0 || EPI == 2) {
                float* C = (float*)Cv;
                float2* p0 = (float2*)&C[(size_t)row0 * N + col];
                float2* p1 = (float2*)&C[(size_t)(row0 + 8) * N + col];
                float2 v0 = make_float2(acc[mi][ni][0], acc[mi][ni][1]);
                float2 v1 = make_float2(acc[mi][ni][2], acc[mi][ni][3]);
                if (EPI == 2) {
                    float2 c0 = *p0, c1 = *p1;
                    v0.x += c0.x; v0.y += c0.y; v1.x += c1.x; v1.y += c1.y;
                }
                *p0 = v0; *p1 = v1;
            } else if (EPI == 1 || EPI == 3) {
                __half* C = (__half*)Cv;
                const float sc = (EPI == 1) ? scale : 1.f;
                *(__half2*)&C[(size_t)row0 * N + col] =
                    __floats2half2_rn(acc[mi][ni][0] * sc, acc[mi][ni][1] * sc);
                *(__half2*)&C[(size_t)(row0 + 8) * N + col] =
                    __floats2half2_rn(acc[mi][ni][2] * sc, acc[mi][ni][3] * sc);
            } else {  // EPI == 4 : SwiGLU, col even = a, col odd = gate
                __half* C = (__half*)Cv;
                const int Nh = N >> 1;
                const int colh = col >> 1;
                const float g0 = acc[mi][ni][1], g1 = acc[mi][ni][3];
                C[(size_t)row0 * Nh + colh] =
                    __float2half(acc[mi][ni][0] * (g0 / (1.f + __expf(-g0))));
                C[(size_t)(row0 + 8) * Nh + colh] =
                    __float2half(acc[mi][ni][2] * (g1 / (1.f + __expf(-g1))));
            }
        }
    }
}

// ---------------- flash attention, fp16 mma + cp.async double buffer ------
// 64 q-rows/CTA, 4 warps x 16 rows. smem halves: sQ[64*72] sP[64*72]
// stages: K[64*72]+V[64*72]; masks (int) after.
#define AQS 72
#define AOFF_P  4608
#define AOFF_ST 9216
#define ASTAGE  9216
#define AOFF_MK 27648
#define ATT_SMEM_BYTES (AOFF_MK*2 + 2*64*4)

__global__ void __launch_bounds__(128) attn_kernel(const __half* __restrict__ q,
                                                   const __half* __restrict__ kv,
                                                   const int* __restrict__ mask,
                                                   __half* __restrict__ out) {
    extern __shared__ __half smh[];
    __half* sQ = smh;
    __half* sP = smh + AOFF_P;

    const int tid = threadIdx.x, lane = tid & 31, wid = tid >> 5;
    const int gr = lane >> 2, gq = lane & 3;
    const int wm = wid * 16;
    const int qt = blockIdx.x, h = blockIdx.y, b = blockIdx.z;
    const size_t qbase = ((size_t)(b * SEQ + qt * 64)) * DIM + h * DHEAD;

    // load Q tile (64x64 halves)
#pragma unroll
    for (int p = 0; p < 4; p++) {
        const int lin = p * 128 + tid;
        const int r = lin >> 3, c8 = (lin & 7) * 8;
        *(uint4*)&sQ[r * AQS + c8] = *(const uint4*)&q[qbase + (size_t)r * DIM + c8];
    }

    auto issue = [&](int jt, int s) {
        __half* sK = smh + AOFF_ST + s * ASTAGE;
        __half* sV = sK + 64 * AQS;
        int*   sMk = (int*)(smh + AOFF_MK) + s * 64;
        const size_t kbase = (size_t)(b * SEQ + jt * 64) * 128;
#pragma unroll
        for (int p = 0; p < 8; p++) {
            const int lin = p * 128 + tid;
            const int j = lin >> 4, c8 = (lin & 15) * 8;
            const __half* src = &kv[kbase + (size_t)j * 128 + c8];
            if (c8 < 64) cp16(&sK[j * AQS + c8], src);
            else         cp16(&sV[j * AQS + c8 - 64], src);
        }
        if (tid < 16) cp16(&sMk[tid * 4], &mask[b * SEQ + jt * 64 + tid * 4]);
        asm volatile("cp.async.commit_group;");
    };

    issue(0, 0);

    float m0 = -1e30f, m1 = -1e30f, l0 = 0.f, l1 = 0.f;
    float o[8][4];
#pragma unroll
    for (int d = 0; d < 8; d++)
#pragma unroll
        for (int j = 0; j < 4; j++) o[d][j] = 0.f;

    for (int jt = 0; jt < SEQ / 64; jt++) {
        if (jt + 1 < SEQ / 64) {
            issue(jt + 1, (jt + 1) & 1);
            asm volatile("cp.async.wait_group 1;");
        } else {
            asm volatile("cp.async.wait_group 0;");
        }
        __syncthreads();

        const int s = jt & 1;
        const __half* sK = smh + AOFF_ST + s * ASTAGE;
        const __half* sV = sK + 64 * AQS;
        const int*   sMk = (const int*)(smh + AOFF_MK) + s * 64;

        // ---- S = Q K^T : 8 n-tiles, 4 k-steps of 16 ----
        float sc[8][4];
#pragma unroll
        for (int n = 0; n < 8; n++)
#pragma unroll
            for (int j = 0; j < 4; j++) sc[n][j] = 0.f;

#pragma unroll
        for (int ks = 0; ks < 4; ks++) {
            const int k = ks * 16 + 2 * gq;
            const __half* ap = sQ + (wm + gr) * AQS + k;
            unsigned a0 = *(const unsigned*)ap;
            unsigned a1 = *(const unsigned*)(ap + 8 * AQS);
            unsigned a2 = *(const unsigned*)(ap + 8);
            unsigned a3 = *(const unsigned*)(ap + 8 * AQS + 8);
#pragma unroll
            for (int n = 0; n < 8; n++) {
                const __half* bp = sK + (n * 8 + gr) * AQS + k;
                unsigned b0 = *(const unsigned*)bp;
                unsigned b1 = *(const unsigned*)(bp + 8);
                MMA_F16(sc[n][0], sc[n][1], sc[n][2], sc[n][3],
                        a0, a1, a2, a3, b0, b1);
            }
        }

        // ---- mask + online softmax ----
#pragma unroll
        for (int n = 0; n < 8; n++) {
            const int c0 = n * 8 + 2 * gq;
            if (sMk[c0] == 0)     { sc[n][0] = -1e30f; sc[n][2] = -1e30f; }
            if (sMk[c0 + 1] == 0) { sc[n][1] = -1e30f; sc[n][3] = -1e30f; }
        }
        float mx0 = -1e30f, mx1 = -1e30f;
#pragma unroll
        for (int n = 0; n < 8; n++) {
            mx0 = fmaxf(mx0, fmaxf(sc[n][0], sc[n][1]));
            mx1 = fmaxf(mx1, fmaxf(sc[n][2], sc[n][3]));
        }
        mx0 = fmaxf(mx0, __shfl_xor_sync(0xffffffffu, mx0, 1));
        mx0 = fmaxf(mx0, __shfl_xor_sync(0xffffffffu, mx0, 2));
        mx1 = fmaxf(mx1, __shfl_xor_sync(0xffffffffu, mx1, 1));
        mx1 = fmaxf(mx1, __shfl_xor_sync(0xffffffffu, mx1, 2));
        const float mn0 = fmaxf(m0, mx0), mn1 = fmaxf(m1, mx1);
        const float corr0 = __expf(m0 - mn0), corr1 = __expf(m1 - mn1);
        float rs0 = 0.f, rs1 = 0.f;
#pragma unroll
        for (int n = 0; n < 8; n++) {
            float p0 = __expf(sc[n][0] - mn0);
            float p1 = __expf(sc[n][1] - mn0);
            float p2 = __expf(sc[n][2] - mn1);
            float p3 = __expf(sc[n][3] - mn1);
            rs0 += p0 + p1; rs1 += p2 + p3;
            *(__half2*)&sP[(wm + gr) * AQS + n * 8 + 2 * gq] = __floats2half2_rn(p0, p1);
            *(__half2*)&sP[(wm + gr + 8) * AQS + n * 8 + 2 * gq] = __floats2half2_rn(p2, p3);
        }
        rs0 += __shfl_xor_sync(0xffffffffu, rs0, 1);
        rs0 += __shfl_xor_sync(0xffffffffu, rs0, 2);
        rs1 += __shfl_xor_sync(0xffffffffu, rs1, 1);
        rs1 += __shfl_xor_sync(0xffffffffu, rs1, 2);
        l0 = l0 * corr0 + rs0; m0 = mn0;
        l1 = l1 * corr1 + rs1; m1 = mn1;
#pragma unroll
        for (int d = 0; d < 8; d++) {
            o[d][0] *= corr0; o[d][1] *= corr0;
            o[d][2] *= corr1; o[d][3] *= corr1;
        }
        __syncwarp();

        // ---- O += P V : 4 k-steps, V fragments via ldmatrix.x4.trans ----
#pragma unroll
        for (int ks = 0; ks < 4; ks++) {
            const int kc = ks * 16;
            const __half* ap = sP + (wm + gr) * AQS + kc + 2 * gq;
            unsigned a0 = *(const unsigned*)ap;
            unsigned a1 = *(const unsigned*)(ap + 8 * AQS);
            unsigned a2 = *(const unsigned*)(ap + 8);
            unsigned a3 = *(const unsigned*)(ap + 8 * AQS + 8);
            const int vrow = kc + (lane & 7) + ((lane >> 3) & 1) * 8;
            const int vcb  = ((lane >> 4) & 1) * 8;
#pragma unroll
            for (int dp = 0; dp < 4; dp++) {       // pairs of d-tiles
                unsigned b0, b1, b2, b3;
                const unsigned addr = smem_u32(&sV[vrow * AQS + dp * 16 + vcb]);
                asm volatile(
                    "ldmatrix.sync.aligned.m8n8.x4.trans.shared.b16 {%0,%1,%2,%3}, [%4];"
                    : "=r"(b0), "=r"(b1), "=r"(b2), "=r"(b3) : "r"(addr));
                MMA_F16(o[dp*2][0], o[dp*2][1], o[dp*2][2], o[dp*2][3],
                        a0, a1, a2, a3, b0, b1);
                MMA_F16(o[dp*2+1][0], o[dp*2+1][1], o[dp*2+1][2], o[dp*2+1][3],
                        a0, a1, a2, a3, b2, b3);
            }
        }
        __syncthreads();
    }

    const float inv0 = 1.f / l0, inv1 = 1.f / l1;
#pragma unroll
    for (int dt = 0; dt < 8; dt++) {
        const int col = dt * 8 + 2 * gq;
        *(__half2*)&out[qbase + (size_t)(wm + gr) * DIM + col] =
            __floats2half2_rn(o[dt][0] * inv0, o[dt][1] * inv0);
        *(__half2*)&out[qbase + (size_t)(wm + gr + 8) * DIM + col] =
            __floats2half2_rn(o[dt][2] * inv1, o[dt][3] * inv1);
    }
}

// ---------------- launch --------------------------------------------------
extern "C" void kernel_launch(void* const* d_in, const int* in_sizes, int n_in,
                              void* d_out, int out_size) {
    (void)in_sizes; (void)n_in; (void)out_size;
    const float* x        = (const float*)d_in[0];
    const float* context  = (const float*)d_in[1];
    const int*   mask     = (const int*)  d_in[2];
    const float* gamma    = (const float*)d_in[3];
    const float* ctxgamma = (const float*)d_in[4];
    const float* Wq       = (const float*)d_in[5];
    const float* Wkv      = (const float*)d_in[6];
    const float* Wout     = (const float*)d_in[7];
    const float* Wff1     = (const float*)d_in[8];
    const float* Wff2     = (const float*)d_in[9];
    float* out = (float*)d_out;

    __half *xn, *cn, *qb, *kvb, *attnb, *ffb, *w;
    cudaGetSymbolAddress((void**)&xn,    g_xn);
    cudaGetSymbolAddress((void**)&cn,    g_cn);
    cudaGetSymbolAddress((void**)&qb,    g_q);
    cudaGetSymbolAddress((void**)&kvb,   g_kv);
    cudaGetSymbolAddress((void**)&attnb, g_attn);
    cudaGetSymbolAddress((void**)&ffb,   g_ff);
    cudaGetSymbolAddress((void**)&w,     g_w);

    cudaFuncSetAttribute(attn_kernel, cudaFuncAttributeMaxDynamicSharedMemorySize, ATT_SMEM_BYTES);
    cudaFuncSetAttribute(hgemm_kernel<0>, cudaFuncAttributeMaxDynamicSharedMemorySize, HGEMM_SMEM_BYTES);
    cudaFuncSetAttribute(hgemm_kernel<1>, cudaFuncAttributeMaxDynamicSharedMemorySize, HGEMM_SMEM_BYTES);
    cudaFuncSetAttribute(hgemm_kernel<2>, cudaFuncAttributeMaxDynamicSharedMemorySize, HGEMM_SMEM_BYTES);
    cudaFuncSetAttribute(hgemm_kernel<3>, cudaFuncAttributeMaxDynamicSharedMemorySize, HGEMM_SMEM_BYTES);
    cudaFuncSetAttribute(hgemm_kernel<4>, cudaFuncAttributeMaxDynamicSharedMemorySize, HGEMM_SMEM_BYTES);

    // weights -> half, transposed to [N][K]
    dim3 tb(32, 8);
    transpose_half_kernel<<<dim3(1024/32, 1024/32), tb>>>(Wq,   w + WQ_OFF,   1024, 1024);
    transpose_half_kernel<<<dim3(128/32,  1024/32), tb>>>(Wkv,  w + WKV_OFF,  1024, 128);
    transpose_half_kernel<<<dim3(1024/32, 1024/32), tb>>>(Wout, w + WOUT_OFF, 1024, 1024);
    transpose_swiglu_kernel<<<dim3(4096/32, 1024/32), tb>>>(Wff1, w + WFF1_OFF);
    transpose_half_kernel<<<dim3(1024/32, 4096/32), tb>>>(Wff2, w + WFF2_OFF, 4096, 1024);

    // layernorms
    ln_kernel<<<ROWS, 256>>>(x, gamma, xn);
    ln_kernel<<<ROWS, 256>>>(context, ctxgamma, cn);

    // q = half((xn @ Wq) * scale)
    hgemm_kernel<1><<<dim3(DIM/128, ROWS/128), 256, HGEMM_SMEM_BYTES>>>(
        ROWS, DIM, DIM, xn, w + WQ_OFF, qb, 0.125f);

    // kv = half(cn @ Wkv)
    hgemm_kernel<3><<<dim3(1, ROWS/128), 256, HGEMM_SMEM_BYTES>>>(
        ROWS, 2*DHEAD, DIM, cn, w + WKV_OFF, kvb, 1.f);

    // attention
    attn_kernel<<<dim3(SEQ/64, HEADS, BATCH), 128, ATT_SMEM_BYTES>>>(qb, kvb, mask, attnb);

    // out = attn @ Wout  (f32 store)
    hgemm_kernel<0><<<dim3(DIM/128, ROWS/128), 256, HGEMM_SMEM_BYTES>>>(
        ROWS, DIM, DIM, attnb, w + WOUT_OFF, out, 1.f);

    // ff = half(silu(gate)*a), fused in xn @ Wff1T (N=8192 interleaved)
    hgemm_kernel<4><<<dim3((2*FFI)/128, ROWS/128), 256, HGEMM_SMEM_BYTES>>>(
        ROWS, 2*FFI, DIM, xn, w + WFF1_OFF, ffb, 1.f);

    // out += ff @ Wff2
    hgemm_kernel<2><<<dim3(DIM/128, ROWS/128), 256, HGEMM_SMEM_BYTES>>>(
        ROWS, DIM, FFI, ffb, w + WFF2_OFF, out, 1.f);
}

// round 7
// speedup vs baseline: 5.4973x; 1.0684x over previous
#include <cuda_runtime.h>
#include <cuda_fp16.h>
#include <math.h>
#include <stdint.h>

// ---------------- problem constants ----------------
#define BATCH 2
#define SEQ   2048
#define DIM   1024
#define HEADS 16
#define DHEAD 64
#define FFI   4096
#define ROWS  (BATCH*SEQ)

// ---------------- scratch (all fp16 activations) ----------------
__device__ __half g_xn  [(size_t)ROWS*DIM];
__device__ __half g_cn  [(size_t)ROWS*DIM];
__device__ __half g_q   [(size_t)ROWS*DIM];
__device__ __half g_kv  [(size_t)ROWS*2*DHEAD];
__device__ __half g_attn[(size_t)ROWS*DIM];
__device__ __half g_ff  [(size_t)ROWS*FFI];
__device__ __half g_w   [14811136];   // fp16 transposed weights

#define WQ_OFF   0
#define WKV_OFF  1048576
#define WOUT_OFF 1179648
#define WFF1_OFF 2228224
#define WFF2_OFF 10616832

__device__ __forceinline__ unsigned smem_u32(const void* p) {
    unsigned sa;
    asm("{.reg .u64 t; cvta.to.shared.u64 t, %1; cvt.u32.u64 %0, t;}" : "=r"(sa) : "l"(p));
    return sa;
}
__device__ __forceinline__ void cp16(void* smem_ptr, const void* gptr) {
    asm volatile("cp.async.cg.shared.global [%0], [%1], 16;"
                 :: "r"(smem_u32(smem_ptr)), "l"(gptr));
}

#define MMA_F16(C0,C1,C2,C3,A0,A1,A2,A3,B0,B1) \
    asm volatile("mma.sync.aligned.m16n8k16.row.col.f32.f16.f16.f32 " \
        "{%0,%1,%2,%3},{%4,%5,%6,%7},{%8,%9},{%0,%1,%2,%3};" \
        : "+f"(C0), "+f"(C1), "+f"(C2), "+f"(C3) \
        : "r"(A0), "r"(A1), "r"(A2), "r"(A3), "r"(B0), "r"(B1))

#define LDSM_X4(R0,R1,R2,R3,ADDR) \
    asm volatile("ldmatrix.sync.aligned.m8n8.x4.shared.b16 {%0,%1,%2,%3}, [%4];" \
        : "=r"(R0), "=r"(R1), "=r"(R2), "=r"(R3) : "r"(ADDR))

// ---------------- preprocessing: transpose f32 -> half [N][K] -------------
__global__ void __launch_bounds__(256) transpose_half_kernel(const float* __restrict__ in,
                                                             __half* __restrict__ out,
                                                             int K, int N) {
    __shared__ float t[32][33];
    const int tx = threadIdx.x, ty = threadIdx.y;   // 32 x 8
    const int n0 = blockIdx.x * 32, k0 = blockIdx.y * 32;
#pragma unroll
    for (int i = 0; i < 32; i += 8)
        t[ty + i][tx] = in[(size_t)(k0 + ty + i) * N + n0 + tx];
    __syncthreads();
#pragma unroll
    for (int i = 0; i < 32; i += 8)
        out[(size_t)(n0 + ty + i) * K + k0 + tx] = __float2half(t[tx][ty + i]);
}

// Wff1: transpose + interleave (a,gate) rows: out row 2j = col j, 2j+1 = col 4096+j
__global__ void __launch_bounds__(256) transpose_swiglu_kernel(const float* __restrict__ in,
                                                               __half* __restrict__ out) {
    __shared__ float ta[32][33], tg[32][33];
    const int tx = threadIdx.x, ty = threadIdx.y;
    const int j0 = blockIdx.x * 32, k0 = blockIdx.y * 32;
#pragma unroll
    for (int i = 0; i < 32; i += 8) {
        ta[ty + i][tx] = in[(size_t)(k0 + ty + i) * 8192 + j0 + tx];
        tg[ty + i][tx] = in[(size_t)(k0 + ty + i) * 8192 + 4096 + j0 + tx];
    }
    __syncthreads();
#pragma unroll
    for (int i = 0; i < 32; i += 8) {
        const int jj = j0 + ty + i;
        out[(size_t)(2 * jj)     * 1024 + k0 + tx] = __float2half(ta[tx][ty + i]);
        out[(size_t)(2 * jj + 1) * 1024 + k0 + tx] = __float2half(tg[tx][ty + i]);
    }
}

// ---------------- LayerNorm (f32 in -> half out) ----------------
__global__ void __launch_bounds__(256) ln_kernel(const float* __restrict__ in,
                                                 const float* __restrict__ g,
                                                 __half* __restrict__ out) {
    const int row = blockIdx.x;
    const int t = threadIdx.x;
    const float* p = in + (size_t)row * DIM;
    float4 v = *(const float4*)&p[t * 4];
    float s  = v.x + v.y + v.z + v.w;
    float sq = v.x*v.x + v.y*v.y + v.z*v.z + v.w*v.w;
#pragma unroll
    for (int off = 16; off; off >>= 1) {
        s  += __shfl_xor_sync(0xffffffffu, s,  off);
        sq += __shfl_xor_sync(0xffffffffu, sq, off);
    }
    __shared__ float rs[8], rq[8];
    if ((t & 31) == 0) { rs[t >> 5] = s; rq[t >> 5] = sq; }
    __syncthreads();
    float ts = 0.f, tq = 0.f;
#pragma unroll
    for (int i = 0; i < 8; i++) { ts += rs[i]; tq += rq[i]; }
    const float mu  = ts * (1.f / DIM);
    const float var = tq * (1.f / DIM) - mu * mu;
    const float rstd = rsqrtf(var + 1e-5f);
    float4 gv = *(const float4*)&g[t * 4];
    __half2* op = (__half2*)&out[(size_t)row * DIM + t * 4];
    op[0] = __floats2half2_rn((v.x - mu) * rstd * gv.x, (v.y - mu) * rstd * gv.y);
    op[1] = __floats2half2_rn((v.z - mu) * rstd * gv.z, (v.w - mu) * rstd * gv.w);
}

// ============ fp16 tensor-core GEMM (ldmatrix, 3-stage cp.async) ============
// C(MxN) = A(MxK) @ Bt(NxK)^T.  128x128x32 tiles, 8 warps (2x4), warp 64x32.
// EPI: 0 store f32, 1 store half*scale, 2 accumulate f32, 3 store half,
//      4 SwiGLU (interleaved pairs -> N/2 half)
#define HS 40                        // smem stride in halves
#define HSTAGE (128*HS*2)            // halves per stage (A+B)
#define HGEMM_SMEM_BYTES (3*HSTAGE*2)

template<int EPI>
__global__ void __launch_bounds__(256) hgemm_kernel(
        int M, int N, int K,
        const __half* __restrict__ A, const __half* __restrict__ Bt,
        void* __restrict__ Cv, float scale) {
    extern __shared__ __half smh[];
    const int tid = threadIdx.x, lane = tid & 31, wid = tid >> 5;
    const int wm = (wid & 1) * 64, wn = (wid >> 1) * 32;
    const int bm = blockIdx.y * 128, bn = blockIdx.x * 128;
    const int gr = lane >> 2, gq = lane & 3;

    float acc[4][4][4] = {};
    const int T = K / 32;

    auto issue = [&](int t) {
        const int s = t % 3;
        const int k0 = t * 32;
        __half* As = smh + s * HSTAGE;
        __half* Bs = As + 128 * HS;
#pragma unroll
        for (int p = 0; p < 2; p++) {
            const int lin = p * 256 + tid;          // 0..511
            const int row = lin >> 2, q8 = (lin & 3) * 8;
            cp16(&As[row * HS + q8], &A [(size_t)(bm + row) * K + k0 + q8]);
            cp16(&Bs[row * HS + q8], &Bt[(size_t)(bn + row) * K + k0 + q8]);
        }
        asm volatile("cp.async.commit_group;");
    };

    issue(0);
    if (T > 1) issue(1);

    // ldmatrix lane addressing (precomputed row/col components)
    const int a_r = lane & 15, a_c = (lane >> 4) << 3;               // A x4
    const int b_r = (lane & 7) + ((lane >> 4) & 1) * 8;              // B x4
    const int b_c = ((lane >> 3) & 1) << 3;

    for (int t = 0; t < T; t++) {
        if (t + 1 < T) asm volatile("cp.async.wait_group 1;");
        else           asm volatile("cp.async.wait_group 0;");
        __syncthreads();
        if (t + 2 < T) issue(t + 2);

        const int s = t % 3;
        const __half* As = smh + s * HSTAGE;
        const __half* Bs = As + 128 * HS;
#pragma unroll
        for (int ks = 0; ks < 2; ks++) {
            const int k = ks * 16;
            unsigned a[4][4], b[4][2];
#pragma unroll
            for (int mi = 0; mi < 4; mi++) {
                const unsigned ad = smem_u32(&As[(wm + mi * 16 + a_r) * HS + k + a_c]);
                LDSM_X4(a[mi][0], a[mi][1], a[mi][2], a[mi][3], ad);
            }
#pragma unroll
            for (int np = 0; np < 2; np++) {
                const unsigned ad = smem_u32(&Bs[(wn + np * 16 + b_r) * HS + k + b_c]);
                LDSM_X4(b[2*np][0], b[2*np][1], b[2*np+1][0], b[2*np+1][1], ad);
            }
#pragma unroll
            for (int mi = 0; mi < 4; mi++)
#pragma unroll
                for (int ni = 0; ni < 4; ni++)
                    MMA_F16(acc[mi][ni][0], acc[mi][ni][1], acc[mi][ni][2], acc[mi][ni][3],
                            a[mi][0], a[mi][1], a[mi][2], a[mi][3], b[ni][0], b[ni][1]);
        }
        __syncthreads();
    }

#pragma unroll
    for (int mi = 0; mi < 4; mi++) {
#pragma unroll
        for (int ni = 0; ni < 4; ni++) {
            const int row0 = bm + wm + mi * 16 + gr;
            const int col  = bn + wn + ni * 8 + 2 * gq;
            if (EPI == 0 || EPI == 2) {
                float* C = (float*)Cv;
                float2* p0 = (float2*)&C[(size_t)row0 * N + col];
                float2* p1 = (float2*)&C[(size_t)(row0 + 8) * N + col];
                float2 v0 = make_float2(acc[mi][ni][0], acc[mi][ni][1]);
                float2 v1 = make_float2(acc[mi][ni][2], acc[mi][ni][3]);
                if (EPI == 2) {
                    float2 c0 = *p0, c1 = *p1;
                    v0.x += c0.x; v0.y += c0.y; v1.x += c1.x; v1.y += c1.y;
                }
                *p0 = v0; *p1 = v1;
            } else if (EPI == 1 || EPI == 3) {
                __half* C = (__half*)Cv;
                const float sc = (EPI == 1) ? scale : 1.f;
                *(__half2*)&C[(size_t)row0 * N + col] =
                    __floats2half2_rn(acc[mi][ni][0] * sc, acc[mi][ni][1] * sc);
                *(__half2*)&C[(size_t)(row0 + 8) * N + col] =
                    __floats2half2_rn(acc[mi][ni][2] * sc, acc[mi][ni][3] * sc);
            } else {  // EPI == 4 : SwiGLU, col even = a, col odd = gate
                __half* C = (__half*)Cv;
                const int Nh = N >> 1;
                const int colh = col >> 1;
                const float g0 = acc[mi][ni][1], g1 = acc[mi][ni][3];
                C[(size_t)row0 * Nh + colh] =
                    __float2half(acc[mi][ni][0] * (g0 / (1.f + __expf(-g0))));
                C[(size_t)(row0 + 8) * Nh + colh] =
                    __float2half(acc[mi][ni][2] * (g1 / (1.f + __expf(-g1))));
            }
        }
    }
}

// ---------------- flash attention, fp16 mma + ldmatrix --------------------
#define AQS 72
#define AOFF_P  4608
#define AOFF_ST 9216
#define ASTAGE  9216
#define AOFF_MK 27648
#define ATT_SMEM_BYTES (AOFF_MK*2 + 2*64*4)

__global__ void __launch_bounds__(128) attn_kernel(const __half* __restrict__ q,
                                                   const __half* __restrict__ kv,
                                                   const int* __restrict__ mask,
                                                   __half* __restrict__ out) {
    extern __shared__ __half smh[];
    __half* sQ = smh;
    __half* sP = smh + AOFF_P;

    const int tid = threadIdx.x, lane = tid & 31, wid = tid >> 5;
    const int gr = lane >> 2, gq = lane & 3;
    const int wm = wid * 16;
    const int qt = blockIdx.x, h = blockIdx.y, b = blockIdx.z;
    const size_t qbase = ((size_t)(b * SEQ + qt * 64)) * DIM + h * DHEAD;

    const int a_r = lane & 15, a_c = (lane >> 4) << 3;
    const int b_r = (lane & 7) + ((lane >> 4) & 1) * 8;
    const int b_c = ((lane >> 3) & 1) << 3;

    // load Q tile (64x64 halves)
#pragma unroll
    for (int p = 0; p < 4; p++) {
        const int lin = p * 128 + tid;
        const int r = lin >> 3, c8 = (lin & 7) * 8;
        *(uint4*)&sQ[r * AQS + c8] = *(const uint4*)&q[qbase + (size_t)r * DIM + c8];
    }

    auto issue = [&](int jt, int s) {
        __half* sK = smh + AOFF_ST + s * ASTAGE;
        __half* sV = sK + 64 * AQS;
        int*   sMk = (int*)(smh + AOFF_MK) + s * 64;
        const size_t kbase = (size_t)(b * SEQ + jt * 64) * 128;
#pragma unroll
        for (int p = 0; p < 8; p++) {
            const int lin = p * 128 + tid;
            const int j = lin >> 4, c8 = (lin & 15) * 8;
            const __half* src = &kv[kbase + (size_t)j * 128 + c8];
            if (c8 < 64) cp16(&sK[j * AQS + c8], src);
            else         cp16(&sV[j * AQS + c8 - 64], src);
        }
        if (tid < 16) cp16(&sMk[tid * 4], &mask[b * SEQ + jt * 64 + tid * 4]);
        asm volatile("cp.async.commit_group;");
    };

    issue(0, 0);

    float m0 = -1e30f, m1 = -1e30f, l0 = 0.f, l1 = 0.f;
    float o[8][4];
#pragma unroll
    for (int d = 0; d < 8; d++)
#pragma unroll
        for (int j = 0; j < 4; j++) o[d][j] = 0.f;

    for (int jt = 0; jt < SEQ / 64; jt++) {
        if (jt + 1 < SEQ / 64) {
            issue(jt + 1, (jt + 1) & 1);
            asm volatile("cp.async.wait_group 1;");
        } else {
            asm volatile("cp.async.wait_group 0;");
        }
        __syncthreads();

        const int s = jt & 1;
        const __half* sK = smh + AOFF_ST + s * ASTAGE;
        const __half* sV = sK + 64 * AQS;
        const int*   sMk = (const int*)(smh + AOFF_MK) + s * 64;

        // ---- S = Q K^T : 8 n-tiles, 4 k-steps of 16 ----
        float sc[8][4];
#pragma unroll
        for (int n = 0; n < 8; n++)
#pragma unroll
            for (int j = 0; j < 4; j++) sc[n][j] = 0.f;

#pragma unroll
        for (int ks = 0; ks < 4; ks++) {
            const int k = ks * 16;
            unsigned a0, a1, a2, a3;
            LDSM_X4(a0, a1, a2, a3, smem_u32(&sQ[(wm + a_r) * AQS + k + a_c]));
#pragma unroll
            for (int np = 0; np < 4; np++) {
                unsigned b0, b1, b2, b3;
                LDSM_X4(b0, b1, b2, b3, smem_u32(&sK[(np * 16 + b_r) * AQS + k + b_c]));
                MMA_F16(sc[2*np][0], sc[2*np][1], sc[2*np][2], sc[2*np][3],
                        a0, a1, a2, a3, b0, b1);
                MMA_F16(sc[2*np+1][0], sc[2*np+1][1], sc[2*np+1][2], sc[2*np+1][3],
                        a0, a1, a2, a3, b2, b3);
            }
        }

        // ---- mask + online softmax ----
#pragma unroll
        for (int n = 0; n < 8; n++) {
            const int c0 = n * 8 + 2 * gq;
            if (sMk[c0] == 0)     { sc[n][0] = -1e30f; sc[n][2] = -1e30f; }
            if (sMk[c0 + 1] == 0) { sc[n][1] = -1e30f; sc[n][3] = -1e30f; }
        }
        float mx0 = -1e30f, mx1 = -1e30f;
#pragma unroll
        for (int n = 0; n < 8; n++) {
            mx0 = fmaxf(mx0, fmaxf(sc[n][0], sc[n][1]));
            mx1 = fmaxf(mx1, fmaxf(sc[n][2], sc[n][3]));
        }
        mx0 = fmaxf(mx0, __shfl_xor_sync(0xffffffffu, mx0, 1));
        mx0 = fmaxf(mx0, __shfl_xor_sync(0xffffffffu, mx0, 2));
        mx1 = fmaxf(mx1, __shfl_xor_sync(0xffffffffu, mx1, 1));
        mx1 = fmaxf(mx1, __shfl_xor_sync(0xffffffffu, mx1, 2));
        const float mn0 = fmaxf(m0, mx0), mn1 = fmaxf(m1, mx1);
        const float corr0 = __expf(m0 - mn0), corr1 = __expf(m1 - mn1);
        float rs0 = 0.f, rs1 = 0.f;
#pragma unroll
        for (int n = 0; n < 8; n++) {
            float p0 = __expf(sc[n][0] - mn0);
            float p1 = __expf(sc[n][1] - mn0);
            float p2 = __expf(sc[n][2] - mn1);
            float p3 = __expf(sc[n][3] - mn1);
            rs0 += p0 + p1; rs1 += p2 + p3;
            *(__half2*)&sP[(wm + gr) * AQS + n * 8 + 2 * gq] = __floats2half2_rn(p0, p1);
            *(__half2*)&sP[(wm + gr + 8) * AQS + n * 8 + 2 * gq] = __floats2half2_rn(p2, p3);
        }
        rs0 += __shfl_xor_sync(0xffffffffu, rs0, 1);
        rs0 += __shfl_xor_sync(0xffffffffu, rs0, 2);
        rs1 += __shfl_xor_sync(0xffffffffu, rs1, 1);
        rs1 += __shfl_xor_sync(0xffffffffu, rs1, 2);
        l0 = l0 * corr0 + rs0; m0 = mn0;
        l1 = l1 * corr1 + rs1; m1 = mn1;
#pragma unroll
        for (int d = 0; d < 8; d++) {
            o[d][0] *= corr0; o[d][1] *= corr0;
            o[d][2] *= corr1; o[d][3] *= corr1;
        }
        __syncwarp();

        // ---- O += P V : 4 k-steps; P via ldmatrix, V via ldmatrix.trans ----
#pragma unroll
        for (int ks = 0; ks < 4; ks++) {
            const int kc = ks * 16;
            unsigned a0, a1, a2, a3;
            LDSM_X4(a0, a1, a2, a3, smem_u32(&sP[(wm + a_r) * AQS + kc + a_c]));
            const int vrow = kc + (lane & 7) + ((lane >> 3) & 1) * 8;
            const int vcb  = ((lane >> 4) & 1) * 8;
#pragma unroll
            for (int dp = 0; dp < 4; dp++) {       // pairs of d-tiles
                unsigned b0, b1, b2, b3;
                const unsigned addr = smem_u32(&sV[vrow * AQS + dp * 16 + vcb]);
                asm volatile(
                    "ldmatrix.sync.aligned.m8n8.x4.trans.shared.b16 {%0,%1,%2,%3}, [%4];"
                    : "=r"(b0), "=r"(b1), "=r"(b2), "=r"(b3) : "r"(addr));
                MMA_F16(o[dp*2][0], o[dp*2][1], o[dp*2][2], o[dp*2][3],
                        a0, a1, a2, a3, b0, b1);
                MMA_F16(o[dp*2+1][0], o[dp*2+1][1], o[dp*2+1][2], o[dp*2+1][3],
                        a0, a1, a2, a3, b2, b3);
            }
        }
        __syncthreads();
    }

    const float inv0 = 1.f / l0, inv1 = 1.f / l1;
#pragma unroll
    for (int dt = 0; dt < 8; dt++) {
        const int col = dt * 8 + 2 * gq;
        *(__half2*)&out[qbase + (size_t)(wm + gr) * DIM + col] =
            __floats2half2_rn(o[dt][0] * inv0, o[dt][1] * inv0);
        *(__half2*)&out[qbase + (size_t)(wm + gr + 8) * DIM + col] =
            __floats2half2_rn(o[dt][2] * inv1, o[dt][3] * inv1);
    }
}

// ---------------- launch --------------------------------------------------
extern "C" void kernel_launch(void* const* d_in, const int* in_sizes, int n_in,
                              void* d_out, int out_size) {
    (void)in_sizes; (void)n_in; (void)out_size;
    const float* x        = (const float*)d_in[0];
    const float* context  = (const float*)d_in[1];
    const int*   mask     = (const int*)  d_in[2];
    const float* gamma    = (const float*)d_in[3];
    const float* ctxgamma = (const float*)d_in[4];
    const float* Wq       = (const float*)d_in[5];
    const float* Wkv      = (const float*)d_in[6];
    const float* Wout     = (const float*)d_in[7];
    const float* Wff1     = (const float*)d_in[8];
    const float* Wff2     = (const float*)d_in[9];
    float* out = (float*)d_out;

    __half *xn, *cn, *qb, *kvb, *attnb, *ffb, *w;
    cudaGetSymbolAddress((void**)&xn,    g_xn);
    cudaGetSymbolAddress((void**)&cn,    g_cn);
    cudaGetSymbolAddress((void**)&qb,    g_q);
    cudaGetSymbolAddress((void**)&kvb,   g_kv);
    cudaGetSymbolAddress((void**)&attnb, g_attn);
    cudaGetSymbolAddress((void**)&ffb,   g_ff);
    cudaGetSymbolAddress((void**)&w,     g_w);

    cudaFuncSetAttribute(attn_kernel, cudaFuncAttributeMaxDynamicSharedMemorySize, ATT_SMEM_BYTES);
    cudaFuncSetAttribute(hgemm_kernel<0>, cudaFuncAttributeMaxDynamicSharedMemorySize, HGEMM_SMEM_BYTES);
    cudaFuncSetAttribute(hgemm_kernel<1>, cudaFuncAttributeMaxDynamicSharedMemorySize, HGEMM_SMEM_BYTES);
    cudaFuncSetAttribute(hgemm_kernel<2>, cudaFuncAttributeMaxDynamicSharedMemorySize, HGEMM_SMEM_BYTES);
    cudaFuncSetAttribute(hgemm_kernel<3>, cudaFuncAttributeMaxDynamicSharedMemorySize, HGEMM_SMEM_BYTES);
    cudaFuncSetAttribute(hgemm_kernel<4>, cudaFuncAttributeMaxDynamicSharedMemorySize, HGEMM_SMEM_BYTES);

    // weights -> half, transposed to [N][K]
    dim3 tb(32, 8);
    transpose_half_kernel<<<dim3(1024/32, 1024/32), tb>>>(Wq,   w + WQ_OFF,   1024, 1024);
    transpose_half_kernel<<<dim3(128/32,  1024/32), tb>>>(Wkv,  w + WKV_OFF,  1024, 128);
    transpose_half_kernel<<<dim3(1024/32, 1024/32), tb>>>(Wout, w + WOUT_OFF, 1024, 1024);
    transpose_swiglu_kernel<<<dim3(4096/32, 1024/32), tb>>>(Wff1, w + WFF1_OFF);
    transpose_half_kernel<<<dim3(1024/32, 4096/32), tb>>>(Wff2, w + WFF2_OFF, 4096, 1024);

    // layernorms
    ln_kernel<<<ROWS, 256>>>(x, gamma, xn);
    ln_kernel<<<ROWS, 256>>>(context, ctxgamma, cn);

    // q = half((xn @ Wq) * scale)
    hgemm_kernel<1><<<dim3(DIM/128, ROWS/128), 256, HGEMM_SMEM_BYTES>>>(
        ROWS, DIM, DIM, xn, w + WQ_OFF, qb, 0.125f);

    // kv = half(cn @ Wkv)
    hgemm_kernel<3><<<dim3(1, ROWS/128), 256, HGEMM_SMEM_BYTES>>>(
        ROWS, 2*DHEAD, DIM, cn, w + WKV_OFF, kvb, 1.f);

    // attention
    attn_kernel<<<dim3(SEQ/64, HEADS, BATCH), 128, ATT_SMEM_BYTES>>>(qb, kvb, mask, attnb);

    // out = attn @ Wout  (f32 store)
    hgemm_kernel<0><<<dim3(DIM/128, ROWS/128), 256, HGEMM_SMEM_BYTES>>>(
        ROWS, DIM, DIM, attnb, w + WOUT_OFF, out, 1.f);

    // ff = half(silu(gate)*a), fused in xn @ Wff1T (N=8192 interleaved)
    hgemm_kernel<4><<<dim3((2*FFI)/128, ROWS/128), 256, HGEMM_SMEM_BYTES>>>(
        ROWS, 2*FFI, DIM, xn, w + WFF1_OFF, ffb, 1.f);

    // out += ff @ Wff2
    hgemm_kernel<2><<<dim3(DIM/128, ROWS/128), 256, HGEMM_SMEM_BYTES>>>(
        ROWS, DIM, FFI, ffb, w + WFF2_OFF, out, 1.f);
}

// round 8
// speedup vs baseline: 5.5908x; 1.0170x over previous
#include <cuda_runtime.h>
#include <cuda_fp16.h>
#include <math.h>
#include <stdint.h>

// ---------------- problem constants ----------------
#define BATCH 2
#define SEQ   2048
#define DIM   1024
#define HEADS 16
#define DHEAD 64
#define FFI   4096
#define ROWS  (BATCH*SEQ)

// ---------------- scratch (all fp16 activations) ----------------
__device__ __half g_xn  [(size_t)ROWS*DIM];
__device__ __half g_cn  [(size_t)ROWS*DIM];
__device__ __half g_q   [(size_t)ROWS*DIM];
__device__ __half g_kv  [(size_t)ROWS*2*DHEAD];
__device__ __half g_attn[(size_t)ROWS*DIM];
__device__ __half g_ff  [(size_t)ROWS*FFI];
__device__ __half g_w   [14811136];   // fp16 transposed weights

#define WQ_OFF   0
#define WKV_OFF  1048576
#define WOUT_OFF 1179648
#define WFF1_OFF 2228224
#define WFF2_OFF 10616832

__device__ __forceinline__ unsigned smem_u32(const void* p) {
    unsigned sa;
    asm("{.reg .u64 t; cvta.to.shared.u64 t, %1; cvt.u32.u64 %0, t;}" : "=r"(sa) : "l"(p));
    return sa;
}
__device__ __forceinline__ void cp16(void* smem_ptr, const void* gptr) {
    asm volatile("cp.async.cg.shared.global [%0], [%1], 16;"
                 :: "r"(smem_u32(smem_ptr)), "l"(gptr));
}

#define MMA_F16(C0,C1,C2,C3,A0,A1,A2,A3,B0,B1) \
    asm volatile("mma.sync.aligned.m16n8k16.row.col.f32.f16.f16.f32 " \
        "{%0,%1,%2,%3},{%4,%5,%6,%7},{%8,%9},{%0,%1,%2,%3};" \
        : "+f"(C0), "+f"(C1), "+f"(C2), "+f"(C3) \
        : "r"(A0), "r"(A1), "r"(A2), "r"(A3), "r"(B0), "r"(B1))

#define LDSM_X4(R0,R1,R2,R3,ADDR) \
    asm volatile("ldmatrix.sync.aligned.m8n8.x4.shared.b16 {%0,%1,%2,%3}, [%4];" \
        : "=r"(R0), "=r"(R1), "=r"(R2), "=r"(R3) : "r"(ADDR))

// ---------------- preprocessing: transpose f32 -> half [N][K] -------------
__global__ void __launch_bounds__(256) transpose_half_kernel(const float* __restrict__ in,
                                                             __half* __restrict__ out,
                                                             int K, int N) {
    __shared__ float t[32][33];
    const int tx = threadIdx.x, ty = threadIdx.y;   // 32 x 8
    const int n0 = blockIdx.x * 32, k0 = blockIdx.y * 32;
#pragma unroll
    for (int i = 0; i < 32; i += 8)
        t[ty + i][tx] = in[(size_t)(k0 + ty + i) * N + n0 + tx];
    __syncthreads();
#pragma unroll
    for (int i = 0; i < 32; i += 8)
        out[(size_t)(n0 + ty + i) * K + k0 + tx] = __float2half(t[tx][ty + i]);
}

// Wff1: transpose + interleave (a,gate) rows: out row 2j = col j, 2j+1 = col 4096+j
__global__ void __launch_bounds__(256) transpose_swiglu_kernel(const float* __restrict__ in,
                                                               __half* __restrict__ out) {
    __shared__ float ta[32][33], tg[32][33];
    const int tx = threadIdx.x, ty = threadIdx.y;
    const int j0 = blockIdx.x * 32, k0 = blockIdx.y * 32;
#pragma unroll
    for (int i = 0; i < 32; i += 8) {
        ta[ty + i][tx] = in[(size_t)(k0 + ty + i) * 8192 + j0 + tx];
        tg[ty + i][tx] = in[(size_t)(k0 + ty + i) * 8192 + 4096 + j0 + tx];
    }
    __syncthreads();
#pragma unroll
    for (int i = 0; i < 32; i += 8) {
        const int jj = j0 + ty + i;
        out[(size_t)(2 * jj)     * 1024 + k0 + tx] = __float2half(ta[tx][ty + i]);
        out[(size_t)(2 * jj + 1) * 1024 + k0 + tx] = __float2half(tg[tx][ty + i]);
    }
}

// ---------------- LayerNorm (f32 in -> half out) ----------------
__global__ void __launch_bounds__(256) ln_kernel(const float* __restrict__ in,
                                                 const float* __restrict__ g,
                                                 __half* __restrict__ out) {
    const int row = blockIdx.x;
    const int t = threadIdx.x;
    const float* p = in + (size_t)row * DIM;
    float4 v = *(const float4*)&p[t * 4];
    float s  = v.x + v.y + v.z + v.w;
    float sq = v.x*v.x + v.y*v.y + v.z*v.z + v.w*v.w;
#pragma unroll
    for (int off = 16; off; off >>= 1) {
        s  += __shfl_xor_sync(0xffffffffu, s,  off);
        sq += __shfl_xor_sync(0xffffffffu, sq, off);
    }
    __shared__ float rs[8], rq[8];
    if ((t & 31) == 0) { rs[t >> 5] = s; rq[t >> 5] = sq; }
    __syncthreads();
    float ts = 0.f, tq = 0.f;
#pragma unroll
    for (int i = 0; i < 8; i++) { ts += rs[i]; tq += rq[i]; }
    const float mu  = ts * (1.f / DIM);
    const float var = tq * (1.f / DIM) - mu * mu;
    const float rstd = rsqrtf(var + 1e-5f);
    float4 gv = *(const float4*)&g[t * 4];
    __half2* op = (__half2*)&out[(size_t)row * DIM + t * 4];
    op[0] = __floats2half2_rn((v.x - mu) * rstd * gv.x, (v.y - mu) * rstd * gv.y);
    op[1] = __floats2half2_rn((v.z - mu) * rstd * gv.z, (v.w - mu) * rstd * gv.w);
}

// ============ fp16 GEMM, 256x128 tiles, K-chunk 64, 2-stage ============
// C(MxN) = A(MxK) @ Bt(NxK)^T.  8 warps (4m x 2n), warp tile 64x64.
// EPI: 0 store f32, 1 store half*scale, 2 accumulate f32, 3 store half,
//      4 SwiGLU (interleaved pairs -> N/2 half)
#define H2S 72
#define H2_STG (256*H2S + 128*H2S)     // halves per stage
#define HG2_SMEM_BYTES (2*H2_STG*2)    // 110592 B

template<int EPI>
__global__ void __launch_bounds__(256) hgemm2_kernel(
        int M, int N, int K,
        const __half* __restrict__ A, const __half* __restrict__ Bt,
        void* __restrict__ Cv, float scale) {
    extern __shared__ __half smh[];
    const int tid = threadIdx.x, lane = tid & 31, wid = tid >> 5;
    const int wm = (wid >> 1) * 64, wn = (wid & 1) * 64;
    const int bm = blockIdx.y * 256, bn = blockIdx.x * 128;
    const int gr = lane >> 2, gq = lane & 3;

    float acc[4][8][4] = {};
    const int T = K / 64;

    auto issue = [&](int t) {
        const int s = t & 1;
        const int k0 = t * 64;
        __half* As = smh + s * H2_STG;
        __half* Bs = As + 256 * H2S;
#pragma unroll
        for (int p = 0; p < 8; p++) {
            const int lin = p * 256 + tid;          // 0..2047
            const int row = lin >> 3, q8 = (lin & 7) * 8;
            cp16(&As[row * H2S + q8], &A[(size_t)(bm + row) * K + k0 + q8]);
        }
#pragma unroll
        for (int p = 0; p < 4; p++) {
            const int lin = p * 256 + tid;          // 0..1023
            const int row = lin >> 3, q8 = (lin & 7) * 8;
            cp16(&Bs[row * H2S + q8], &Bt[(size_t)(bn + row) * K + k0 + q8]);
        }
        asm volatile("cp.async.commit_group;");
    };

    issue(0);
    if (T > 1) issue(1);

    const int a_r = lane & 15, a_c = (lane >> 4) << 3;
    const int b_r = (lane & 7) + ((lane >> 4) & 1) * 8;
    const int b_c = ((lane >> 3) & 1) << 3;

    for (int t = 0; t < T; t++) {
        if (t + 1 < T) asm volatile("cp.async.wait_group 1;");
        else           asm volatile("cp.async.wait_group 0;");
        __syncthreads();

        const int s = t & 1;
        const __half* As = smh + s * H2_STG;
        const __half* Bs = As + 256 * H2S;
#pragma unroll
        for (int ks = 0; ks < 4; ks++) {
            const int k = ks * 16;
            unsigned a[4][4], b[8][2];
#pragma unroll
            for (int mi = 0; mi < 4; mi++) {
                const unsigned ad = smem_u32(&As[(wm + mi * 16 + a_r) * H2S + k + a_c]);
                LDSM_X4(a[mi][0], a[mi][1], a[mi][2], a[mi][3], ad);
            }
#pragma unroll
            for (int np = 0; np < 4; np++) {
                const unsigned ad = smem_u32(&Bs[(wn + np * 16 + b_r) * H2S + k + b_c]);
                LDSM_X4(b[2*np][0], b[2*np][1], b[2*np+1][0], b[2*np+1][1], ad);
            }
#pragma unroll
            for (int mi = 0; mi < 4; mi++)
#pragma unroll
                for (int ni = 0; ni < 8; ni++)
                    MMA_F16(acc[mi][ni][0], acc[mi][ni][1], acc[mi][ni][2], acc[mi][ni][3],
                            a[mi][0], a[mi][1], a[mi][2], a[mi][3], b[ni][0], b[ni][1]);
        }
        __syncthreads();
        if (t + 2 < T) issue(t + 2);
    }

#pragma unroll
    for (int mi = 0; mi < 4; mi++) {
#pragma unroll
        for (int ni = 0; ni < 8; ni++) {
            const int row0 = bm + wm + mi * 16 + gr;
            const int col  = bn + wn + ni * 8 + 2 * gq;
            if (EPI == 0 || EPI == 2) {
                float* C = (float*)Cv;
                float2* p0 = (float2*)&C[(size_t)row0 * N + col];
                float2* p1 = (float2*)&C[(size_t)(row0 + 8) * N + col];
                float2 v0 = make_float2(acc[mi][ni][0], acc[mi][ni][1]);
                float2 v1 = make_float2(acc[mi][ni][2], acc[mi][ni][3]);
                if (EPI == 2) {
                    float2 c0 = *p0, c1 = *p1;
                    v0.x += c0.x; v0.y += c0.y; v1.x += c1.x; v1.y += c1.y;
                }
                *p0 = v0; *p1 = v1;
            } else if (EPI == 1 || EPI == 3) {
                __half* C = (__half*)Cv;
                const float sc = (EPI == 1) ? scale : 1.f;
                *(__half2*)&C[(size_t)row0 * N + col] =
                    __floats2half2_rn(acc[mi][ni][0] * sc, acc[mi][ni][1] * sc);
                *(__half2*)&C[(size_t)(row0 + 8) * N + col] =
                    __floats2half2_rn(acc[mi][ni][2] * sc, acc[mi][ni][3] * sc);
            } else {  // EPI == 4 : SwiGLU
                __half* C = (__half*)Cv;
                const int Nh = N >> 1;
                const int colh = col >> 1;
                const float g0 = acc[mi][ni][1], g1 = acc[mi][ni][3];
                C[(size_t)row0 * Nh + colh] =
                    __float2half(acc[mi][ni][0] * (g0 / (1.f + __expf(-g0))));
                C[(size_t)(row0 + 8) * Nh + colh] =
                    __float2half(acc[mi][ni][2] * (g1 / (1.f + __expf(-g1))));
            }
        }
    }
}

// ---------------- kv GEMM: 128x128 tiles (N=128 only) ----------------
#define HS 40
#define HSTAGE (128*HS*2)
#define HGEMM_SMEM_BYTES (3*HSTAGE*2)

__global__ void __launch_bounds__(256) kv_gemm_kernel(
        int M, int N, int K,
        const __half* __restrict__ A, const __half* __restrict__ Bt,
        __half* __restrict__ C) {
    extern __shared__ __half smh[];
    const int tid = threadIdx.x, lane = tid & 31, wid = tid >> 5;
    const int wm = (wid & 1) * 64, wn = (wid >> 1) * 32;
    const int bm = blockIdx.y * 128, bn = blockIdx.x * 128;
    const int gr = lane >> 2, gq = lane & 3;

    float acc[4][4][4] = {};
    const int T = K / 32;

    auto issue = [&](int t) {
        const int s = t % 3;
        const int k0 = t * 32;
        __half* As = smh + s * HSTAGE;
        __half* Bs = As + 128 * HS;
#pragma unroll
        for (int p = 0; p < 2; p++) {
            const int lin = p * 256 + tid;
            const int row = lin >> 2, q8 = (lin & 3) * 8;
            cp16(&As[row * HS + q8], &A [(size_t)(bm + row) * K + k0 + q8]);
            cp16(&Bs[row * HS + q8], &Bt[(size_t)(bn + row) * K + k0 + q8]);
        }
        asm volatile("cp.async.commit_group;");
    };

    issue(0);
    if (T > 1) issue(1);

    const int a_r = lane & 15, a_c = (lane >> 4) << 3;
    const int b_r = (lane & 7) + ((lane >> 4) & 1) * 8;
    const int b_c = ((lane >> 3) & 1) << 3;

    for (int t = 0; t < T; t++) {
        if (t + 1 < T) asm volatile("cp.async.wait_group 1;");
        else           asm volatile("cp.async.wait_group 0;");
        __syncthreads();
        if (t + 2 < T) issue(t + 2);

        const int s = t % 3;
        const __half* As = smh + s * HSTAGE;
        const __half* Bs = As + 128 * HS;
#pragma unroll
        for (int ks = 0; ks < 2; ks++) {
            const int k = ks * 16;
            unsigned a[4][4], b[4][2];
#pragma unroll
            for (int mi = 0; mi < 4; mi++) {
                const unsigned ad = smem_u32(&As[(wm + mi * 16 + a_r) * HS + k + a_c]);
                LDSM_X4(a[mi][0], a[mi][1], a[mi][2], a[mi][3], ad);
            }
#pragma unroll
            for (int np = 0; np < 2; np++) {
                const unsigned ad = smem_u32(&Bs[(wn + np * 16 + b_r) * HS + k + b_c]);
                LDSM_X4(b[2*np][0], b[2*np][1], b[2*np+1][0], b[2*np+1][1], ad);
            }
#pragma unroll
            for (int mi = 0; mi < 4; mi++)
#pragma unroll
                for (int ni = 0; ni < 4; ni++)
                    MMA_F16(acc[mi][ni][0], acc[mi][ni][1], acc[mi][ni][2], acc[mi][ni][3],
                            a[mi][0], a[mi][1], a[mi][2], a[mi][3], b[ni][0], b[ni][1]);
        }
        __syncthreads();
    }

#pragma unroll
    for (int mi = 0; mi < 4; mi++) {
#pragma unroll
        for (int ni = 0; ni < 4; ni++) {
            const int row0 = bm + wm + mi * 16 + gr;
            const int col  = bn + wn + ni * 8 + 2 * gq;
            *(__half2*)&C[(size_t)row0 * N + col] =
                __floats2half2_rn(acc[mi][ni][0], acc[mi][ni][1]);
            *(__half2*)&C[(size_t)(row0 + 8) * N + col] =
                __floats2half2_rn(acc[mi][ni][2], acc[mi][ni][3]);
        }
    }
}

// ---------------- flash attention, fp16 mma + ldmatrix --------------------
#define AQS 72
#define AOFF_P  4608
#define AOFF_ST 9216
#define ASTAGE  9216
#define AOFF_MK 27648
#define ATT_SMEM_BYTES (AOFF_MK*2 + 2*64*4)

__global__ void __launch_bounds__(128) attn_kernel(const __half* __restrict__ q,
                                                   const __half* __restrict__ kv,
                                                   const int* __restrict__ mask,
                                                   __half* __restrict__ out) {
    extern __shared__ __half smh[];
    __half* sQ = smh;
    __half* sP = smh + AOFF_P;

    const int tid = threadIdx.x, lane = tid & 31, wid = tid >> 5;
    const int gr = lane >> 2, gq = lane & 3;
    const int wm = wid * 16;
    const int qt = blockIdx.x, h = blockIdx.y, b = blockIdx.z;
    const size_t qbase = ((size_t)(b * SEQ + qt * 64)) * DIM + h * DHEAD;

    const int a_r = lane & 15, a_c = (lane >> 4) << 3;
    const int b_r = (lane & 7) + ((lane >> 4) & 1) * 8;
    const int b_c = ((lane >> 3) & 1) << 3;

#pragma unroll
    for (int p = 0; p < 4; p++) {
        const int lin = p * 128 + tid;
        const int r = lin >> 3, c8 = (lin & 7) * 8;
        *(uint4*)&sQ[r * AQS + c8] = *(const uint4*)&q[qbase + (size_t)r * DIM + c8];
    }

    auto issue = [&](int jt, int s) {
        __half* sK = smh + AOFF_ST + s * ASTAGE;
        __half* sV = sK + 64 * AQS;
        int*   sMk = (int*)(smh + AOFF_MK) + s * 64;
        const size_t kbase = (size_t)(b * SEQ + jt * 64) * 128;
#pragma unroll
        for (int p = 0; p < 8; p++) {
            const int lin = p * 128 + tid;
            const int j = lin >> 4, c8 = (lin & 15) * 8;
            const __half* src = &kv[kbase + (size_t)j * 128 + c8];
            if (c8 < 64) cp16(&sK[j * AQS + c8], src);
            else         cp16(&sV[j * AQS + c8 - 64], src);
        }
        if (tid < 16) cp16(&sMk[tid * 4], &mask[b * SEQ + jt * 64 + tid * 4]);
        asm volatile("cp.async.commit_group;");
    };

    issue(0, 0);

    float m0 = -1e30f, m1 = -1e30f, l0 = 0.f, l1 = 0.f;
    float o[8][4];
#pragma unroll
    for (int d = 0; d < 8; d++)
#pragma unroll
        for (int j = 0; j < 4; j++) o[d][j] = 0.f;

    for (int jt = 0; jt < SEQ / 64; jt++) {
        if (jt + 1 < SEQ / 64) {
            issue(jt + 1, (jt + 1) & 1);
            asm volatile("cp.async.wait_group 1;");
        } else {
            asm volatile("cp.async.wait_group 0;");
        }
        __syncthreads();

        const int s = jt & 1;
        const __half* sK = smh + AOFF_ST + s * ASTAGE;
        const __half* sV = sK + 64 * AQS;
        const int*   sMk = (const int*)(smh + AOFF_MK) + s * 64;

        float sc[8][4];
#pragma unroll
        for (int n = 0; n < 8; n++)
#pragma unroll
            for (int j = 0; j < 4; j++) sc[n][j] = 0.f;

#pragma unroll
        for (int ks = 0; ks < 4; ks++) {
            const int k = ks * 16;
            unsigned a0, a1, a2, a3;
            LDSM_X4(a0, a1, a2, a3, smem_u32(&sQ[(wm + a_r) * AQS + k + a_c]));
#pragma unroll
            for (int np = 0; np < 4; np++) {
                unsigned b0, b1, b2, b3;
                LDSM_X4(b0, b1, b2, b3, smem_u32(&sK[(np * 16 + b_r) * AQS + k + b_c]));
                MMA_F16(sc[2*np][0], sc[2*np][1], sc[2*np][2], sc[2*np][3],
                        a0, a1, a2, a3, b0, b1);
                MMA_F16(sc[2*np+1][0], sc[2*np+1][1], sc[2*np+1][2], sc[2*np+1][3],
                        a0, a1, a2, a3, b2, b3);
            }
        }

#pragma unroll
        for (int n = 0; n < 8; n++) {
            const int c0 = n * 8 + 2 * gq;
            if (sMk[c0] == 0)     { sc[n][0] = -1e30f; sc[n][2] = -1e30f; }
            if (sMk[c0 + 1] == 0) { sc[n][1] = -1e30f; sc[n][3] = -1e30f; }
        }
        float mx0 = -1e30f, mx1 = -1e30f;
#pragma unroll
        for (int n = 0; n < 8; n++) {
            mx0 = fmaxf(mx0, fmaxf(sc[n][0], sc[n][1]));
            mx1 = fmaxf(mx1, fmaxf(sc[n][2], sc[n][3]));
        }
        mx0 = fmaxf(mx0, __shfl_xor_sync(0xffffffffu, mx0, 1));
        mx0 = fmaxf(mx0, __shfl_xor_sync(0xffffffffu, mx0, 2));
        mx1 = fmaxf(mx1, __shfl_xor_sync(0xffffffffu, mx1, 1));
        mx1 = fmaxf(mx1, __shfl_xor_sync(0xffffffffu, mx1, 2));
        const float mn0 = fmaxf(m0, mx0), mn1 = fmaxf(m1, mx1);
        const float corr0 = __expf(m0 - mn0), corr1 = __expf(m1 - mn1);
        float rs0 = 0.f, rs1 = 0.f;
#pragma unroll
        for (int n = 0; n < 8; n++) {
            float p0 = __expf(sc[n][0] - mn0);
            float p1 = __expf(sc[n][1] - mn0);
            float p2 = __expf(sc[n][2] - mn1);
            float p3 = __expf(sc[n][3] - mn1);
            rs0 += p0 + p1; rs1 += p2 + p3;
            *(__half2*)&sP[(wm + gr) * AQS + n * 8 + 2 * gq] = __floats2half2_rn(p0, p1);
            *(__half2*)&sP[(wm + gr + 8) * AQS + n * 8 + 2 * gq] = __floats2half2_rn(p2, p3);
        }
        rs0 += __shfl_xor_sync(0xffffffffu, rs0, 1);
        rs0 += __shfl_xor_sync(0xffffffffu, rs0, 2);
        rs1 += __shfl_xor_sync(0xffffffffu, rs1, 1);
        rs1 += __shfl_xor_sync(0xffffffffu, rs1, 2);
        l0 = l0 * corr0 + rs0; m0 = mn0;
        l1 = l1 * corr1 + rs1; m1 = mn1;
#pragma unroll
        for (int d = 0; d < 8; d++) {
            o[d][0] *= corr0; o[d][1] *= corr0;
            o[d][2] *= corr1; o[d][3] *= corr1;
        }
        __syncwarp();

#pragma unroll
        for (int ks = 0; ks < 4; ks++) {
            const int kc = ks * 16;
            unsigned a0, a1, a2, a3;
            LDSM_X4(a0, a1, a2, a3, smem_u32(&sP[(wm + a_r) * AQS + kc + a_c]));
            const int vrow = kc + (lane & 7) + ((lane >> 3) & 1) * 8;
            const int vcb  = ((lane >> 4) & 1) * 8;
#pragma unroll
            for (int dp = 0; dp < 4; dp++) {
                unsigned b0, b1, b2, b3;
                const unsigned addr = smem_u32(&sV[vrow * AQS + dp * 16 + vcb]);
                asm volatile(
                    "ldmatrix.sync.aligned.m8n8.x4.trans.shared.b16 {%0,%1,%2,%3}, [%4];"
                    : "=r"(b0), "=r"(b1), "=r"(b2), "=r"(b3) : "r"(addr));
                MMA_F16(o[dp*2][0], o[dp*2][1], o[dp*2][2], o[dp*2][3],
                        a0, a1, a2, a3, b0, b1);
                MMA_F16(o[dp*2+1][0], o[dp*2+1][1], o[dp*2+1][2], o[dp*2+1][3],
                        a0, a1, a2, a3, b2, b3);
            }
        }
        __syncthreads();
    }

    const float inv0 = 1.f / l0, inv1 = 1.f / l1;
#pragma unroll
    for (int dt = 0; dt < 8; dt++) {
        const int col = dt * 8 + 2 * gq;
        *(__half2*)&out[qbase + (size_t)(wm + gr) * DIM + col] =
            __floats2half2_rn(o[dt][0] * inv0, o[dt][1] * inv0);
        *(__half2*)&out[qbase + (size_t)(wm + gr + 8) * DIM + col] =
            __floats2half2_rn(o[dt][2] * inv1, o[dt][3] * inv1);
    }
}

// ---------------- launch --------------------------------------------------
extern "C" void kernel_launch(void* const* d_in, const int* in_sizes, int n_in,
                              void* d_out, int out_size) {
    (void)in_sizes; (void)n_in; (void)out_size;
    const float* x        = (const float*)d_in[0];
    const float* context  = (const float*)d_in[1];
    const int*   mask     = (const int*)  d_in[2];
    const float* gamma    = (const float*)d_in[3];
    const float* ctxgamma = (const float*)d_in[4];
    const float* Wq       = (const float*)d_in[5];
    const float* Wkv      = (const float*)d_in[6];
    const float* Wout     = (const float*)d_in[7];
    const float* Wff1     = (const float*)d_in[8];
    const float* Wff2     = (const float*)d_in[9];
    float* out = (float*)d_out;

    __half *xn, *cn, *qb, *kvb, *attnb, *ffb, *w;
    cudaGetSymbolAddress((void**)&xn,    g_xn);
    cudaGetSymbolAddress((void**)&cn,    g_cn);
    cudaGetSymbolAddress((void**)&qb,    g_q);
    cudaGetSymbolAddress((void**)&kvb,   g_kv);
    cudaGetSymbolAddress((void**)&attnb, g_attn);
    cudaGetSymbolAddress((void**)&ffb,   g_ff);
    cudaGetSymbolAddress((void**)&w,     g_w);

    cudaFuncSetAttribute(attn_kernel, cudaFuncAttributeMaxDynamicSharedMemorySize, ATT_SMEM_BYTES);
    cudaFuncSetAttribute(kv_gemm_kernel, cudaFuncAttributeMaxDynamicSharedMemorySize, HGEMM_SMEM_BYTES);
    cudaFuncSetAttribute(hgemm2_kernel<0>, cudaFuncAttributeMaxDynamicSharedMemorySize, HG2_SMEM_BYTES);
    cudaFuncSetAttribute(hgemm2_kernel<1>, cudaFuncAttributeMaxDynamicSharedMemorySize, HG2_SMEM_BYTES);
    cudaFuncSetAttribute(hgemm2_kernel<2>, cudaFuncAttributeMaxDynamicSharedMemorySize, HG2_SMEM_BYTES);
    cudaFuncSetAttribute(hgemm2_kernel<4>, cudaFuncAttributeMaxDynamicSharedMemorySize, HG2_SMEM_BYTES);

    // weights -> half, transposed to [N][K]
    dim3 tb(32, 8);
    transpose_half_kernel<<<dim3(1024/32, 1024/32), tb>>>(Wq,   w + WQ_OFF,   1024, 1024);
    transpose_half_kernel<<<dim3(128/32,  1024/32), tb>>>(Wkv,  w + WKV_OFF,  1024, 128);
    transpose_half_kernel<<<dim3(1024/32, 1024/32), tb>>>(Wout, w + WOUT_OFF, 1024, 1024);
    transpose_swiglu_kernel<<<dim3(4096/32, 1024/32), tb>>>(Wff1, w + WFF1_OFF);
    transpose_half_kernel<<<dim3(1024/32, 4096/32), tb>>>(Wff2, w + WFF2_OFF, 4096, 1024);

    // layernorms
    ln_kernel<<<ROWS, 256>>>(x, gamma, xn);
    ln_kernel<<<ROWS, 256>>>(context, ctxgamma, cn);

    // q = half((xn @ Wq) * scale)     grid 8x16 = 128 CTAs (1 wave)
    hgemm2_kernel<1><<<dim3(DIM/128, ROWS/256), 256, HG2_SMEM_BYTES>>>(
        ROWS, DIM, DIM, xn, w + WQ_OFF, qb, 0.125f);

    // kv = half(cn @ Wkv)
    kv_gemm_kernel<<<dim3(1, ROWS/128), 256, HGEMM_SMEM_BYTES>>>(
        ROWS, 2*DHEAD, DIM, cn, w + WKV_OFF, kvb);

    // attention
    attn_kernel<<<dim3(SEQ/64, HEADS, BATCH), 128, ATT_SMEM_BYTES>>>(qb, kvb, mask, attnb);

    // out = attn @ Wout               grid 8x16 = 128 CTAs
    hgemm2_kernel<0><<<dim3(DIM/128, ROWS/256), 256, HG2_SMEM_BYTES>>>(
        ROWS, DIM, DIM, attnb, w + WOUT_OFF, out, 1.f);

    // ff = half(silu(gate)*a), fused in xn @ Wff1T (N=8192 interleaved)
    hgemm2_kernel<4><<<dim3((2*FFI)/128, ROWS/256), 256, HG2_SMEM_BYTES>>>(
        ROWS, 2*FFI, DIM, xn, w + WFF1_OFF, ffb, 1.f);

    // out += ff @ Wff2                grid 8x16 = 128 CTAs
    hgemm2_kernel<2><<<dim3(DIM/128, ROWS/256), 256, HG2_SMEM_BYTES>>>(
        ROWS, DIM, FFI, ffb, w + WFF2_OFF, out, 1.f);
}

// round 9
// speedup vs baseline: 5.6104x; 1.0035x over previous
#include <cuda_runtime.h>
#include <cuda_fp16.h>
#include <math.h>
#include <stdint.h>

// ---------------- problem constants ----------------
#define BATCH 2
#define SEQ   2048
#define DIM   1024
#define HEADS 16
#define DHEAD 64
#define FFI   4096
#define ROWS  (BATCH*SEQ)
#define CATW  5120               // 1024 attn + 4096 ff, combined row width

// ---------------- scratch ----------------
__device__ __half g_xn [(size_t)ROWS*DIM];
__device__ __half g_cn [(size_t)ROWS*DIM];
__device__ __half g_q  [(size_t)ROWS*DIM];
__device__ __half g_kv [(size_t)ROWS*2*DHEAD];
__device__ __half g_cat[(size_t)ROWS*CATW];      // [attn(1024) | ff(4096)] per row
__device__ __half g_w  [14811136];               // combined fp16 weights

#define WQFF_OFF 0                               // [9216][1024]  (scaled Wq + interleaved Wff1)
#define WKV_OFF  9437184                         // [128][1024]
#define WOUT2_OFF 9568256                        // [1024][5120]  (WoutT | Wff2T)

__device__ __forceinline__ unsigned smem_u32(const void* p) {
    unsigned sa;
    asm("{.reg .u64 t; cvta.to.shared.u64 t, %1; cvt.u32.u64 %0, t;}" : "=r"(sa) : "l"(p));
    return sa;
}
__device__ __forceinline__ void cp16(void* smem_ptr, const void* gptr) {
    asm volatile("cp.async.cg.shared.global [%0], [%1], 16;"
                 :: "r"(smem_u32(smem_ptr)), "l"(gptr));
}

#define MMA_F16(C0,C1,C2,C3,A0,A1,A2,A3,B0,B1) \
    asm volatile("mma.sync.aligned.m16n8k16.row.col.f32.f16.f16.f32 " \
        "{%0,%1,%2,%3},{%4,%5,%6,%7},{%8,%9},{%0,%1,%2,%3};" \
        : "+f"(C0), "+f"(C1), "+f"(C2), "+f"(C3) \
        : "r"(A0), "r"(A1), "r"(A2), "r"(A3), "r"(B0), "r"(B1))

#define LDSM_X4(R0,R1,R2,R3,ADDR) \
    asm volatile("ldmatrix.sync.aligned.m8n8.x4.shared.b16 {%0,%1,%2,%3}, [%4];" \
        : "=r"(R0), "=r"(R1), "=r"(R2), "=r"(R3) : "r"(ADDR))

// ---------------- preprocessing: transpose f32 -> half [N][K] -------------
// out[n][k] (row stride ostride) = scale * in[k][n]
__global__ void __launch_bounds__(256) transpose_half_kernel(const float* __restrict__ in,
                                                             __half* __restrict__ out,
                                                             int K, int N, int ostride,
                                                             float scale) {
    __shared__ float t[32][33];
    const int tx = threadIdx.x, ty = threadIdx.y;   // 32 x 8
    const int n0 = blockIdx.x * 32, k0 = blockIdx.y * 32;
#pragma unroll
    for (int i = 0; i < 32; i += 8)
        t[ty + i][tx] = in[(size_t)(k0 + ty + i) * N + n0 + tx];
    __syncthreads();
#pragma unroll
    for (int i = 0; i < 32; i += 8)
        out[(size_t)(n0 + ty + i) * ostride + k0 + tx] = __float2half(scale * t[tx][ty + i]);
}

// Wff1: transpose + interleave into rows 2j / 2j+1 (a / gate), K=1024
__global__ void __launch_bounds__(256) transpose_swiglu_kernel(const float* __restrict__ in,
                                                               __half* __restrict__ out) {
    __shared__ float ta[32][33], tg[32][33];
    const int tx = threadIdx.x, ty = threadIdx.y;
    const int j0 = blockIdx.x * 32, k0 = blockIdx.y * 32;
#pragma unroll
    for (int i = 0; i < 32; i += 8) {
        ta[ty + i][tx] = in[(size_t)(k0 + ty + i) * 8192 + j0 + tx];
        tg[ty + i][tx] = in[(size_t)(k0 + ty + i) * 8192 + 4096 + j0 + tx];
    }
    __syncthreads();
#pragma unroll
    for (int i = 0; i < 32; i += 8) {
        const int jj = j0 + ty + i;
        out[(size_t)(2 * jj)     * 1024 + k0 + tx] = __float2half(ta[tx][ty + i]);
        out[(size_t)(2 * jj + 1) * 1024 + k0 + tx] = __float2half(tg[tx][ty + i]);
    }
}

// ---------------- LayerNorm (f32 in -> half out) ----------------
__global__ void __launch_bounds__(256) ln_kernel(const float* __restrict__ in,
                                                 const float* __restrict__ g,
                                                 __half* __restrict__ out) {
    const int row = blockIdx.x;
    const int t = threadIdx.x;
    const float* p = in + (size_t)row * DIM;
    float4 v = *(const float4*)&p[t * 4];
    float s  = v.x + v.y + v.z + v.w;
    float sq = v.x*v.x + v.y*v.y + v.z*v.z + v.w*v.w;
#pragma unroll
    for (int off = 16; off; off >>= 1) {
        s  += __shfl_xor_sync(0xffffffffu, s,  off);
        sq += __shfl_xor_sync(0xffffffffu, sq, off);
    }
    __shared__ float rs[8], rq[8];
    if ((t & 31) == 0) { rs[t >> 5] = s; rq[t >> 5] = sq; }
    __syncthreads();
    float ts = 0.f, tq = 0.f;
#pragma unroll
    for (int i = 0; i < 8; i++) { ts += rs[i]; tq += rq[i]; }
    const float mu  = ts * (1.f / DIM);
    const float var = tq * (1.f / DIM) - mu * mu;
    const float rstd = rsqrtf(var + 1e-5f);
    float4 gv = *(const float4*)&g[t * 4];
    __half2* op = (__half2*)&out[(size_t)row * DIM + t * 4];
    op[0] = __floats2half2_rn((v.x - mu) * rstd * gv.x, (v.y - mu) * rstd * gv.y);
    op[1] = __floats2half2_rn((v.z - mu) * rstd * gv.z, (v.w - mu) * rstd * gv.w);
}

// ============ fp16 GEMM, 256x128 tiles, K-chunk 64, 2-stage ============
// C = A(M x K, row stride lda) @ Bt(N x K)^T.  8 warps (4m x 2n), warp 64x64.
// EPI 0: store f32 to Cv (stride N)
// EPI 5: QFF combined — cols <1024: half store to Cv (q, stride 1024);
//        cols >=1024: SwiGLU pairs -> Cv2 (ff, stride CATW)
#define H2S 72
#define H2_STG (256*H2S + 128*H2S)
#define HG2_SMEM_BYTES (2*H2_STG*2)

template<int EPI>
__global__ void __launch_bounds__(256) hgemm2_kernel(
        int M, int N, int K, int lda,
        const __half* __restrict__ A, const __half* __restrict__ Bt,
        void* __restrict__ Cv, __half* __restrict__ Cv2) {
    extern __shared__ __half smh[];
    const int tid = threadIdx.x, lane = tid & 31, wid = tid >> 5;
    const int wm = (wid >> 1) * 64, wn = (wid & 1) * 64;
    const int bm = blockIdx.y * 256, bn = blockIdx.x * 128;
    const int gr = lane >> 2, gq = lane & 3;

    float acc[4][8][4] = {};
    const int T = K / 64;

    auto issue = [&](int t) {
        const int s = t & 1;
        const int k0 = t * 64;
        __half* As = smh + s * H2_STG;
        __half* Bs = As + 256 * H2S;
#pragma unroll
        for (int p = 0; p < 8; p++) {
            const int lin = p * 256 + tid;
            const int row = lin >> 3, q8 = (lin & 7) * 8;
            cp16(&As[row * H2S + q8], &A[(size_t)(bm + row) * lda + k0 + q8]);
        }
#pragma unroll
        for (int p = 0; p < 4; p++) {
            const int lin = p * 256 + tid;
            const int row = lin >> 3, q8 = (lin & 7) * 8;
            cp16(&Bs[row * H2S + q8], &Bt[(size_t)(bn + row) * K + k0 + q8]);
        }
        asm volatile("cp.async.commit_group;");
    };

    issue(0);
    if (T > 1) issue(1);

    const int a_r = lane & 15, a_c = (lane >> 4) << 3;
    const int b_r = (lane & 7) + ((lane >> 4) & 1) * 8;
    const int b_c = ((lane >> 3) & 1) << 3;

    for (int t = 0; t < T; t++) {
        if (t + 1 < T) asm volatile("cp.async.wait_group 1;");
        else           asm volatile("cp.async.wait_group 0;");
        __syncthreads();

        const int s = t & 1;
        const __half* As = smh + s * H2_STG;
        const __half* Bs = As + 256 * H2S;
#pragma unroll
        for (int ks = 0; ks < 4; ks++) {
            const int k = ks * 16;
            unsigned a[4][4], b[8][2];
#pragma unroll
            for (int mi = 0; mi < 4; mi++) {
                const unsigned ad = smem_u32(&As[(wm + mi * 16 + a_r) * H2S + k + a_c]);
                LDSM_X4(a[mi][0], a[mi][1], a[mi][2], a[mi][3], ad);
            }
#pragma unroll
            for (int np = 0; np < 4; np++) {
                const unsigned ad = smem_u32(&Bs[(wn + np * 16 + b_r) * H2S + k + b_c]);
                LDSM_X4(b[2*np][0], b[2*np][1], b[2*np+1][0], b[2*np+1][1], ad);
            }
#pragma unroll
            for (int mi = 0; mi < 4; mi++)
#pragma unroll
                for (int ni = 0; ni < 8; ni++)
                    MMA_F16(acc[mi][ni][0], acc[mi][ni][1], acc[mi][ni][2], acc[mi][ni][3],
                            a[mi][0], a[mi][1], a[mi][2], a[mi][3], b[ni][0], b[ni][1]);
        }
        __syncthreads();
        if (t + 2 < T) issue(t + 2);
    }

#pragma unroll
    for (int mi = 0; mi < 4; mi++) {
#pragma unroll
        for (int ni = 0; ni < 8; ni++) {
            const int row0 = bm + wm + mi * 16 + gr;
            const int col  = bn + wn + ni * 8 + 2 * gq;
            if (EPI == 0) {
                float* C = (float*)Cv;
                *(float2*)&C[(size_t)row0 * N + col] =
                    make_float2(acc[mi][ni][0], acc[mi][ni][1]);
                *(float2*)&C[(size_t)(row0 + 8) * N + col] =
                    make_float2(acc[mi][ni][2], acc[mi][ni][3]);
            } else {  // EPI == 5 : QFF
                if (bn < 1024) {     // q region (scale folded into weights)
                    __half* C = (__half*)Cv;
                    *(__half2*)&C[(size_t)row0 * 1024 + col] =
                        __floats2half2_rn(acc[mi][ni][0], acc[mi][ni][1]);
                    *(__half2*)&C[(size_t)(row0 + 8) * 1024 + col] =
                        __floats2half2_rn(acc[mi][ni][2], acc[mi][ni][3]);
                } else {             // ff region: (a, gate) pairs
                    const int colh = (col - 1024) >> 1;
                    const float g0 = acc[mi][ni][1], g1 = acc[mi][ni][3];
                    Cv2[(size_t)row0 * CATW + colh] =
                        __float2half(acc[mi][ni][0] * (g0 / (1.f + __expf(-g0))));
                    Cv2[(size_t)(row0 + 8) * CATW + colh] =
                        __float2half(acc[mi][ni][2] * (g1 / (1.f + __expf(-g1))));
                }
            }
        }
    }
}

// ---------------- kv GEMM: 128x128 tiles (N=128 only) ----------------
#define HS 40
#define HSTAGE (128*HS*2)
#define HGEMM_SMEM_BYTES (3*HSTAGE*2)

__global__ void __launch_bounds__(256) kv_gemm_kernel(
        int M, int N, int K,
        const __half* __restrict__ A, const __half* __restrict__ Bt,
        __half* __restrict__ C) {
    extern __shared__ __half smh[];
    const int tid = threadIdx.x, lane = tid & 31, wid = tid >> 5;
    const int wm = (wid & 1) * 64, wn = (wid >> 1) * 32;
    const int bm = blockIdx.y * 128, bn = blockIdx.x * 128;
    const int gr = lane >> 2, gq = lane & 3;

    float acc[4][4][4] = {};
    const int T = K / 32;

    auto issue = [&](int t) {
        const int s = t % 3;
        const int k0 = t * 32;
        __half* As = smh + s * HSTAGE;
        __half* Bs = As + 128 * HS;
#pragma unroll
        for (int p = 0; p < 2; p++) {
            const int lin = p * 256 + tid;
            const int row = lin >> 2, q8 = (lin & 3) * 8;
            cp16(&As[row * HS + q8], &A [(size_t)(bm + row) * K + k0 + q8]);
            cp16(&Bs[row * HS + q8], &Bt[(size_t)(bn + row) * K + k0 + q8]);
        }
        asm volatile("cp.async.commit_group;");
    };

    issue(0);
    if (T > 1) issue(1);

    const int a_r = lane & 15, a_c = (lane >> 4) << 3;
    const int b_r = (lane & 7) + ((lane >> 4) & 1) * 8;
    const int b_c = ((lane >> 3) & 1) << 3;

    for (int t = 0; t < T; t++) {
        if (t + 1 < T) asm volatile("cp.async.wait_group 1;");
        else           asm volatile("cp.async.wait_group 0;");
        __syncthreads();
        if (t + 2 < T) issue(t + 2);

        const int s = t % 3;
        const __half* As = smh + s * HSTAGE;
        const __half* Bs = As + 128 * HS;
#pragma unroll
        for (int ks = 0; ks < 2; ks++) {
            const int k = ks * 16;
            unsigned a[4][4], b[4][2];
#pragma unroll
            for (int mi = 0; mi < 4; mi++) {
                const unsigned ad = smem_u32(&As[(wm + mi * 16 + a_r) * HS + k + a_c]);
                LDSM_X4(a[mi][0], a[mi][1], a[mi][2], a[mi][3], ad);
            }
#pragma unroll
            for (int np = 0; np < 2; np++) {
                const unsigned ad = smem_u32(&Bs[(wn + np * 16 + b_r) * HS + k + b_c]);
                LDSM_X4(b[2*np][0], b[2*np][1], b[2*np+1][0], b[2*np+1][1], ad);
            }
#pragma unroll
            for (int mi = 0; mi < 4; mi++)
#pragma unroll
                for (int ni = 0; ni < 4; ni++)
                    MMA_F16(acc[mi][ni][0], acc[mi][ni][1], acc[mi][ni][2], acc[mi][ni][3],
                            a[mi][0], a[mi][1], a[mi][2], a[mi][3], b[ni][0], b[ni][1]);
        }
        __syncthreads();
    }

#pragma unroll
    for (int mi = 0; mi < 4; mi++) {
#pragma unroll
        for (int ni = 0; ni < 4; ni++) {
            const int row0 = bm + wm + mi * 16 + gr;
            const int col  = bn + wn + ni * 8 + 2 * gq;
            *(__half2*)&C[(size_t)row0 * N + col] =
                __floats2half2_rn(acc[mi][ni][0], acc[mi][ni][1]);
            *(__half2*)&C[(size_t)(row0 + 8) * N + col] =
                __floats2half2_rn(acc[mi][ni][2], acc[mi][ni][3]);
        }
    }
}

// ---------------- flash attention, fp16 mma + ldmatrix --------------------
// output goes into g_cat (row stride CATW), columns h*64..h*64+63
#define AQS 72
#define AOFF_P  4608
#define AOFF_ST 9216
#define ASTAGE  9216
#define AOFF_MK 27648
#define ATT_SMEM_BYTES (AOFF_MK*2 + 2*64*4)

__global__ void __launch_bounds__(128) attn_kernel(const __half* __restrict__ q,
                                                   const __half* __restrict__ kv,
                                                   const int* __restrict__ mask,
                                                   __half* __restrict__ out) {
    extern __shared__ __half smh[];
    __half* sQ = smh;
    __half* sP = smh + AOFF_P;

    const int tid = threadIdx.x, lane = tid & 31, wid = tid >> 5;
    const int gr = lane >> 2, gq = lane & 3;
    const int wm = wid * 16;
    const int qt = blockIdx.x, h = blockIdx.y, b = blockIdx.z;
    const size_t qbase = ((size_t)(b * SEQ + qt * 64)) * DIM + h * DHEAD;
    const size_t obase = ((size_t)(b * SEQ + qt * 64)) * CATW + h * DHEAD;

    const int a_r = lane & 15, a_c = (lane >> 4) << 3;
    const int b_r = (lane & 7) + ((lane >> 4) & 1) * 8;
    const int b_c = ((lane >> 3) & 1) << 3;

#pragma unroll
    for (int p = 0; p < 4; p++) {
        const int lin = p * 128 + tid;
        const int r = lin >> 3, c8 = (lin & 7) * 8;
        *(uint4*)&sQ[r * AQS + c8] = *(const uint4*)&q[qbase + (size_t)r * DIM + c8];
    }

    auto issue = [&](int jt, int s) {
        __half* sK = smh + AOFF_ST + s * ASTAGE;
        __half* sV = sK + 64 * AQS;
        int*   sMk = (int*)(smh + AOFF_MK) + s * 64;
        const size_t kbase = (size_t)(b * SEQ + jt * 64) * 128;
#pragma unroll
        for (int p = 0; p < 8; p++) {
            const int lin = p * 128 + tid;
            const int j = lin >> 4, c8 = (lin & 15) * 8;
            const __half* src = &kv[kbase + (size_t)j * 128 + c8];
            if (c8 < 64) cp16(&sK[j * AQS + c8], src);
            else         cp16(&sV[j * AQS + c8 - 64], src);
        }
        if (tid < 16) cp16(&sMk[tid * 4], &mask[b * SEQ + jt * 64 + tid * 4]);
        asm volatile("cp.async.commit_group;");
    };

    issue(0, 0);

    float m0 = -1e30f, m1 = -1e30f, l0 = 0.f, l1 = 0.f;
    float o[8][4];
#pragma unroll
    for (int d = 0; d < 8; d++)
#pragma unroll
        for (int j = 0; j < 4; j++) o[d][j] = 0.f;

    for (int jt = 0; jt < SEQ / 64; jt++) {
        if (jt + 1 < SEQ / 64) {
            issue(jt + 1, (jt + 1) & 1);
            asm volatile("cp.async.wait_group 1;");
        } else {
            asm volatile("cp.async.wait_group 0;");
        }
        __syncthreads();

        const int s = jt & 1;
        const __half* sK = smh + AOFF_ST + s * ASTAGE;
        const __half* sV = sK + 64 * AQS;
        const int*   sMk = (const int*)(smh + AOFF_MK) + s * 64;

        float sc[8][4];
#pragma unroll
        for (int n = 0; n < 8; n++)
#pragma unroll
            for (int j = 0; j < 4; j++) sc[n][j] = 0.f;

#pragma unroll
        for (int ks = 0; ks < 4; ks++) {
            const int k = ks * 16;
            unsigned a0, a1, a2, a3;
            LDSM_X4(a0, a1, a2, a3, smem_u32(&sQ[(wm + a_r) * AQS + k + a_c]));
#pragma unroll
            for (int np = 0; np < 4; np++) {
                unsigned b0, b1, b2, b3;
                LDSM_X4(b0, b1, b2, b3, smem_u32(&sK[(np * 16 + b_r) * AQS + k + b_c]));
                MMA_F16(sc[2*np][0], sc[2*np][1], sc[2*np][2], sc[2*np][3],
                        a0, a1, a2, a3, b0, b1);
                MMA_F16(sc[2*np+1][0], sc[2*np+1][1], sc[2*np+1][2], sc[2*np+1][3],
                        a0, a1, a2, a3, b2, b3);
            }
        }

#pragma unroll
        for (int n = 0; n < 8; n++) {
            const int c0 = n * 8 + 2 * gq;
            if (sMk[c0] == 0)     { sc[n][0] = -1e30f; sc[n][2] = -1e30f; }
            if (sMk[c0 + 1] == 0) { sc[n][1] = -1e30f; sc[n][3] = -1e30f; }
        }
        float mx0 = -1e30f, mx1 = -1e30f;
#pragma unroll
        for (int n = 0; n < 8; n++) {
            mx0 = fmaxf(mx0, fmaxf(sc[n][0], sc[n][1]));
            mx1 = fmaxf(mx1, fmaxf(sc[n][2], sc[n][3]));
        }
        mx0 = fmaxf(mx0, __shfl_xor_sync(0xffffffffu, mx0, 1));
        mx0 = fmaxf(mx0, __shfl_xor_sync(0xffffffffu, mx0, 2));
        mx1 = fmaxf(mx1, __shfl_xor_sync(0xffffffffu, mx1, 1));
        mx1 = fmaxf(mx1, __shfl_xor_sync(0xffffffffu, mx1, 2));
        const float mn0 = fmaxf(m0, mx0), mn1 = fmaxf(m1, mx1);
        const float corr0 = __expf(m0 - mn0), corr1 = __expf(m1 - mn1);
        float rs0 = 0.f, rs1 = 0.f;
#pragma unroll
        for (int n = 0; n < 8; n++) {
            float p0 = __expf(sc[n][0] - mn0);
            float p1 = __expf(sc[n][1] - mn0);
            float p2 = __expf(sc[n][2] - mn1);
            float p3 = __expf(sc[n][3] - mn1);
            rs0 += p0 + p1; rs1 += p2 + p3;
            *(__half2*)&sP[(wm + gr) * AQS + n * 8 + 2 * gq] = __floats2half2_rn(p0, p1);
            *(__half2*)&sP[(wm + gr + 8) * AQS + n * 8 + 2 * gq] = __floats2half2_rn(p2, p3);
        }
        rs0 += __shfl_xor_sync(0xffffffffu, rs0, 1);
        rs0 += __shfl_xor_sync(0xffffffffu, rs0, 2);
        rs1 += __shfl_xor_sync(0xffffffffu, rs1, 1);
        rs1 += __shfl_xor_sync(0xffffffffu, rs1, 2);
        l0 = l0 * corr0 + rs0; m0 = mn0;
        l1 = l1 * corr1 + rs1; m1 = mn1;
#pragma unroll
        for (int d = 0; d < 8; d++) {
            o[d][0] *= corr0; o[d][1] *= corr0;
            o[d][2] *= corr1; o[d][3] *= corr1;
        }
        __syncwarp();

#pragma unroll
        for (int ks = 0; ks < 4; ks++) {
            const int kc = ks * 16;
            unsigned a0, a1, a2, a3;
            LDSM_X4(a0, a1, a2, a3, smem_u32(&sP[(wm + a_r) * AQS + kc + a_c]));
            const int vrow = kc + (lane & 7) + ((lane >> 3) & 1) * 8;
            const int vcb  = ((lane >> 4) & 1) * 8;
#pragma unroll
            for (int dp = 0; dp < 4; dp++) {
                unsigned b0, b1, b2, b3;
                const unsigned addr = smem_u32(&sV[vrow * AQS + dp * 16 + vcb]);
                asm volatile(
                    "ldmatrix.sync.aligned.m8n8.x4.trans.shared.b16 {%0,%1,%2,%3}, [%4];"
                    : "=r"(b0), "=r"(b1), "=r"(b2), "=r"(b3) : "r"(addr));
                MMA_F16(o[dp*2][0], o[dp*2][1], o[dp*2][2], o[dp*2][3],
                        a0, a1, a2, a3, b0, b1);
                MMA_F16(o[dp*2+1][0], o[dp*2+1][1], o[dp*2+1][2], o[dp*2+1][3],
                        a0, a1, a2, a3, b2, b3);
            }
        }
        __syncthreads();
    }

    const float inv0 = 1.f / l0, inv1 = 1.f / l1;
#pragma unroll
    for (int dt = 0; dt < 8; dt++) {
        const int col = dt * 8 + 2 * gq;
        *(__half2*)&out[obase + (size_t)(wm + gr) * CATW + col] =
            __floats2half2_rn(o[dt][0] * inv0, o[dt][1] * inv0);
        *(__half2*)&out[obase + (size_t)(wm + gr + 8) * CATW + col] =
            __floats2half2_rn(o[dt][2] * inv1, o[dt][3] * inv1);
    }
}

// ---------------- launch --------------------------------------------------
extern "C" void kernel_launch(void* const* d_in, const int* in_sizes, int n_in,
                              void* d_out, int out_size) {
    (void)in_sizes; (void)n_in; (void)out_size;
    const float* x        = (const float*)d_in[0];
    const float* context  = (const float*)d_in[1];
    const int*   mask     = (const int*)  d_in[2];
    const float* gamma    = (const float*)d_in[3];
    const float* ctxgamma = (const float*)d_in[4];
    const float* Wq       = (const float*)d_in[5];
    const float* Wkv      = (const float*)d_in[6];
    const float* Wout     = (const float*)d_in[7];
    const float* Wff1     = (const float*)d_in[8];
    const float* Wff2     = (const float*)d_in[9];
    float* out = (float*)d_out;

    __half *xn, *cn, *qb, *kvb, *cat, *w;
    cudaGetSymbolAddress((void**)&xn,  g_xn);
    cudaGetSymbolAddress((void**)&cn,  g_cn);
    cudaGetSymbolAddress((void**)&qb,  g_q);
    cudaGetSymbolAddress((void**)&kvb, g_kv);
    cudaGetSymbolAddress((void**)&cat, g_cat);
    cudaGetSymbolAddress((void**)&w,   g_w);

    cudaFuncSetAttribute(attn_kernel, cudaFuncAttributeMaxDynamicSharedMemorySize, ATT_SMEM_BYTES);
    cudaFuncSetAttribute(kv_gemm_kernel, cudaFuncAttributeMaxDynamicSharedMemorySize, HGEMM_SMEM_BYTES);
    cudaFuncSetAttribute(hgemm2_kernel<0>, cudaFuncAttributeMaxDynamicSharedMemorySize, HG2_SMEM_BYTES);
    cudaFuncSetAttribute(hgemm2_kernel<5>, cudaFuncAttributeMaxDynamicSharedMemorySize, HG2_SMEM_BYTES);

    dim3 tb(32, 8);
    // #0: Wq -> w_qff rows 0..1023, scale 0.125 folded
    transpose_half_kernel<<<dim3(1024/32, 1024/32), tb>>>(Wq, w + WQFF_OFF, 1024, 1024, 1024, 0.125f);
    // #1: Wff1 -> w_qff rows 1024..9215 (interleaved a/gate)
    transpose_swiglu_kernel<<<dim3(4096/32, 1024/32), tb>>>(Wff1, w + WQFF_OFF + 1024*1024);
    // #2,#3: layernorms
    ln_kernel<<<ROWS, 256>>>(x, gamma, xn);
    ln_kernel<<<ROWS, 256>>>(context, ctxgamma, cn);
    // #4: Wkv
    transpose_half_kernel<<<dim3(128/32, 1024/32), tb>>>(Wkv, w + WKV_OFF, 1024, 128, 1024, 1.f);

    // #5 (ncu profiles this): QFF GEMM — q + SwiGLU(ff) in one pass, N=9216
    hgemm2_kernel<5><<<dim3(9216/128, ROWS/256), 256, HG2_SMEM_BYTES>>>(
        ROWS, 9216, DIM, DIM, xn, w + WQFF_OFF, qb, cat + 1024);

    // #6: Wout -> w_out2 cols 0..1023 ; #7: Wff2 -> cols 1024..5119
    transpose_half_kernel<<<dim3(1024/32, 1024/32), tb>>>(Wout, w + WOUT2_OFF, 1024, 1024, CATW, 1.f);
    transpose_half_kernel<<<dim3(1024/32, 4096/32), tb>>>(Wff2, w + WOUT2_OFF + 1024, 4096, 1024, CATW, 1.f);

    // #8: kv = half(cn @ Wkv)
    kv_gemm_kernel<<<dim3(1, ROWS/128), 256, HGEMM_SMEM_BYTES>>>(
        ROWS, 2*DHEAD, DIM, cn, w + WKV_OFF, kvb);

    // #9: attention -> g_cat cols 0..1023
    attn_kernel<<<dim3(SEQ/64, HEADS, BATCH), 128, ATT_SMEM_BYTES>>>(qb, kvb, mask, cat);

    // #10: out = [attn|ff] @ [WoutT|Wff2T]^T, K=5120, single f32 store
    hgemm2_kernel<0><<<dim3(DIM/128, ROWS/256), 256, HG2_SMEM_BYTES>>>(
        ROWS, DIM, CATW, CATW, cat, w + WOUT2_OFF, out, nullptr);
}

// round 10
// speedup vs baseline: 5.8568x; 1.0439x over previous
#include <cuda_runtime.h>
#include <cuda_fp16.h>
#include <math.h>
#include <stdint.h>

// ---------------- problem constants ----------------
#define BATCH 2
#define SEQ   2048
#define DIM   1024
#define HEADS 16
#define DHEAD 64
#define FFI   4096
#define ROWS  (BATCH*SEQ)
#define CATW  5120               // 1024 attn + 4096 ff, combined row width

// ---------------- scratch ----------------
__device__ __half g_xn [(size_t)ROWS*DIM];
__device__ __half g_cn [(size_t)ROWS*DIM];
__device__ __half g_q  [(size_t)ROWS*DIM];
__device__ __half g_kv [(size_t)ROWS*2*DHEAD];
__device__ __half g_cat[(size_t)ROWS*CATW];      // [attn(1024) | ff(4096)] per row
__device__ __half g_w  [14811136];               // combined fp16 weights

#define WQFF_OFF 0                               // [9216][1024]  (scaled Wq + interleaved Wff1)
#define WKV_OFF  9437184                         // [128][1024]
#define WOUT2_OFF 9568256                        // [1024][5120]  (WoutT | Wff2T)

__device__ __forceinline__ unsigned smem_u32(const void* p) {
    unsigned sa;
    asm("{.reg .u64 t; cvta.to.shared.u64 t, %1; cvt.u32.u64 %0, t;}" : "=r"(sa) : "l"(p));
    return sa;
}
__device__ __forceinline__ void cp16(void* smem_ptr, const void* gptr) {
    asm volatile("cp.async.cg.shared.global [%0], [%1], 16;"
                 :: "r"(smem_u32(smem_ptr)), "l"(gptr));
}

#define MMA_F16(C0,C1,C2,C3,A0,A1,A2,A3,B0,B1) \
    asm volatile("mma.sync.aligned.m16n8k16.row.col.f32.f16.f16.f32 " \
        "{%0,%1,%2,%3},{%4,%5,%6,%7},{%8,%9},{%0,%1,%2,%3};" \
        : "+f"(C0), "+f"(C1), "+f"(C2), "+f"(C3) \
        : "r"(A0), "r"(A1), "r"(A2), "r"(A3), "r"(B0), "r"(B1))

#define LDSM_X4(R0,R1,R2,R3,ADDR) \
    asm volatile("ldmatrix.sync.aligned.m8n8.x4.shared.b16 {%0,%1,%2,%3}, [%4];" \
        : "=r"(R0), "=r"(R1), "=r"(R2), "=r"(R3) : "r"(ADDR))

// ---------------- preprocessing: transpose f32 -> half [N][K] -------------
__global__ void __launch_bounds__(256) transpose_half_kernel(const float* __restrict__ in,
                                                             __half* __restrict__ out,
                                                             int K, int N, int ostride,
                                                             float scale) {
    __shared__ float t[32][33];
    const int tx = threadIdx.x, ty = threadIdx.y;   // 32 x 8
    const int n0 = blockIdx.x * 32, k0 = blockIdx.y * 32;
#pragma unroll
    for (int i = 0; i < 32; i += 8)
        t[ty + i][tx] = in[(size_t)(k0 + ty + i) * N + n0 + tx];
    __syncthreads();
#pragma unroll
    for (int i = 0; i < 32; i += 8)
        out[(size_t)(n0 + ty + i) * ostride + k0 + tx] = __float2half(scale * t[tx][ty + i]);
}

// Wff1: transpose + interleave into rows 2j / 2j+1 (a / gate), K=1024
__global__ void __launch_bounds__(256) transpose_swiglu_kernel(const float* __restrict__ in,
                                                               __half* __restrict__ out) {
    __shared__ float ta[32][33], tg[32][33];
    const int tx = threadIdx.x, ty = threadIdx.y;
    const int j0 = blockIdx.x * 32, k0 = blockIdx.y * 32;
#pragma unroll
    for (int i = 0; i < 32; i += 8) {
        ta[ty + i][tx] = in[(size_t)(k0 + ty + i) * 8192 + j0 + tx];
        tg[ty + i][tx] = in[(size_t)(k0 + ty + i) * 8192 + 4096 + j0 + tx];
    }
    __syncthreads();
#pragma unroll
    for (int i = 0; i < 32; i += 8) {
        const int jj = j0 + ty + i;
        out[(size_t)(2 * jj)     * 1024 + k0 + tx] = __float2half(ta[tx][ty + i]);
        out[(size_t)(2 * jj + 1) * 1024 + k0 + tx] = __float2half(tg[tx][ty + i]);
    }
}

// ---------------- LayerNorm (f32 in -> half out) ----------------
__global__ void __launch_bounds__(256) ln_kernel(const float* __restrict__ in,
                                                 const float* __restrict__ g,
                                                 __half* __restrict__ out) {
    const int row = blockIdx.x;
    const int t = threadIdx.x;
    const float* p = in + (size_t)row * DIM;
    float4 v = *(const float4*)&p[t * 4];
    float s  = v.x + v.y + v.z + v.w;
    float sq = v.x*v.x + v.y*v.y + v.z*v.z + v.w*v.w;
#pragma unroll
    for (int off = 16; off; off >>= 1) {
        s  += __shfl_xor_sync(0xffffffffu, s,  off);
        sq += __shfl_xor_sync(0xffffffffu, sq, off);
    }
    __shared__ float rs[8], rq[8];
    if ((t & 31) == 0) { rs[t >> 5] = s; rq[t >> 5] = sq; }
    __syncthreads();
    float ts = 0.f, tq = 0.f;
#pragma unroll
    for (int i = 0; i < 8; i++) { ts += rs[i]; tq += rq[i]; }
    const float mu  = ts * (1.f / DIM);
    const float var = tq * (1.f / DIM) - mu * mu;
    const float rstd = rsqrtf(var + 1e-5f);
    float4 gv = *(const float4*)&g[t * 4];
    __half2* op = (__half2*)&out[(size_t)row * DIM + t * 4];
    op[0] = __floats2half2_rn((v.x - mu) * rstd * gv.x, (v.y - mu) * rstd * gv.y);
    op[1] = __floats2half2_rn((v.z - mu) * rstd * gv.z, (v.w - mu) * rstd * gv.w);
}

// ============ fp16 GEMM, 256x128 tiles, K-chunk 64, 2-stage ============
#define H2S 72
#define H2_STG (256*H2S + 128*H2S)
#define HG2_SMEM_BYTES (2*H2_STG*2)

template<int EPI>
__global__ void __launch_bounds__(256) hgemm2_kernel(
        int M, int N, int K, int lda,
        const __half* __restrict__ A, const __half* __restrict__ Bt,
        void* __restrict__ Cv, __half* __restrict__ Cv2) {
    extern __shared__ __half smh[];
    const int tid = threadIdx.x, lane = tid & 31, wid = tid >> 5;
    const int wm = (wid >> 1) * 64, wn = (wid & 1) * 64;
    const int bm = blockIdx.y * 256, bn = blockIdx.x * 128;
    const int gr = lane >> 2, gq = lane & 3;

    float acc[4][8][4] = {};
    const int T = K / 64;

    auto issue = [&](int t) {
        const int s = t & 1;
        const int k0 = t * 64;
        __half* As = smh + s * H2_STG;
        __half* Bs = As + 256 * H2S;
#pragma unroll
        for (int p = 0; p < 8; p++) {
            const int lin = p * 256 + tid;
            const int row = lin >> 3, q8 = (lin & 7) * 8;
            cp16(&As[row * H2S + q8], &A[(size_t)(bm + row) * lda + k0 + q8]);
        }
#pragma unroll
        for (int p = 0; p < 4; p++) {
            const int lin = p * 256 + tid;
            const int row = lin >> 3, q8 = (lin & 7) * 8;
            cp16(&Bs[row * H2S + q8], &Bt[(size_t)(bn + row) * K + k0 + q8]);
        }
        asm volatile("cp.async.commit_group;");
    };

    issue(0);
    if (T > 1) issue(1);

    const int a_r = lane & 15, a_c = (lane >> 4) << 3;
    const int b_r = (lane & 7) + ((lane >> 4) & 1) * 8;
    const int b_c = ((lane >> 3) & 1) << 3;

    for (int t = 0; t < T; t++) {
        if (t + 1 < T) asm volatile("cp.async.wait_group 1;");
        else           asm volatile("cp.async.wait_group 0;");
        __syncthreads();

        const int s = t & 1;
        const __half* As = smh + s * H2_STG;
        const __half* Bs = As + 256 * H2S;
#pragma unroll
        for (int ks = 0; ks < 4; ks++) {
            const int k = ks * 16;
            unsigned a[4][4], b[8][2];
#pragma unroll
            for (int mi = 0; mi < 4; mi++) {
                const unsigned ad = smem_u32(&As[(wm + mi * 16 + a_r) * H2S + k + a_c]);
                LDSM_X4(a[mi][0], a[mi][1], a[mi][2], a[mi][3], ad);
            }
#pragma unroll
            for (int np = 0; np < 4; np++) {
                const unsigned ad = smem_u32(&Bs[(wn + np * 16 + b_r) * H2S + k + b_c]);
                LDSM_X4(b[2*np][0], b[2*np][1], b[2*np+1][0], b[2*np+1][1], ad);
            }
#pragma unroll
            for (int mi = 0; mi < 4; mi++)
#pragma unroll
                for (int ni = 0; ni < 8; ni++)
                    MMA_F16(acc[mi][ni][0], acc[mi][ni][1], acc[mi][ni][2], acc[mi][ni][3],
                            a[mi][0], a[mi][1], a[mi][2], a[mi][3], b[ni][0], b[ni][1]);
        }
        __syncthreads();
        if (t + 2 < T) issue(t + 2);
    }

#pragma unroll
    for (int mi = 0; mi < 4; mi++) {
#pragma unroll
        for (int ni = 0; ni < 8; ni++) {
            const int row0 = bm + wm + mi * 16 + gr;
            const int col  = bn + wn + ni * 8 + 2 * gq;
            if (EPI == 0) {
                float* C = (float*)Cv;
                *(float2*)&C[(size_t)row0 * N + col] =
                    make_float2(acc[mi][ni][0], acc[mi][ni][1]);
                *(float2*)&C[(size_t)(row0 + 8) * N + col] =
                    make_float2(acc[mi][ni][2], acc[mi][ni][3]);
            } else {  // EPI == 5 : QFF
                if (bn < 1024) {
                    __half* C = (__half*)Cv;
                    *(__half2*)&C[(size_t)row0 * 1024 + col] =
                        __floats2half2_rn(acc[mi][ni][0], acc[mi][ni][1]);
                    *(__half2*)&C[(size_t)(row0 + 8) * 1024 + col] =
                        __floats2half2_rn(acc[mi][ni][2], acc[mi][ni][3]);
                } else {
                    const int colh = (col - 1024) >> 1;
                    const float g0 = acc[mi][ni][1], g1 = acc[mi][ni][3];
                    Cv2[(size_t)row0 * CATW + colh] =
                        __float2half(acc[mi][ni][0] * (g0 / (1.f + __expf(-g0))));
                    Cv2[(size_t)(row0 + 8) * CATW + colh] =
                        __float2half(acc[mi][ni][2] * (g1 / (1.f + __expf(-g1))));
                }
            }
        }
    }
}

// ---------------- kv GEMM: 128x128 tiles (N=128 only) ----------------
#define HS 40
#define HSTAGE (128*HS*2)
#define HGEMM_SMEM_BYTES (3*HSTAGE*2)

__global__ void __launch_bounds__(256) kv_gemm_kernel(
        int M, int N, int K,
        const __half* __restrict__ A, const __half* __restrict__ Bt,
        __half* __restrict__ C) {
    extern __shared__ __half smh[];
    const int tid = threadIdx.x, lane = tid & 31, wid = tid >> 5;
    const int wm = (wid & 1) * 64, wn = (wid >> 1) * 32;
    const int bm = blockIdx.y * 128, bn = blockIdx.x * 128;
    const int gr = lane >> 2, gq = lane & 3;

    float acc[4][4][4] = {};
    const int T = K / 32;

    auto issue = [&](int t) {
        const int s = t % 3;
        const int k0 = t * 32;
        __half* As = smh + s * HSTAGE;
        __half* Bs = As + 128 * HS;
#pragma unroll
        for (int p = 0; p < 2; p++) {
            const int lin = p * 256 + tid;
            const int row = lin >> 2, q8 = (lin & 3) * 8;
            cp16(&As[row * HS + q8], &A [(size_t)(bm + row) * K + k0 + q8]);
            cp16(&Bs[row * HS + q8], &Bt[(size_t)(bn + row) * K + k0 + q8]);
        }
        asm volatile("cp.async.commit_group;");
    };

    issue(0);
    if (T > 1) issue(1);

    const int a_r = lane & 15, a_c = (lane >> 4) << 3;
    const int b_r = (lane & 7) + ((lane >> 4) & 1) * 8;
    const int b_c = ((lane >> 3) & 1) << 3;

    for (int t = 0; t < T; t++) {
        if (t + 1 < T) asm volatile("cp.async.wait_group 1;");
        else           asm volatile("cp.async.wait_group 0;");
        __syncthreads();
        if (t + 2 < T) issue(t + 2);

        const int s = t % 3;
        const __half* As = smh + s * HSTAGE;
        const __half* Bs = As + 128 * HS;
#pragma unroll
        for (int ks = 0; ks < 2; ks++) {
            const int k = ks * 16;
            unsigned a[4][4], b[4][2];
#pragma unroll
            for (int mi = 0; mi < 4; mi++) {
                const unsigned ad = smem_u32(&As[(wm + mi * 16 + a_r) * HS + k + a_c]);
                LDSM_X4(a[mi][0], a[mi][1], a[mi][2], a[mi][3], ad);
            }
#pragma unroll
            for (int np = 0; np < 2; np++) {
                const unsigned ad = smem_u32(&Bs[(wn + np * 16 + b_r) * HS + k + b_c]);
                LDSM_X4(b[2*np][0], b[2*np][1], b[2*np+1][0], b[2*np+1][1], ad);
            }
#pragma unroll
            for (int mi = 0; mi < 4; mi++)
#pragma unroll
                for (int ni = 0; ni < 4; ni++)
                    MMA_F16(acc[mi][ni][0], acc[mi][ni][1], acc[mi][ni][2], acc[mi][ni][3],
                            a[mi][0], a[mi][1], a[mi][2], a[mi][3], b[ni][0], b[ni][1]);
        }
        __syncthreads();
    }

#pragma unroll
    for (int mi = 0; mi < 4; mi++) {
#pragma unroll
        for (int ni = 0; ni < 4; ni++) {
            const int row0 = bm + wm + mi * 16 + gr;
            const int col  = bn + wn + ni * 8 + 2 * gq;
            *(__half2*)&C[(size_t)row0 * N + col] =
                __floats2half2_rn(acc[mi][ni][0], acc[mi][ni][1]);
            *(__half2*)&C[(size_t)(row0 + 8) * N + col] =
                __floats2half2_rn(acc[mi][ni][2], acc[mi][ni][3]);
        }
    }
}

// ---------------- flash attention, fp16 mma + ldmatrix --------------------
#define AQS 72
#define AOFF_P  4608
#define AOFF_ST 9216
#define ASTAGE  9216
#define AOFF_MK 27648
#define ATT_SMEM_BYTES (AOFF_MK*2 + 2*64*4)

__global__ void __launch_bounds__(128) attn_kernel(const __half* __restrict__ q,
                                                   const __half* __restrict__ kv,
                                                   const int* __restrict__ mask,
                                                   __half* __restrict__ out) {
    extern __shared__ __half smh[];
    __half* sQ = smh;
    __half* sP = smh + AOFF_P;

    const int tid = threadIdx.x, lane = tid & 31, wid = tid >> 5;
    const int gr = lane >> 2, gq = lane & 3;
    const int wm = wid * 16;
    const int qt = blockIdx.x, h = blockIdx.y, b = blockIdx.z;
    const size_t qbase = ((size_t)(b * SEQ + qt * 64)) * DIM + h * DHEAD;
    const size_t obase = ((size_t)(b * SEQ + qt * 64)) * CATW + h * DHEAD;

    const int a_r = lane & 15, a_c = (lane >> 4) << 3;
    const int b_r = (lane & 7) + ((lane >> 4) & 1) * 8;
    const int b_c = ((lane >> 3) & 1) << 3;

#pragma unroll
    for (int p = 0; p < 4; p++) {
        const int lin = p * 128 + tid;
        const int r = lin >> 3, c8 = (lin & 7) * 8;
        *(uint4*)&sQ[r * AQS + c8] = *(const uint4*)&q[qbase + (size_t)r * DIM + c8];
    }

    auto issue = [&](int jt, int s) {
        __half* sK = smh + AOFF_ST + s * ASTAGE;
        __half* sV = sK + 64 * AQS;
        int*   sMk = (int*)(smh + AOFF_MK) + s * 64;
        const size_t kbase = (size_t)(b * SEQ + jt * 64) * 128;
#pragma unroll
        for (int p = 0; p < 8; p++) {
            const int lin = p * 128 + tid;
            const int j = lin >> 4, c8 = (lin & 15) * 8;
            const __half* src = &kv[kbase + (size_t)j * 128 + c8];
            if (c8 < 64) cp16(&sK[j * AQS + c8], src);
            else         cp16(&sV[j * AQS + c8 - 64], src);
        }
        if (tid < 16) cp16(&sMk[tid * 4], &mask[b * SEQ + jt * 64 + tid * 4]);
        asm volatile("cp.async.commit_group;");
    };

    issue(0, 0);

    float m0 = -1e30f, m1 = -1e30f, l0 = 0.f, l1 = 0.f;
    float o[8][4];
#pragma unroll
    for (int d = 0; d < 8; d++)
#pragma unroll
        for (int j = 0; j < 4; j++) o[d][j] = 0.f;

    for (int jt = 0; jt < SEQ / 64; jt++) {
        if (jt + 1 < SEQ / 64) {
            issue(jt + 1, (jt + 1) & 1);
            asm volatile("cp.async.wait_group 1;");
        } else {
            asm volatile("cp.async.wait_group 0;");
        }
        __syncthreads();

        const int s = jt & 1;
        const __half* sK = smh + AOFF_ST + s * ASTAGE;
        const __half* sV = sK + 64 * AQS;
        const int*   sMk = (const int*)(smh + AOFF_MK) + s * 64;

        float sc[8][4];
#pragma unroll
        for (int n = 0; n < 8; n++)
#pragma unroll
            for (int j = 0; j < 4; j++) sc[n][j] = 0.f;

#pragma unroll
        for (int ks = 0; ks < 4; ks++) {
            const int k = ks * 16;
            unsigned a0, a1, a2, a3;
            LDSM_X4(a0, a1, a2, a3, smem_u32(&sQ[(wm + a_r) * AQS + k + a_c]));
#pragma unroll
            for (int np = 0; np < 4; np++) {
                unsigned b0, b1, b2, b3;
                LDSM_X4(b0, b1, b2, b3, smem_u32(&sK[(np * 16 + b_r) * AQS + k + b_c]));
                MMA_F16(sc[2*np][0], sc[2*np][1], sc[2*np][2], sc[2*np][3],
                        a0, a1, a2, a3, b0, b1);
                MMA_F16(sc[2*np+1][0], sc[2*np+1][1], sc[2*np+1][2], sc[2*np+1][3],
                        a0, a1, a2, a3, b2, b3);
            }
        }

#pragma unroll
        for (int n = 0; n < 8; n++) {
            const int c0 = n * 8 + 2 * gq;
            if (sMk[c0] == 0)     { sc[n][0] = -1e30f; sc[n][2] = -1e30f; }
            if (sMk[c0 + 1] == 0) { sc[n][1] = -1e30f; sc[n][3] = -1e30f; }
        }
        float mx0 = -1e30f, mx1 = -1e30f;
#pragma unroll
        for (int n = 0; n < 8; n++) {
            mx0 = fmaxf(mx0, fmaxf(sc[n][0], sc[n][1]));
            mx1 = fmaxf(mx1, fmaxf(sc[n][2], sc[n][3]));
        }
        mx0 = fmaxf(mx0, __shfl_xor_sync(0xffffffffu, mx0, 1));
        mx0 = fmaxf(mx0, __shfl_xor_sync(0xffffffffu, mx0, 2));
        mx1 = fmaxf(mx1, __shfl_xor_sync(0xffffffffu, mx1, 1));
        mx1 = fmaxf(mx1, __shfl_xor_sync(0xffffffffu, mx1, 2));
        const float mn0 = fmaxf(m0, mx0), mn1 = fmaxf(m1, mx1);
        const float corr0 = __expf(m0 - mn0), corr1 = __expf(m1 - mn1);
        float rs0 = 0.f, rs1 = 0.f;
#pragma unroll
        for (int n = 0; n < 8; n++) {
            float p0 = __expf(sc[n][0] - mn0);
            float p1 = __expf(sc[n][1] - mn0);
            float p2 = __expf(sc[n][2] - mn1);
            float p3 = __expf(sc[n][3] - mn1);
            rs0 += p0 + p1; rs1 += p2 + p3;
            *(__half2*)&sP[(wm + gr) * AQS + n * 8 + 2 * gq] = __floats2half2_rn(p0, p1);
            *(__half2*)&sP[(wm + gr + 8) * AQS + n * 8 + 2 * gq] = __floats2half2_rn(p2, p3);
        }
        rs0 += __shfl_xor_sync(0xffffffffu, rs0, 1);
        rs0 += __shfl_xor_sync(0xffffffffu, rs0, 2);
        rs1 += __shfl_xor_sync(0xffffffffu, rs1, 1);
        rs1 += __shfl_xor_sync(0xffffffffu, rs1, 2);
        l0 = l0 * corr0 + rs0; m0 = mn0;
        l1 = l1 * corr1 + rs1; m1 = mn1;
#pragma unroll
        for (int d = 0; d < 8; d++) {
            o[d][0] *= corr0; o[d][1] *= corr0;
            o[d][2] *= corr1; o[d][3] *= corr1;
        }
        __syncwarp();

#pragma unroll
        for (int ks = 0; ks < 4; ks++) {
            const int kc = ks * 16;
            unsigned a0, a1, a2, a3;
            LDSM_X4(a0, a1, a2, a3, smem_u32(&sP[(wm + a_r) * AQS + kc + a_c]));
            const int vrow = kc + (lane & 7) + ((lane >> 3) & 1) * 8;
            const int vcb  = ((lane >> 4) & 1) * 8;
#pragma unroll
            for (int dp = 0; dp < 4; dp++) {
                unsigned b0, b1, b2, b3;
                const unsigned addr = smem_u32(&sV[vrow * AQS + dp * 16 + vcb]);
                asm volatile(
                    "ldmatrix.sync.aligned.m8n8.x4.trans.shared.b16 {%0,%1,%2,%3}, [%4];"
                    : "=r"(b0), "=r"(b1), "=r"(b2), "=r"(b3) : "r"(addr));
                MMA_F16(o[dp*2][0], o[dp*2][1], o[dp*2][2], o[dp*2][3],
                        a0, a1, a2, a3, b0, b1);
                MMA_F16(o[dp*2+1][0], o[dp*2+1][1], o[dp*2+1][2], o[dp*2+1][3],
                        a0, a1, a2, a3, b2, b3);
            }
        }
        __syncthreads();
    }

    const float inv0 = 1.f / l0, inv1 = 1.f / l1;
#pragma unroll
    for (int dt = 0; dt < 8; dt++) {
        const int col = dt * 8 + 2 * gq;
        *(__half2*)&out[obase + (size_t)(wm + gr) * CATW + col] =
            __floats2half2_rn(o[dt][0] * inv0, o[dt][1] * inv0);
        *(__half2*)&out[obase + (size_t)(wm + gr + 8) * CATW + col] =
            __floats2half2_rn(o[dt][2] * inv1, o[dt][3] * inv1);
    }
}

// ---------------- launch --------------------------------------------------
extern "C" void kernel_launch(void* const* d_in, const int* in_sizes, int n_in,
                              void* d_out, int out_size) {
    (void)in_sizes; (void)n_in; (void)out_size;
    const float* x        = (const float*)d_in[0];
    const float* context  = (const float*)d_in[1];
    const int*   mask     = (const int*)  d_in[2];
    const float* gamma    = (const float*)d_in[3];
    const float* ctxgamma = (const float*)d_in[4];
    const float* Wq       = (const float*)d_in[5];
    const float* Wkv      = (const float*)d_in[6];
    const float* Wout     = (const float*)d_in[7];
    const float* Wff1     = (const float*)d_in[8];
    const float* Wff2     = (const float*)d_in[9];
    float* out = (float*)d_out;

    __half *xn, *cn, *qb, *kvb, *cat, *w;
    cudaGetSymbolAddress((void**)&xn,  g_xn);
    cudaGetSymbolAddress((void**)&cn,  g_cn);
    cudaGetSymbolAddress((void**)&qb,  g_q);
    cudaGetSymbolAddress((void**)&kvb, g_kv);
    cudaGetSymbolAddress((void**)&cat, g_cat);
    cudaGetSymbolAddress((void**)&w,   g_w);

    cudaFuncSetAttribute(attn_kernel, cudaFuncAttributeMaxDynamicSharedMemorySize, ATT_SMEM_BYTES);
    cudaFuncSetAttribute(kv_gemm_kernel, cudaFuncAttributeMaxDynamicSharedMemorySize, HGEMM_SMEM_BYTES);
    cudaFuncSetAttribute(hgemm2_kernel<0>, cudaFuncAttributeMaxDynamicSharedMemorySize, HG2_SMEM_BYTES);
    cudaFuncSetAttribute(hgemm2_kernel<5>, cudaFuncAttributeMaxDynamicSharedMemorySize, HG2_SMEM_BYTES);

    // fork a side stream for the independent (ctx/kv/Wout2) chain
    cudaStream_t s1;
    cudaStreamCreateWithFlags(&s1, cudaStreamNonBlocking);
    cudaEvent_t eFork, eJoin;
    cudaEventCreateWithFlags(&eFork, cudaEventDisableTiming);
    cudaEventCreateWithFlags(&eJoin, cudaEventDisableTiming);

    dim3 tb(32, 8);

    cudaEventRecord(eFork, 0);
    cudaStreamWaitEvent(s1, eFork, 0);

    // ---- main stream: x chain -> QFF GEMM ----
    ln_kernel<<<ROWS, 256>>>(x, gamma, xn);
    transpose_half_kernel<<<dim3(1024/32, 1024/32), tb>>>(Wq, w + WQFF_OFF, 1024, 1024, 1024, 0.125f);
    transpose_swiglu_kernel<<<dim3(4096/32, 1024/32), tb>>>(Wff1, w + WQFF_OFF + 1024*1024);
    hgemm2_kernel<5><<<dim3(9216/128, ROWS/256), 256, HG2_SMEM_BYTES>>>(
        ROWS, 9216, DIM, DIM, xn, w + WQFF_OFF, qb, cat + 1024);

    // ---- side stream: ctx chain + Wout2 prep (overlaps QFF GEMM) ----
    ln_kernel<<<ROWS, 256, 0, s1>>>(context, ctxgamma, cn);
    transpose_half_kernel<<<dim3(128/32, 1024/32), tb, 0, s1>>>(Wkv, w + WKV_OFF, 1024, 128, 1024, 1.f);
    kv_gemm_kernel<<<dim3(1, ROWS/128), 256, HGEMM_SMEM_BYTES, s1>>>(
        ROWS, 2*DHEAD, DIM, cn, w + WKV_OFF, kvb);
    transpose_half_kernel<<<dim3(1024/32, 1024/32), tb, 0, s1>>>(Wout, w + WOUT2_OFF, 1024, 1024, CATW, 1.f);
    transpose_half_kernel<<<dim3(1024/32, 4096/32), tb, 0, s1>>>(Wff2, w + WOUT2_OFF + 1024, 4096, 1024, CATW, 1.f);
    cudaEventRecord(eJoin, s1);

    // ---- join, then attention + OUT GEMM on main stream ----
    cudaStreamWaitEvent(0, eJoin, 0);
    attn_kernel<<<dim3(SEQ/64, HEADS, BATCH), 128, ATT_SMEM_BYTES>>>(qb, kvb, mask, cat);
    hgemm2_kernel<0><<<dim3(DIM/128, ROWS/256), 256, HG2_SMEM_BYTES>>>(
        ROWS, DIM, CATW, CATW, cat, w + WOUT2_OFF, out, nullptr);

    cudaEventDestroy(eFork);
    cudaEventDestroy(eJoin);
    cudaStreamDestroy(s1);
}

// round 11
// speedup vs baseline: 5.9622x; 1.0180x over previous
#include <cuda_runtime.h>
#include <cuda_fp16.h>
#include <math.h>
#include <stdint.h>

// ---------------- problem constants ----------------
#define BATCH 2
#define SEQ   2048
#define DIM   1024
#define HEADS 16
#define DHEAD 64
#define FFI   4096
#define ROWS  (BATCH*SEQ)
#define CATW  5120               // 1024 attn + 4096 ff, combined row width

// ---------------- scratch ----------------
__device__ __half g_xn [(size_t)ROWS*DIM];
__device__ __half g_cn [(size_t)ROWS*DIM];
__device__ __half g_q  [(size_t)ROWS*DIM];
__device__ __half g_kv [(size_t)ROWS*2*DHEAD];
__device__ __half g_cat[(size_t)ROWS*CATW];      // [attn(1024) | ff(4096)] per row
__device__ __half g_w  [14811136];               // combined fp16 weights

#define WQFF_OFF 0                               // [9216][1024]  (scaled Wq + interleaved Wff1)
#define WKV_OFF  9437184                         // [128][1024]
#define WOUT2_OFF 9568256                        // [1024][5120]  (WoutT | Wff2T)

__device__ __forceinline__ unsigned smem_u32(const void* p) {
    unsigned sa;
    asm("{.reg .u64 t; cvta.to.shared.u64 t, %1; cvt.u32.u64 %0, t;}" : "=r"(sa) : "l"(p));
    return sa;
}
__device__ __forceinline__ void cp16(void* smem_ptr, const void* gptr) {
    asm volatile("cp.async.cg.shared.global [%0], [%1], 16;"
                 :: "r"(smem_u32(smem_ptr)), "l"(gptr));
}

#define MMA_F16(C0,C1,C2,C3,A0,A1,A2,A3,B0,B1) \
    asm volatile("mma.sync.aligned.m16n8k16.row.col.f32.f16.f16.f32 " \
        "{%0,%1,%2,%3},{%4,%5,%6,%7},{%8,%9},{%0,%1,%2,%3};" \
        : "+f"(C0), "+f"(C1), "+f"(C2), "+f"(C3) \
        : "r"(A0), "r"(A1), "r"(A2), "r"(A3), "r"(B0), "r"(B1))

#define LDSM_X4(R0,R1,R2,R3,ADDR) \
    asm volatile("ldmatrix.sync.aligned.m8n8.x4.shared.b16 {%0,%1,%2,%3}, [%4];" \
        : "=r"(R0), "=r"(R1), "=r"(R2), "=r"(R3) : "r"(ADDR))

// ---------------- preprocessing: transpose f32 -> half [N][K] -------------
__global__ void __launch_bounds__(256) transpose_half_kernel(const float* __restrict__ in,
                                                             __half* __restrict__ out,
                                                             int K, int N, int ostride,
                                                             float scale) {
    __shared__ float t[32][33];
    const int tx = threadIdx.x, ty = threadIdx.y;   // 32 x 8
    const int n0 = blockIdx.x * 32, k0 = blockIdx.y * 32;
#pragma unroll
    for (int i = 0; i < 32; i += 8)
        t[ty + i][tx] = in[(size_t)(k0 + ty + i) * N + n0 + tx];
    __syncthreads();
#pragma unroll
    for (int i = 0; i < 32; i += 8)
        out[(size_t)(n0 + ty + i) * ostride + k0 + tx] = __float2half(scale * t[tx][ty + i]);
}

// Wff1: transpose + interleave into rows 2j / 2j+1 (a / gate), K=1024
__global__ void __launch_bounds__(256) transpose_swiglu_kernel(const float* __restrict__ in,
                                                               __half* __restrict__ out) {
    __shared__ float ta[32][33], tg[32][33];
    const int tx = threadIdx.x, ty = threadIdx.y;
    const int j0 = blockIdx.x * 32, k0 = blockIdx.y * 32;
#pragma unroll
    for (int i = 0; i < 32; i += 8) {
        ta[ty + i][tx] = in[(size_t)(k0 + ty + i) * 8192 + j0 + tx];
        tg[ty + i][tx] = in[(size_t)(k0 + ty + i) * 8192 + 4096 + j0 + tx];
    }
    __syncthreads();
#pragma unroll
    for (int i = 0; i < 32; i += 8) {
        const int jj = j0 + ty + i;
        out[(size_t)(2 * jj)     * 1024 + k0 + tx] = __float2half(ta[tx][ty + i]);
        out[(size_t)(2 * jj + 1) * 1024 + k0 + tx] = __float2half(tg[tx][ty + i]);
    }
}

// ---------------- LayerNorm (f32 in -> half out) ----------------
__global__ void __launch_bounds__(256) ln_kernel(const float* __restrict__ in,
                                                 const float* __restrict__ g,
                                                 __half* __restrict__ out) {
    const int row = blockIdx.x;
    const int t = threadIdx.x;
    const float* p = in + (size_t)row * DIM;
    float4 v = *(const float4*)&p[t * 4];
    float s  = v.x + v.y + v.z + v.w;
    float sq = v.x*v.x + v.y*v.y + v.z*v.z + v.w*v.w;
#pragma unroll
    for (int off = 16; off; off >>= 1) {
        s  += __shfl_xor_sync(0xffffffffu, s,  off);
        sq += __shfl_xor_sync(0xffffffffu, sq, off);
    }
    __shared__ float rs[8], rq[8];
    if ((t & 31) == 0) { rs[t >> 5] = s; rq[t >> 5] = sq; }
    __syncthreads();
    float ts = 0.f, tq = 0.f;
#pragma unroll
    for (int i = 0; i < 8; i++) { ts += rs[i]; tq += rq[i]; }
    const float mu  = ts * (1.f / DIM);
    const float var = tq * (1.f / DIM) - mu * mu;
    const float rstd = rsqrtf(var + 1e-5f);
    float4 gv = *(const float4*)&g[t * 4];
    __half2* op = (__half2*)&out[(size_t)row * DIM + t * 4];
    op[0] = __floats2half2_rn((v.x - mu) * rstd * gv.x, (v.y - mu) * rstd * gv.y);
    op[1] = __floats2half2_rn((v.z - mu) * rstd * gv.z, (v.w - mu) * rstd * gv.w);
}

// ============ fp16 GEMM, 256x128 tiles, 512 threads (16 warps 4m x 4n) ====
// warp tile 64x32, K-chunk 64, 2-stage cp.async.
// EPI 0: store f32; EPI 5: QFF combined (q half store / SwiGLU pairs)
#define H2S 72
#define H2_STG (256*H2S + 128*H2S)
#define HG2_SMEM_BYTES (2*H2_STG*2)

template<int EPI>
__global__ void __launch_bounds__(512) hgemm2_kernel(
        int M, int N, int K, int lda,
        const __half* __restrict__ A, const __half* __restrict__ Bt,
        void* __restrict__ Cv, __half* __restrict__ Cv2) {
    extern __shared__ __half smh[];
    const int tid = threadIdx.x, lane = tid & 31, wid = tid >> 5;
    const int wm = (wid >> 2) * 64, wn = (wid & 3) * 32;
    const int bm = blockIdx.y * 256, bn = blockIdx.x * 128;
    const int gr = lane >> 2, gq = lane & 3;

    float acc[4][4][4] = {};
    const int T = K / 64;

    auto issue = [&](int t) {
        const int s = t & 1;
        const int k0 = t * 64;
        __half* As = smh + s * H2_STG;
        __half* Bs = As + 256 * H2S;
#pragma unroll
        for (int p = 0; p < 4; p++) {
            const int lin = p * 512 + tid;          // 0..2047
            const int row = lin >> 3, q8 = (lin & 7) * 8;
            cp16(&As[row * H2S + q8], &A[(size_t)(bm + row) * lda + k0 + q8]);
        }
#pragma unroll
        for (int p = 0; p < 2; p++) {
            const int lin = p * 512 + tid;          // 0..1023
            const int row = lin >> 3, q8 = (lin & 7) * 8;
            cp16(&Bs[row * H2S + q8], &Bt[(size_t)(bn + row) * K + k0 + q8]);
        }
        asm volatile("cp.async.commit_group;");
    };

    issue(0);
    if (T > 1) issue(1);

    const int a_r = lane & 15, a_c = (lane >> 4) << 3;
    const int b_r = (lane & 7) + ((lane >> 4) & 1) * 8;
    const int b_c = ((lane >> 3) & 1) << 3;

    for (int t = 0; t < T; t++) {
        if (t + 1 < T) asm volatile("cp.async.wait_group 1;");
        else           asm volatile("cp.async.wait_group 0;");
        __syncthreads();

        const int s = t & 1;
        const __half* As = smh + s * H2_STG;
        const __half* Bs = As + 256 * H2S;
#pragma unroll
        for (int ks = 0; ks < 4; ks++) {
            const int k = ks * 16;
            unsigned a[4][4], b[4][2];
#pragma unroll
            for (int mi = 0; mi < 4; mi++) {
                const unsigned ad = smem_u32(&As[(wm + mi * 16 + a_r) * H2S + k + a_c]);
                LDSM_X4(a[mi][0], a[mi][1], a[mi][2], a[mi][3], ad);
            }
#pragma unroll
            for (int np = 0; np < 2; np++) {
                const unsigned ad = smem_u32(&Bs[(wn + np * 16 + b_r) * H2S + k + b_c]);
                LDSM_X4(b[2*np][0], b[2*np][1], b[2*np+1][0], b[2*np+1][1], ad);
            }
#pragma unroll
            for (int mi = 0; mi < 4; mi++)
#pragma unroll
                for (int ni = 0; ni < 4; ni++)
                    MMA_F16(acc[mi][ni][0], acc[mi][ni][1], acc[mi][ni][2], acc[mi][ni][3],
                            a[mi][0], a[mi][1], a[mi][2], a[mi][3], b[ni][0], b[ni][1]);
        }
        __syncthreads();
        if (t + 2 < T) issue(t + 2);
    }

#pragma unroll
    for (int mi = 0; mi < 4; mi++) {
#pragma unroll
        for (int ni = 0; ni < 4; ni++) {
            const int row0 = bm + wm + mi * 16 + gr;
            const int col  = bn + wn + ni * 8 + 2 * gq;
            if (EPI == 0) {
                float* C = (float*)Cv;
                *(float2*)&C[(size_t)row0 * N + col] =
                    make_float2(acc[mi][ni][0], acc[mi][ni][1]);
                *(float2*)&C[(size_t)(row0 + 8) * N + col] =
                    make_float2(acc[mi][ni][2], acc[mi][ni][3]);
            } else {  // EPI == 5 : QFF
                if (bn < 1024) {
                    __half* C = (__half*)Cv;
                    *(__half2*)&C[(size_t)row0 * 1024 + col] =
                        __floats2half2_rn(acc[mi][ni][0], acc[mi][ni][1]);
                    *(__half2*)&C[(size_t)(row0 + 8) * 1024 + col] =
                        __floats2half2_rn(acc[mi][ni][2], acc[mi][ni][3]);
                } else {
                    const int colh = (col - 1024) >> 1;
                    const float g0 = acc[mi][ni][1], g1 = acc[mi][ni][3];
                    Cv2[(size_t)row0 * CATW + colh] =
                        __float2half(acc[mi][ni][0] * (g0 / (1.f + __expf(-g0))));
                    Cv2[(size_t)(row0 + 8) * CATW + colh] =
                        __float2half(acc[mi][ni][2] * (g1 / (1.f + __expf(-g1))));
                }
            }
        }
    }
}

// ---------------- kv GEMM: 128x128 tiles (N=128 only) ----------------
#define HS 40
#define HSTAGE (128*HS*2)
#define HGEMM_SMEM_BYTES (3*HSTAGE*2)

__global__ void __launch_bounds__(256) kv_gemm_kernel(
        int M, int N, int K,
        const __half* __restrict__ A, const __half* __restrict__ Bt,
        __half* __restrict__ C) {
    extern __shared__ __half smh[];
    const int tid = threadIdx.x, lane = tid & 31, wid = tid >> 5;
    const int wm = (wid & 1) * 64, wn = (wid >> 1) * 32;
    const int bm = blockIdx.y * 128, bn = blockIdx.x * 128;
    const int gr = lane >> 2, gq = lane & 3;

    float acc[4][4][4] = {};
    const int T = K / 32;

    auto issue = [&](int t) {
        const int s = t % 3;
        const int k0 = t * 32;
        __half* As = smh + s * HSTAGE;
        __half* Bs = As + 128 * HS;
#pragma unroll
        for (int p = 0; p < 2; p++) {
            const int lin = p * 256 + tid;
            const int row = lin >> 2, q8 = (lin & 3) * 8;
            cp16(&As[row * HS + q8], &A [(size_t)(bm + row) * K + k0 + q8]);
            cp16(&Bs[row * HS + q8], &Bt[(size_t)(bn + row) * K + k0 + q8]);
        }
        asm volatile("cp.async.commit_group;");
    };

    issue(0);
    if (T > 1) issue(1);

    const int a_r = lane & 15, a_c = (lane >> 4) << 3;
    const int b_r = (lane & 7) + ((lane >> 4) & 1) * 8;
    const int b_c = ((lane >> 3) & 1) << 3;

    for (int t = 0; t < T; t++) {
        if (t + 1 < T) asm volatile("cp.async.wait_group 1;");
        else           asm volatile("cp.async.wait_group 0;");
        __syncthreads();
        if (t + 2 < T) issue(t + 2);

        const int s = t % 3;
        const __half* As = smh + s * HSTAGE;
        const __half* Bs = As + 128 * HS;
#pragma unroll
        for (int ks = 0; ks < 2; ks++) {
            const int k = ks * 16;
            unsigned a[4][4], b[4][2];
#pragma unroll
            for (int mi = 0; mi < 4; mi++) {
                const unsigned ad = smem_u32(&As[(wm + mi * 16 + a_r) * HS + k + a_c]);
                LDSM_X4(a[mi][0], a[mi][1], a[mi][2], a[mi][3], ad);
            }
#pragma unroll
            for (int np = 0; np < 2; np++) {
                const unsigned ad = smem_u32(&Bs[(wn + np * 16 + b_r) * HS + k + b_c]);
                LDSM_X4(b[2*np][0], b[2*np][1], b[2*np+1][0], b[2*np+1][1], ad);
            }
#pragma unroll
            for (int mi = 0; mi < 4; mi++)
#pragma unroll
                for (int ni = 0; ni < 4; ni++)
                    MMA_F16(acc[mi][ni][0], acc[mi][ni][1], acc[mi][ni][2], acc[mi][ni][3],
                            a[mi][0], a[mi][1], a[mi][2], a[mi][3], b[ni][0], b[ni][1]);
        }
        __syncthreads();
    }

#pragma unroll
    for (int mi = 0; mi < 4; mi++) {
#pragma unroll
        for (int ni = 0; ni < 4; ni++) {
            const int row0 = bm + wm + mi * 16 + gr;
            const int col  = bn + wn + ni * 8 + 2 * gq;
            *(__half2*)&C[(size_t)row0 * N + col] =
                __floats2half2_rn(acc[mi][ni][0], acc[mi][ni][1]);
            *(__half2*)&C[(size_t)(row0 + 8) * N + col] =
                __floats2half2_rn(acc[mi][ni][2], acc[mi][ni][3]);
        }
    }
}

// ---------------- flash attention, fp16 mma + ldmatrix --------------------
#define AQS 72
#define AOFF_P  4608
#define AOFF_ST 9216
#define ASTAGE  9216
#define AOFF_MK 27648
#define ATT_SMEM_BYTES (AOFF_MK*2 + 2*64*4)

__global__ void __launch_bounds__(128) attn_kernel(const __half* __restrict__ q,
                                                   const __half* __restrict__ kv,
                                                   const int* __restrict__ mask,
                                                   __half* __restrict__ out) {
    extern __shared__ __half smh[];
    __half* sQ = smh;
    __half* sP = smh + AOFF_P;

    const int tid = threadIdx.x, lane = tid & 31, wid = tid >> 5;
    const int gr = lane >> 2, gq = lane & 3;
    const int wm = wid * 16;
    const int qt = blockIdx.x, h = blockIdx.y, b = blockIdx.z;
    const size_t qbase = ((size_t)(b * SEQ + qt * 64)) * DIM + h * DHEAD;
    const size_t obase = ((size_t)(b * SEQ + qt * 64)) * CATW + h * DHEAD;

    const int a_r = lane & 15, a_c = (lane >> 4) << 3;
    const int b_r = (lane & 7) + ((lane >> 4) & 1) * 8;
    const int b_c = ((lane >> 3) & 1) << 3;

#pragma unroll
    for (int p = 0; p < 4; p++) {
        const int lin = p * 128 + tid;
        const int r = lin >> 3, c8 = (lin & 7) * 8;
        *(uint4*)&sQ[r * AQS + c8] = *(const uint4*)&q[qbase + (size_t)r * DIM + c8];
    }

    auto issue = [&](int jt, int s) {
        __half* sK = smh + AOFF_ST + s * ASTAGE;
        __half* sV = sK + 64 * AQS;
        int*   sMk = (int*)(smh + AOFF_MK) + s * 64;
        const size_t kbase = (size_t)(b * SEQ + jt * 64) * 128;
#pragma unroll
        for (int p = 0; p < 8; p++) {
            const int lin = p * 128 + tid;
            const int j = lin >> 4, c8 = (lin & 15) * 8;
            const __half* src = &kv[kbase + (size_t)j * 128 + c8];
            if (c8 < 64) cp16(&sK[j * AQS + c8], src);
            else         cp16(&sV[j * AQS + c8 - 64], src);
        }
        if (tid < 16) cp16(&sMk[tid * 4], &mask[b * SEQ + jt * 64 + tid * 4]);
        asm volatile("cp.async.commit_group;");
    };

    issue(0, 0);

    float m0 = -1e30f, m1 = -1e30f, l0 = 0.f, l1 = 0.f;
    float o[8][4];
#pragma unroll
    for (int d = 0; d < 8; d++)
#pragma unroll
        for (int j = 0; j < 4; j++) o[d][j] = 0.f;

    for (int jt = 0; jt < SEQ / 64; jt++) {
        if (jt + 1 < SEQ / 64) {
            issue(jt + 1, (jt + 1) & 1);
            asm volatile("cp.async.wait_group 1;");
        } else {
            asm volatile("cp.async.wait_group 0;");
        }
        __syncthreads();

        const int s = jt & 1;
        const __half* sK = smh + AOFF_ST + s * ASTAGE;
        const __half* sV = sK + 64 * AQS;
        const int*   sMk = (const int*)(smh + AOFF_MK) + s * 64;

        float sc[8][4];
#pragma unroll
        for (int n = 0; n < 8; n++)
#pragma unroll
            for (int j = 0; j < 4; j++) sc[n][j] = 0.f;

#pragma unroll
        for (int ks = 0; ks < 4; ks++) {
            const int k = ks * 16;
            unsigned a0, a1, a2, a3;
            LDSM_X4(a0, a1, a2, a3, smem_u32(&sQ[(wm + a_r) * AQS + k + a_c]));
#pragma unroll
            for (int np = 0; np < 4; np++) {
                unsigned b0, b1, b2, b3;
                LDSM_X4(b0, b1, b2, b3, smem_u32(&sK[(np * 16 + b_r) * AQS + k + b_c]));
                MMA_F16(sc[2*np][0], sc[2*np][1], sc[2*np][2], sc[2*np][3],
                        a0, a1, a2, a3, b0, b1);
                MMA_F16(sc[2*np+1][0], sc[2*np+1][1], sc[2*np+1][2], sc[2*np+1][3],
                        a0, a1, a2, a3, b2, b3);
            }
        }

#pragma unroll
        for (int n = 0; n < 8; n++) {
            const int c0 = n * 8 + 2 * gq;
            if (sMk[c0] == 0)     { sc[n][0] = -1e30f; sc[n][2] = -1e30f; }
            if (sMk[c0 + 1] == 0) { sc[n][1] = -1e30f; sc[n][3] = -1e30f; }
        }
        float mx0 = -1e30f, mx1 = -1e30f;
#pragma unroll
        for (int n = 0; n < 8; n++) {
            mx0 = fmaxf(mx0, fmaxf(sc[n][0], sc[n][1]));
            mx1 = fmaxf(mx1, fmaxf(sc[n][2], sc[n][3]));
        }
        mx0 = fmaxf(mx0, __shfl_xor_sync(0xffffffffu, mx0, 1));
        mx0 = fmaxf(mx0, __shfl_xor_sync(0xffffffffu, mx0, 2));
        mx1 = fmaxf(mx1, __shfl_xor_sync(0xffffffffu, mx1, 1));
        mx1 = fmaxf(mx1, __shfl_xor_sync(0xffffffffu, mx1, 2));
        const float mn0 = fmaxf(m0, mx0), mn1 = fmaxf(m1, mx1);
        const float corr0 = __expf(m0 - mn0), corr1 = __expf(m1 - mn1);
        float rs0 = 0.f, rs1 = 0.f;
#pragma unroll
        for (int n = 0; n < 8; n++) {
            float p0 = __expf(sc[n][0] - mn0);
            float p1 = __expf(sc[n][1] - mn0);
            float p2 = __expf(sc[n][2] - mn1);
            float p3 = __expf(sc[n][3] - mn1);
            rs0 += p0 + p1; rs1 += p2 + p3;
            *(__half2*)&sP[(wm + gr) * AQS + n * 8 + 2 * gq] = __floats2half2_rn(p0, p1);
            *(__half2*)&sP[(wm + gr + 8) * AQS + n * 8 + 2 * gq] = __floats2half2_rn(p2, p3);
        }
        rs0 += __shfl_xor_sync(0xffffffffu, rs0, 1);
        rs0 += __shfl_xor_sync(0xffffffffu, rs0, 2);
        rs1 += __shfl_xor_sync(0xffffffffu, rs1, 1);
        rs1 += __shfl_xor_sync(0xffffffffu, rs1, 2);
        l0 = l0 * corr0 + rs0; m0 = mn0;
        l1 = l1 * corr1 + rs1; m1 = mn1;
#pragma unroll
        for (int d = 0; d < 8; d++) {
            o[d][0] *= corr0; o[d][1] *= corr0;
            o[d][2] *= corr1; o[d][3] *= corr1;
        }
        __syncwarp();

#pragma unroll
        for (int ks = 0; ks < 4; ks++) {
            const int kc = ks * 16;
            unsigned a0, a1, a2, a3;
            LDSM_X4(a0, a1, a2, a3, smem_u32(&sP[(wm + a_r) * AQS + kc + a_c]));
            const int vrow = kc + (lane & 7) + ((lane >> 3) & 1) * 8;
            const int vcb  = ((lane >> 4) & 1) * 8;
#pragma unroll
            for (int dp = 0; dp < 4; dp++) {
                unsigned b0, b1, b2, b3;
                const unsigned addr = smem_u32(&sV[vrow * AQS + dp * 16 + vcb]);
                asm volatile(
                    "ldmatrix.sync.aligned.m8n8.x4.trans.shared.b16 {%0,%1,%2,%3}, [%4];"
                    : "=r"(b0), "=r"(b1), "=r"(b2), "=r"(b3) : "r"(addr));
                MMA_F16(o[dp*2][0], o[dp*2][1], o[dp*2][2], o[dp*2][3],
                        a0, a1, a2, a3, b0, b1);
                MMA_F16(o[dp*2+1][0], o[dp*2+1][1], o[dp*2+1][2], o[dp*2+1][3],
                        a0, a1, a2, a3, b2, b3);
            }
        }
        __syncthreads();
    }

    const float inv0 = 1.f / l0, inv1 = 1.f / l1;
#pragma unroll
    for (int dt = 0; dt < 8; dt++) {
        const int col = dt * 8 + 2 * gq;
        *(__half2*)&out[obase + (size_t)(wm + gr) * CATW + col] =
            __floats2half2_rn(o[dt][0] * inv0, o[dt][1] * inv0);
        *(__half2*)&out[obase + (size_t)(wm + gr + 8) * CATW + col] =
            __floats2half2_rn(o[dt][2] * inv1, o[dt][3] * inv1);
    }
}

// ---------------- launch --------------------------------------------------
extern "C" void kernel_launch(void* const* d_in, const int* in_sizes, int n_in,
                              void* d_out, int out_size) {
    (void)in_sizes; (void)n_in; (void)out_size;
    const float* x        = (const float*)d_in[0];
    const float* context  = (const float*)d_in[1];
    const int*   mask     = (const int*)  d_in[2];
    const float* gamma    = (const float*)d_in[3];
    const float* ctxgamma = (const float*)d_in[4];
    const float* Wq       = (const float*)d_in[5];
    const float* Wkv      = (const float*)d_in[6];
    const float* Wout     = (const float*)d_in[7];
    const float* Wff1     = (const float*)d_in[8];
    const float* Wff2     = (const float*)d_in[9];
    float* out = (float*)d_out;

    __half *xn, *cn, *qb, *kvb, *cat, *w;
    cudaGetSymbolAddress((void**)&xn,  g_xn);
    cudaGetSymbolAddress((void**)&cn,  g_cn);
    cudaGetSymbolAddress((void**)&qb,  g_q);
    cudaGetSymbolAddress((void**)&kvb, g_kv);
    cudaGetSymbolAddress((void**)&cat, g_cat);
    cudaGetSymbolAddress((void**)&w,   g_w);

    cudaFuncSetAttribute(attn_kernel, cudaFuncAttributeMaxDynamicSharedMemorySize, ATT_SMEM_BYTES);
    cudaFuncSetAttribute(kv_gemm_kernel, cudaFuncAttributeMaxDynamicSharedMemorySize, HGEMM_SMEM_BYTES);
    cudaFuncSetAttribute(hgemm2_kernel<0>, cudaFuncAttributeMaxDynamicSharedMemorySize, HG2_SMEM_BYTES);
    cudaFuncSetAttribute(hgemm2_kernel<5>, cudaFuncAttributeMaxDynamicSharedMemorySize, HG2_SMEM_BYTES);

    // fork a side stream for the independent (ctx/kv/Wout2) chain
    cudaStream_t s1;
    cudaStreamCreateWithFlags(&s1, cudaStreamNonBlocking);
    cudaEvent_t eFork, eJoin;
    cudaEventCreateWithFlags(&eFork, cudaEventDisableTiming);
    cudaEventCreateWithFlags(&eJoin, cudaEventDisableTiming);

    dim3 tb(32, 8);

    cudaEventRecord(eFork, 0);
    cudaStreamWaitEvent(s1, eFork, 0);

    // ---- main stream: x chain -> QFF GEMM ----
    ln_kernel<<<ROWS, 256>>>(x, gamma, xn);
    transpose_half_kernel<<<dim3(1024/32, 1024/32), tb>>>(Wq, w + WQFF_OFF, 1024, 1024, 1024, 0.125f);
    transpose_swiglu_kernel<<<dim3(4096/32, 1024/32), tb>>>(Wff1, w + WQFF_OFF + 1024*1024);
    hgemm2_kernel<5><<<dim3(9216/128, ROWS/256), 512, HG2_SMEM_BYTES>>>(
        ROWS, 9216, DIM, DIM, xn, w + WQFF_OFF, qb, cat + 1024);

    // ---- side stream: ctx chain + Wout2 prep (overlaps QFF GEMM) ----
    ln_kernel<<<ROWS, 256, 0, s1>>>(context, ctxgamma, cn);
    transpose_half_kernel<<<dim3(128/32, 1024/32), tb, 0, s1>>>(Wkv, w + WKV_OFF, 1024, 128, 1024, 1.f);
    kv_gemm_kernel<<<dim3(1, ROWS/128), 256, HGEMM_SMEM_BYTES, s1>>>(
        ROWS, 2*DHEAD, DIM, cn, w + WKV_OFF, kvb);
    transpose_half_kernel<<<dim3(1024/32, 1024/32), tb, 0, s1>>>(Wout, w + WOUT2_OFF, 1024, 1024, CATW, 1.f);
    transpose_half_kernel<<<dim3(1024/32, 4096/32), tb, 0, s1>>>(Wff2, w + WOUT2_OFF + 1024, 4096, 1024, CATW, 1.f);
    cudaEventRecord(eJoin, s1);

    // ---- join, then attention + OUT GEMM on main stream ----
    cudaStreamWaitEvent(0, eJoin, 0);
    attn_kernel<<<dim3(SEQ/64, HEADS, BATCH), 128, ATT_SMEM_BYTES>>>(qb, kvb, mask, cat);
    hgemm2_kernel<0><<<dim3(DIM/128, ROWS/256), 512, HG2_SMEM_BYTES>>>(
        ROWS, DIM, CATW, CATW, cat, w + WOUT2_OFF, out, nullptr);

    cudaEventDestroy(eFork);
    cudaEventDestroy(eJoin);
    cudaStreamDestroy(s1);
}